// round 1
// baseline (speedup 1.0000x reference)
#include <cuda_runtime.h>
#include <math.h>

// ---------------------------------------------------------------------------
// Problem shapes (fixed):
//   bs=4, H=16, DK=64, D=1024, n_w=128, n_v=1024
// Pipeline:
//   w1 = heads(w_feat @ Ww1^T + bw1)            (4,16,128,64)
//   v1..v4 = heads(v_feat @ Wv{i}^T + bv{i})    (4,16,1024,64)
//   S = w1 @ v3^T ; P = softmax_v(S) ; cross = sum_w P   (4,16,1024)
//   scores = v1 @ v2^T + cross[j] ; softmax_j ; ctx = P @ v4
//   out = concat(ctx) @ Wout^T + bout           (4,1024,1024)
// ---------------------------------------------------------------------------

// Scratch (device globals; no runtime allocation allowed)
__device__ float g_w1[4 * 16 * 128 * 64];       //  2 MB
__device__ float g_v1[4 * 16 * 1024 * 64];      // 16 MB
__device__ float g_v2[4 * 16 * 1024 * 64];      // 16 MB
__device__ float g_v3[4 * 16 * 1024 * 64];      // 16 MB
__device__ float g_v4[4 * 16 * 1024 * 64];      // 16 MB
__device__ float g_S [4 * 16 * 128 * 1024];     // 32 MB
__device__ float g_cr[4 * 16 * 1024];           // 256 KB
__device__ float g_ctx[4 * 1024 * 1024];        // 16 MB (concat layout b,i,h*64+d)

// ---------------------------------------------------------------------------
// Generic SGEMM: C[m][o] = sum_k A[m][k] * W[o][k] + bias[o]
// A: (M,1024) row-major, W: (1024,1024) row-major. 128x128 tile, BK=8,
// 256 threads, 8x8 register micro-tile.
// mode 0: scatter to head layout out[((b*16+h)*n + i)*64 + d], b=m/n, o=h*64+d
// mode 1: flat out[m*1024 + o]
// ---------------------------------------------------------------------------
__global__ void __launch_bounds__(256) sgemm_proj(
    const float* __restrict__ A, const float* __restrict__ W,
    const float* __restrict__ bias, float* __restrict__ out,
    int M, int n_per_b, int mode)
{
    const int K = 1024;
    __shared__ float As[8][128];
    __shared__ float Bs[8][128];

    int t  = threadIdx.x;
    int tx = t & 15, ty = t >> 4;
    int bm = blockIdx.y * 128, bn = blockIdx.x * 128;
    int lr = t >> 1;            // 0..127
    int lk = (t & 1) << 2;      // 0 or 4

    const float* Ap = A + (size_t)(bm + lr) * K + lk;
    const float* Wp = W + (size_t)(bn + lr) * K + lk;

    float acc[8][8];
#pragma unroll
    for (int i = 0; i < 8; i++)
#pragma unroll
        for (int j = 0; j < 8; j++) acc[i][j] = 0.f;

    for (int k0 = 0; k0 < K; k0 += 8) {
        float4 a4 = *(const float4*)(Ap + k0);
        float4 b4 = *(const float4*)(Wp + k0);
        __syncthreads();
        As[lk + 0][lr] = a4.x; As[lk + 1][lr] = a4.y;
        As[lk + 2][lr] = a4.z; As[lk + 3][lr] = a4.w;
        Bs[lk + 0][lr] = b4.x; Bs[lk + 1][lr] = b4.y;
        Bs[lk + 2][lr] = b4.z; Bs[lk + 3][lr] = b4.w;
        __syncthreads();
#pragma unroll
        for (int kk = 0; kk < 8; kk++) {
            float ar[8], br[8];
#pragma unroll
            for (int i = 0; i < 4; i++) {
                ar[i]     = As[kk][ty * 4 + i];
                ar[4 + i] = As[kk][64 + ty * 4 + i];
                br[i]     = Bs[kk][tx * 4 + i];
                br[4 + i] = Bs[kk][64 + tx * 4 + i];
            }
#pragma unroll
            for (int i = 0; i < 8; i++)
#pragma unroll
                for (int j = 0; j < 8; j++)
                    acc[i][j] += ar[i] * br[j];
        }
    }

#pragma unroll
    for (int i = 0; i < 8; i++) {
        int m  = bm + ((i < 4) ? (ty * 4 + i) : (64 + ty * 4 + (i - 4)));
        int b  = m / n_per_b;
        int ii = m % n_per_b;
#pragma unroll
        for (int j = 0; j < 8; j++) {
            int o = bn + ((j < 4) ? (tx * 4 + j) : (64 + tx * 4 + (j - 4)));
            float v = acc[i][j] + bias[o];
            if (mode == 0) {
                int h = o >> 6, d = o & 63;
                out[(((size_t)(b * 16 + h)) * n_per_b + ii) * 64 + d] = v;
            } else {
                out[(size_t)m * 1024 + o] = v;
            }
        }
    }
}

// ---------------------------------------------------------------------------
// Cross scores: per (bh), S[w][v] = w1[bh,w,:] . v3[bh,v,:], K=64.
// grid (vtile 0..7, bh 0..63), 256 threads, 128x128 tile, BK=8.
// ---------------------------------------------------------------------------
__global__ void __launch_bounds__(256) cross_scores(
    const float* __restrict__ w1, const float* __restrict__ v3,
    float* __restrict__ S)
{
    __shared__ float As[8][128];
    __shared__ float Bs[8][128];

    int bh = blockIdx.y, vt = blockIdx.x;
    int t  = threadIdx.x;
    int tx = t & 15, ty = t >> 4;
    int lr = t >> 1;
    int lk = (t & 1) << 2;

    const float* Ap = w1 + (size_t)bh * 8192  + (size_t)lr * 64 + lk;
    const float* Bp = v3 + (size_t)bh * 65536 + (size_t)vt * 8192 + (size_t)lr * 64 + lk;

    float acc[8][8];
#pragma unroll
    for (int i = 0; i < 8; i++)
#pragma unroll
        for (int j = 0; j < 8; j++) acc[i][j] = 0.f;

    for (int k0 = 0; k0 < 64; k0 += 8) {
        float4 a4 = *(const float4*)(Ap + k0);
        float4 b4 = *(const float4*)(Bp + k0);
        __syncthreads();
        As[lk + 0][lr] = a4.x; As[lk + 1][lr] = a4.y;
        As[lk + 2][lr] = a4.z; As[lk + 3][lr] = a4.w;
        Bs[lk + 0][lr] = b4.x; Bs[lk + 1][lr] = b4.y;
        Bs[lk + 2][lr] = b4.z; Bs[lk + 3][lr] = b4.w;
        __syncthreads();
#pragma unroll
        for (int kk = 0; kk < 8; kk++) {
            float ar[8], br[8];
#pragma unroll
            for (int i = 0; i < 4; i++) {
                ar[i]     = As[kk][ty * 4 + i];
                ar[4 + i] = As[kk][64 + ty * 4 + i];
                br[i]     = Bs[kk][tx * 4 + i];
                br[4 + i] = Bs[kk][64 + tx * 4 + i];
            }
#pragma unroll
            for (int i = 0; i < 8; i++)
#pragma unroll
                for (int j = 0; j < 8; j++)
                    acc[i][j] += ar[i] * br[j];
        }
    }

    float* Sb = S + (size_t)bh * 131072;   // 128*1024
#pragma unroll
    for (int i = 0; i < 8; i++) {
        int w = (i < 4) ? (ty * 4 + i) : (64 + ty * 4 + (i - 4));
#pragma unroll
        for (int j = 0; j < 8; j++) {
            int v = vt * 128 + ((j < 4) ? (tx * 4 + j) : (64 + tx * 4 + (j - 4)));
            Sb[(size_t)w * 1024 + v] = acc[i][j];
        }
    }
}

// ---------------------------------------------------------------------------
// Row softmax in place over rows of length 1024. grid = 8192, block = 256.
// ---------------------------------------------------------------------------
__global__ void __launch_bounds__(256) softmax_rows(float* __restrict__ S)
{
    float* p = S + (size_t)blockIdx.x * 1024;
    int t = threadIdx.x;
    __shared__ float sred[8];

    float x[4];
    float mx = -1e30f;
#pragma unroll
    for (int j = 0; j < 4; j++) { x[j] = p[t + 256 * j]; mx = fmaxf(mx, x[j]); }
#pragma unroll
    for (int o = 16; o; o >>= 1) mx = fmaxf(mx, __shfl_xor_sync(0xffffffffu, mx, o));
    if ((t & 31) == 0) sred[t >> 5] = mx;
    __syncthreads();
    float bm = sred[0];
#pragma unroll
    for (int w = 1; w < 8; w++) bm = fmaxf(bm, sred[w]);
    __syncthreads();

    float sum = 0.f;
#pragma unroll
    for (int j = 0; j < 4; j++) { x[j] = __expf(x[j] - bm); sum += x[j]; }
#pragma unroll
    for (int o = 16; o; o >>= 1) sum += __shfl_xor_sync(0xffffffffu, sum, o);
    if ((t & 31) == 0) sred[t >> 5] = sum;
    __syncthreads();
    float tot = 0.f;
#pragma unroll
    for (int w = 0; w < 8; w++) tot += sred[w];
    float inv = 1.f / tot;
#pragma unroll
    for (int j = 0; j < 4; j++) p[t + 256 * j] = x[j] * inv;
}

// ---------------------------------------------------------------------------
// Column sum over w (128 rows): cross[bh][v] = sum_w P[bh][w][v].
// grid = 64, block = 1024.
// ---------------------------------------------------------------------------
__global__ void __launch_bounds__(1024) cross_colsum(
    const float* __restrict__ S, float* __restrict__ cross)
{
    int bh = blockIdx.x;
    int v  = threadIdx.x;
    const float* base = S + (size_t)bh * 131072 + v;
    float a = 0.f;
#pragma unroll
    for (int w = 0; w < 128; w++) a += base[(size_t)w * 1024];
    cross[(size_t)bh * 1024 + v] = a;
}

// ---------------------------------------------------------------------------
// Flash self-attention with per-key bias.
//   scores[i][j] = v1_i . v2_j + cross[j]; softmax_j; ctx_i = sum_j p * v4_j
// grid (qtile 0..7, bh 0..63), 128 threads; each thread owns one query row.
// Writes directly in concat layout: out[b][row][h*64+d].
// ---------------------------------------------------------------------------
__global__ void __launch_bounds__(128) attn_kernel(
    const float* __restrict__ v1, const float* __restrict__ v2,
    const float* __restrict__ v4, const float* __restrict__ cross,
    float* __restrict__ outc)
{
    int bh = blockIdx.y;
    int qt = blockIdx.x;
    int t  = threadIdx.x;
    int b  = bh >> 4, h = bh & 15;

    const float* q_base  = v1 + (size_t)bh * 65536 + (size_t)qt * 8192;
    const float* k_base  = v2 + (size_t)bh * 65536;
    const float* pv_base = v4 + (size_t)bh * 65536;
    const float* cr      = cross + (size_t)bh * 1024;

    __shared__ float ks[64][64];
    __shared__ float vs[64][64];
    __shared__ float crs[64];

    // Stage this thread's query row into registers via coalesced smem staging.
    float q[64];
    for (int half = 0; half < 2; half++) {
        __syncthreads();
        for (int idx = t; idx < 64 * 64; idx += 128)
            ((float*)ks)[idx] = q_base[half * 4096 + idx];
        __syncthreads();
        if ((t >> 6) == half) {
            int r = t & 63;
#pragma unroll
            for (int k = 0; k < 64; k++) q[k] = ks[r][k];
        }
    }

    float acc[64];
#pragma unroll
    for (int d = 0; d < 64; d++) acc[d] = 0.f;
    float m = -1e30f, l = 0.f;

    for (int jt = 0; jt < 16; jt++) {
        __syncthreads();
        for (int idx = t; idx < 64 * 64; idx += 128) {
            ((float*)ks)[idx] = k_base[jt * 4096 + idx];
            ((float*)vs)[idx] = pv_base[jt * 4096 + idx];
        }
        if (t < 64) crs[t] = cr[jt * 64 + t];
        __syncthreads();

        for (int j = 0; j < 64; j++) {
            float s = crs[j];
#pragma unroll
            for (int k = 0; k < 64; k++) s += q[k] * ks[j][k];
            if (s <= m) {
                float p = __expf(s - m);
                l += p;
#pragma unroll
                for (int d = 0; d < 64; d++) acc[d] += p * vs[j][d];
            } else {
                float sc = __expf(m - s);
                l = l * sc + 1.f;
#pragma unroll
                for (int d = 0; d < 64; d++) acc[d] = acc[d] * sc + vs[j][d];
                m = s;
            }
        }
    }

    float inv = 1.f / l;
    int row = qt * 128 + t;
    float* op = outc + ((size_t)b * 1024 + row) * 1024 + h * 64;
#pragma unroll
    for (int d = 0; d < 64; d++) op[d] = acc[d] * inv;
}

// ---------------------------------------------------------------------------
// Launch
// ---------------------------------------------------------------------------
extern "C" void kernel_launch(void* const* d_in, const int* in_sizes, int n_in,
                              void* d_out, int out_size)
{
    const float* w_feat = (const float*)d_in[0];
    const float* v_feat = (const float*)d_in[1];
    const float* Ww1  = (const float*)d_in[2];
    const float* bw1  = (const float*)d_in[3];
    const float* Wv1  = (const float*)d_in[4];
    const float* bv1  = (const float*)d_in[5];
    const float* Wv2  = (const float*)d_in[6];
    const float* bv2  = (const float*)d_in[7];
    const float* Wv3  = (const float*)d_in[8];
    const float* bv3  = (const float*)d_in[9];
    const float* Wv4  = (const float*)d_in[10];
    const float* bv4  = (const float*)d_in[11];
    const float* Wout = (const float*)d_in[12];
    const float* bout = (const float*)d_in[13];
    float* out = (float*)d_out;

    float *w1p, *v1p, *v2p, *v3p, *v4p, *Sp, *crp, *ctxp;
    cudaGetSymbolAddress((void**)&w1p, g_w1);
    cudaGetSymbolAddress((void**)&v1p, g_v1);
    cudaGetSymbolAddress((void**)&v2p, g_v2);
    cudaGetSymbolAddress((void**)&v3p, g_v3);
    cudaGetSymbolAddress((void**)&v4p, g_v4);
    cudaGetSymbolAddress((void**)&Sp,  g_S);
    cudaGetSymbolAddress((void**)&crp, g_cr);
    cudaGetSymbolAddress((void**)&ctxp, g_ctx);

    // Projections (head-layout outputs)
    sgemm_proj<<<dim3(8, 4),  256>>>(w_feat, Ww1, bw1, w1p, 512,  128,  0);
    sgemm_proj<<<dim3(8, 32), 256>>>(v_feat, Wv1, bv1, v1p, 4096, 1024, 0);
    sgemm_proj<<<dim3(8, 32), 256>>>(v_feat, Wv2, bv2, v2p, 4096, 1024, 0);
    sgemm_proj<<<dim3(8, 32), 256>>>(v_feat, Wv3, bv3, v3p, 4096, 1024, 0);
    sgemm_proj<<<dim3(8, 32), 256>>>(v_feat, Wv4, bv4, v4p, 4096, 1024, 0);

    // Cross-attention bias: S = w1 @ v3^T, row-softmax, column-sum over w
    cross_scores<<<dim3(8, 64), 256>>>(w1p, v3p, Sp);
    softmax_rows<<<8192, 256>>>(Sp);
    cross_colsum<<<64, 1024>>>(Sp, crp);

    // Fused self-attention with bias, writes concat layout
    attn_kernel<<<dim3(8, 64), 128>>>(v1p, v2p, v4p, crp, ctxp);

    // Output projection
    sgemm_proj<<<dim3(8, 32), 256>>>(ctxp, Wout, bout, out, 4096, 1024, 1);
}

// round 3
// speedup vs baseline: 1.5338x; 1.5338x over previous
#include <cuda_runtime.h>
#include <cuda_bf16.h>
#include <cstdint>
#include <math.h>

// ---------------------------------------------------------------------------
// Shapes: bs=4, H=16, DK=64, D=1024, n_w=128, n_v=1024
// GEMMs: mma.sync (HMMA) bf16x3 error-compensated (hi/lo split), fp32 accum.
// NOTE: harness ptxas targets base sm_103 -> tcgen05/cta_group unavailable.
// ---------------------------------------------------------------------------

__device__ __forceinline__ uint32_t smem_u32(const void* p) {
    uint32_t a;
    asm("{ .reg .u64 t; cvta.to.shared.u64 t, %1; cvt.u32.u64 %0, t; }"
        : "=r"(a) : "l"(p));
    return a;
}

__device__ __forceinline__ void cp_async16(uint32_t dst, const void* src) {
    asm volatile("cp.async.cg.shared.global [%0], [%1], 16;"
                 :: "r"(dst), "l"(src) : "memory");
}
__device__ __forceinline__ void cp_commit() {
    asm volatile("cp.async.commit_group;" ::: "memory");
}
__device__ __forceinline__ void cp_wait0() {
    asm volatile("cp.async.wait_group 0;" ::: "memory");
}

__device__ __forceinline__ void ldmatrix_x4(uint32_t* r, uint32_t addr) {
    asm volatile("ldmatrix.sync.aligned.m8n8.x4.shared.b16 {%0,%1,%2,%3}, [%4];"
                 : "=r"(r[0]), "=r"(r[1]), "=r"(r[2]), "=r"(r[3]) : "r"(addr));
}
__device__ __forceinline__ void ldmatrix_x2(uint32_t* r, uint32_t addr) {
    asm volatile("ldmatrix.sync.aligned.m8n8.x2.shared.b16 {%0,%1}, [%2];"
                 : "=r"(r[0]), "=r"(r[1]) : "r"(addr));
}

__device__ __forceinline__ void mma_bf16(float* c, const uint32_t* a, const uint32_t* b) {
    asm volatile(
        "mma.sync.aligned.m16n8k16.row.col.f32.bf16.bf16.f32 "
        "{%0,%1,%2,%3}, {%4,%5,%6,%7}, {%8,%9}, {%0,%1,%2,%3};"
        : "+f"(c[0]), "+f"(c[1]), "+f"(c[2]), "+f"(c[3])
        : "r"(a[0]), "r"(a[1]), "r"(a[2]), "r"(a[3]), "r"(b[0]), "r"(b[1]));
}

// ----------------------------- scratch ------------------------------------
__device__ __align__(256) float g_w1[4 * 16 * 128 * 64];
__device__ __align__(256) float g_v1[4 * 16 * 1024 * 64];
__device__ __align__(256) float g_v2[4 * 16 * 1024 * 64];
__device__ __align__(256) float g_v3[4 * 16 * 1024 * 64];
__device__ __align__(256) float g_v4[4 * 16 * 1024 * 64];
__device__ __align__(256) float g_S [4 * 16 * 128 * 1024];
__device__ __align__(256) float g_cr[4 * 16 * 1024];
__device__ __align__(256) float g_ctx[4 * 1024 * 1024];

__device__ __align__(256) __nv_bfloat16 g_Ahv[4194304], g_Alv[4194304];
__device__ __align__(256) __nv_bfloat16 g_Ahw[524288],  g_Alw[524288];
__device__ __align__(256) __nv_bfloat16 g_Wh[6 * 1048576], g_Wl[6 * 1048576];
__device__ __align__(256) __nv_bfloat16 g_Ch[4194304],  g_Cl[4194304];

// ----------------------------- split fp32 -> bf16 hi/lo -------------------
__global__ void __launch_bounds__(256) split_kernel(
    const float* __restrict__ x, __nv_bfloat16* __restrict__ hi,
    __nv_bfloat16* __restrict__ lo, int n4)
{
    int i = blockIdx.x * 256 + threadIdx.x;
    if (i >= n4) return;
    float4 v = ((const float4*)x)[i];
    __nv_bfloat16 h0 = __float2bfloat16(v.x);
    __nv_bfloat16 h1 = __float2bfloat16(v.y);
    __nv_bfloat16 h2 = __float2bfloat16(v.z);
    __nv_bfloat16 h3 = __float2bfloat16(v.w);
    __nv_bfloat16 l0 = __float2bfloat16(v.x - __bfloat162float(h0));
    __nv_bfloat16 l1 = __float2bfloat16(v.y - __bfloat162float(h1));
    __nv_bfloat16 l2 = __float2bfloat16(v.z - __bfloat162float(h2));
    __nv_bfloat16 l3 = __float2bfloat16(v.w - __bfloat162float(h3));
    __nv_bfloat162* hp = (__nv_bfloat162*)hi;
    __nv_bfloat162* lp = (__nv_bfloat162*)lo;
    hp[2 * i]     = __nv_bfloat162{h0, h1};
    hp[2 * i + 1] = __nv_bfloat162{h2, h3};
    lp[2 * i]     = __nv_bfloat162{l0, l1};
    lp[2 * i + 1] = __nv_bfloat162{l2, l3};
}

// ----------------------------- HMMA GEMM ----------------------------------
// C[m][o] = sum_k A[m][k]*W[o][k] + bias[o]; K=1024 fixed.
// Tiles: 128x128 CTA, BK=32, double-buffered cp.async.
// Warp layout: 8 warps = 2(m) x 4(n); warp tile 64x32.
// smem tile: [128 rows][40 bf16] (80B pitch, conflict-free ldmatrix).
// Stage layout: Ah(0) Al(10240) Wh(20480) Wl(30720); stage stride 40960.
// mode 0: head scatter out[((b*16+h)*n_per_b+i)*64+d]; mode 1: flat.
static constexpr int GPITCH = 80;                 // bytes per smem row
static constexpr int TILE_BYTES = 128 * GPITCH;   // 10240
static constexpr int STAGE_BYTES = 4 * TILE_BYTES;
static constexpr int GEMM_SMEM_BYTES = 2 * STAGE_BYTES;  // 81920

__global__ void __launch_bounds__(256) hmma_gemm(
    const __nv_bfloat16* __restrict__ Ah, const __nv_bfloat16* __restrict__ Al,
    const __nv_bfloat16* __restrict__ Wh, const __nv_bfloat16* __restrict__ Wl,
    const float* __restrict__ bias, float* __restrict__ out,
    int n_per_b, int mode)
{
    extern __shared__ char smem[];
    const uint32_t sb = smem_u32(smem);
    int t = threadIdx.x;
    int lane = t & 31, wid = t >> 5;
    int bm = blockIdx.y * 128, bn = blockIdx.x * 128;
    int wm = (wid & 1) * 64;
    int wn = (wid >> 1) * 32;

    float acc[4][4][4];
#pragma unroll
    for (int i = 0; i < 4; i++)
#pragma unroll
        for (int j = 0; j < 4; j++)
#pragma unroll
            for (int k = 0; k < 4; k++) acc[i][j][k] = 0.f;

    // per-thread load coords: chunk t and t+256 of 512 (16B chunks)
    int r0 = t >> 2, c0 = t & 3;          // chunk t
    int r1 = (t + 256) >> 2, c1 = t & 3;  // chunk t+256

    const __nv_bfloat16* srcs[4] = {Ah, Al, Wh, Wl};
    int rowoff[4] = {bm, bm, bn, bn};

    auto stage_load = [&](int s, int k0) {
        uint32_t base = sb + s * STAGE_BYTES;
#pragma unroll
        for (int tile = 0; tile < 4; tile++) {
            const __nv_bfloat16* g = srcs[tile] + (size_t)rowoff[tile] * 1024 + k0;
            uint32_t tb = base + tile * TILE_BYTES;
            cp_async16(tb + r0 * GPITCH + c0 * 16, g + (size_t)r0 * 1024 + c0 * 8);
            cp_async16(tb + r1 * GPITCH + c1 * 16, g + (size_t)r1 * 1024 + c1 * 8);
        }
        cp_commit();
    };

    stage_load(0, 0);

    // ldmatrix lane-address components
    int a_r = (lane & 15);          // row within 16
    int a_c = (lane >> 4) << 3;     // 0 or 8 (k offset)
    int b_r = (lane & 7);
    int b_c = ((lane >> 3) & 1) << 3;

    for (int c = 0; c < 32; c++) {
        cp_wait0();
        __syncthreads();
        if (c + 1 < 32) stage_load((c + 1) & 1, (c + 1) * 32);

        uint32_t base = sb + (c & 1) * STAGE_BYTES;
        uint32_t tAh = base, tAl = base + TILE_BYTES;
        uint32_t tWh = base + 2 * TILE_BYTES, tWl = base + 3 * TILE_BYTES;

#pragma unroll
        for (int kk = 0; kk < 32; kk += 16) {
            uint32_t ah[4][4], al[4][4], bh[4][2], bl[4][2];
#pragma unroll
            for (int mt = 0; mt < 4; mt++) {
                uint32_t off = (uint32_t)((wm + mt * 16 + a_r) * GPITCH + (kk + a_c) * 2);
                ldmatrix_x4(ah[mt], tAh + off);
                ldmatrix_x4(al[mt], tAl + off);
            }
#pragma unroll
            for (int nt = 0; nt < 4; nt++) {
                uint32_t off = (uint32_t)((wn + nt * 8 + b_r) * GPITCH + (kk + b_c) * 2);
                ldmatrix_x2(bh[nt], tWh + off);
                ldmatrix_x2(bl[nt], tWl + off);
            }
#pragma unroll
            for (int mt = 0; mt < 4; mt++)
#pragma unroll
                for (int nt = 0; nt < 4; nt++) {
                    mma_bf16(acc[mt][nt], ah[mt], bh[nt]);
                    mma_bf16(acc[mt][nt], ah[mt], bl[nt]);
                    mma_bf16(acc[mt][nt], al[mt], bh[nt]);
                }
        }
        __syncthreads();
    }

    // epilogue
#pragma unroll
    for (int mt = 0; mt < 4; mt++) {
        int row_a = bm + wm + mt * 16 + (lane >> 2);
#pragma unroll
        for (int rr = 0; rr < 2; rr++) {
            int row = row_a + rr * 8;
            int b = row / n_per_b;
            int ii = row % n_per_b;
#pragma unroll
            for (int nt = 0; nt < 4; nt++) {
                int o = bn + wn + nt * 8 + (lane & 3) * 2;
                float2 v;
                v.x = acc[mt][nt][rr * 2 + 0] + bias[o];
                v.y = acc[mt][nt][rr * 2 + 1] + bias[o + 1];
                if (mode == 0) {
                    int h = o >> 6, d = o & 63;
                    *(float2*)&out[(((size_t)(b * 16 + h) * n_per_b + ii) << 6) + d] = v;
                } else {
                    *(float2*)&out[(size_t)row * 1024 + o] = v;
                }
            }
        }
    }
}

// ---------------------------------------------------------------------------
// Cross scores: per (bh), S[w][v] = w1[bh,w,:] . v3[bh,v,:], K=64 (scalar)
// ---------------------------------------------------------------------------
__global__ void __launch_bounds__(256) cross_scores(
    const float* __restrict__ w1, const float* __restrict__ v3,
    float* __restrict__ S)
{
    __shared__ float As[8][128];
    __shared__ float Bs[8][128];

    int bh = blockIdx.y, vt = blockIdx.x;
    int t  = threadIdx.x;
    int tx = t & 15, ty = t >> 4;
    int lr = t >> 1;
    int lk = (t & 1) << 2;

    const float* Ap = w1 + (size_t)bh * 8192  + (size_t)lr * 64 + lk;
    const float* Bp = v3 + (size_t)bh * 65536 + (size_t)vt * 8192 + (size_t)lr * 64 + lk;

    float acc[8][8];
#pragma unroll
    for (int i = 0; i < 8; i++)
#pragma unroll
        for (int j = 0; j < 8; j++) acc[i][j] = 0.f;

    for (int k0 = 0; k0 < 64; k0 += 8) {
        float4 a4 = *(const float4*)(Ap + k0);
        float4 b4 = *(const float4*)(Bp + k0);
        __syncthreads();
        As[lk + 0][lr] = a4.x; As[lk + 1][lr] = a4.y;
        As[lk + 2][lr] = a4.z; As[lk + 3][lr] = a4.w;
        Bs[lk + 0][lr] = b4.x; Bs[lk + 1][lr] = b4.y;
        Bs[lk + 2][lr] = b4.z; Bs[lk + 3][lr] = b4.w;
        __syncthreads();
#pragma unroll
        for (int kk = 0; kk < 8; kk++) {
            float ar[8], br[8];
#pragma unroll
            for (int i = 0; i < 4; i++) {
                ar[i]     = As[kk][ty * 4 + i];
                ar[4 + i] = As[kk][64 + ty * 4 + i];
                br[i]     = Bs[kk][tx * 4 + i];
                br[4 + i] = Bs[kk][64 + tx * 4 + i];
            }
#pragma unroll
            for (int i = 0; i < 8; i++)
#pragma unroll
                for (int j = 0; j < 8; j++)
                    acc[i][j] += ar[i] * br[j];
        }
    }

    float* Sb = S + (size_t)bh * 131072;
#pragma unroll
    for (int i = 0; i < 8; i++) {
        int wv = (i < 4) ? (ty * 4 + i) : (64 + ty * 4 + (i - 4));
#pragma unroll
        for (int j = 0; j < 8; j++) {
            int v = vt * 128 + ((j < 4) ? (tx * 4 + j) : (64 + tx * 4 + (j - 4)));
            Sb[(size_t)wv * 1024 + v] = acc[i][j];
        }
    }
}

__global__ void __launch_bounds__(256) softmax_rows(float* __restrict__ S)
{
    float* p = S + (size_t)blockIdx.x * 1024;
    int t = threadIdx.x;
    __shared__ float sred[8];

    float x[4];
    float mx = -1e30f;
#pragma unroll
    for (int j = 0; j < 4; j++) { x[j] = p[t + 256 * j]; mx = fmaxf(mx, x[j]); }
#pragma unroll
    for (int o = 16; o; o >>= 1) mx = fmaxf(mx, __shfl_xor_sync(0xffffffffu, mx, o));
    if ((t & 31) == 0) sred[t >> 5] = mx;
    __syncthreads();
    float bm = sred[0];
#pragma unroll
    for (int w = 1; w < 8; w++) bm = fmaxf(bm, sred[w]);
    __syncthreads();

    float sum = 0.f;
#pragma unroll
    for (int j = 0; j < 4; j++) { x[j] = __expf(x[j] - bm); sum += x[j]; }
#pragma unroll
    for (int o = 16; o; o >>= 1) sum += __shfl_xor_sync(0xffffffffu, sum, o);
    if ((t & 31) == 0) sred[t >> 5] = sum;
    __syncthreads();
    float tot = 0.f;
#pragma unroll
    for (int w = 0; w < 8; w++) tot += sred[w];
    float inv = 1.f / tot;
#pragma unroll
    for (int j = 0; j < 4; j++) p[t + 256 * j] = x[j] * inv;
}

__global__ void __launch_bounds__(1024) cross_colsum(
    const float* __restrict__ S, float* __restrict__ cross)
{
    int bh = blockIdx.x;
    int v  = threadIdx.x;
    const float* base = S + (size_t)bh * 131072 + v;
    float a = 0.f;
#pragma unroll
    for (int w = 0; w < 128; w++) a += base[(size_t)w * 1024];
    cross[(size_t)bh * 1024 + v] = a;
}

// ---------------------------------------------------------------------------
// Flash self-attention with per-key bias (float4 smem reads).
// ---------------------------------------------------------------------------
__global__ void __launch_bounds__(128) attn_kernel(
    const float* __restrict__ v1, const float* __restrict__ v2,
    const float* __restrict__ v4, const float* __restrict__ cross,
    float* __restrict__ outc)
{
    int bh = blockIdx.y;
    int qt = blockIdx.x;
    int t  = threadIdx.x;
    int b  = bh >> 4, h = bh & 15;

    const float4* q_base  = (const float4*)(v1 + (size_t)bh * 65536 + (size_t)qt * 8192);
    const float4* k_base  = (const float4*)(v2 + (size_t)bh * 65536);
    const float4* pv_base = (const float4*)(v4 + (size_t)bh * 65536);
    const float* cr       = cross + (size_t)bh * 1024;

    __shared__ float4 ks[64 * 16];
    __shared__ float4 vs[64 * 16];
    __shared__ float crs[64];

    float4 q[16];
#pragma unroll
    for (int half = 0; half < 2; half++) {
        __syncthreads();
        for (int idx = t; idx < 1024; idx += 128)
            ks[idx] = q_base[half * 1024 + idx];
        __syncthreads();
        if ((t >> 6) == half) {
            int r = t & 63;
#pragma unroll
            for (int k = 0; k < 16; k++) q[k] = ks[r * 16 + k];
        }
    }

    float4 acc[16];
#pragma unroll
    for (int d = 0; d < 16; d++) acc[d] = float4{0.f, 0.f, 0.f, 0.f};
    float m = -1e30f, l = 0.f;

    for (int jt = 0; jt < 16; jt++) {
        __syncthreads();
        for (int idx = t; idx < 1024; idx += 128) {
            ks[idx] = k_base[jt * 1024 + idx];
            vs[idx] = pv_base[jt * 1024 + idx];
        }
        if (t < 64) crs[t] = cr[jt * 64 + t];
        __syncthreads();

        for (int j = 0; j < 64; j++) {
            const float4* kr = &ks[j * 16];
            float s = crs[j];
#pragma unroll
            for (int k = 0; k < 16; k++) {
                float4 kk = kr[k];
                s += q[k].x * kk.x + q[k].y * kk.y + q[k].z * kk.z + q[k].w * kk.w;
            }
            const float4* vr = &vs[j * 16];
            if (s <= m) {
                float p = __expf(s - m);
                l += p;
#pragma unroll
                for (int d = 0; d < 16; d++) {
                    float4 vv = vr[d];
                    acc[d].x += p * vv.x; acc[d].y += p * vv.y;
                    acc[d].z += p * vv.z; acc[d].w += p * vv.w;
                }
            } else {
                float sc = __expf(m - s);
                l = l * sc + 1.f;
#pragma unroll
                for (int d = 0; d < 16; d++) {
                    float4 vv = vr[d];
                    acc[d].x = acc[d].x * sc + vv.x; acc[d].y = acc[d].y * sc + vv.y;
                    acc[d].z = acc[d].z * sc + vv.z; acc[d].w = acc[d].w * sc + vv.w;
                }
                m = s;
            }
        }
    }

    float inv = 1.f / l;
    int row = qt * 128 + t;
    float4* op = (float4*)(outc + ((size_t)b * 1024 + row) * 1024 + h * 64);
#pragma unroll
    for (int d = 0; d < 16; d++) {
        float4 v = acc[d];
        v.x *= inv; v.y *= inv; v.z *= inv; v.w *= inv;
        op[d] = v;
    }
}

// ---------------------------------------------------------------------------
// Launch
// ---------------------------------------------------------------------------
extern "C" void kernel_launch(void* const* d_in, const int* in_sizes, int n_in,
                              void* d_out, int out_size)
{
    const float* w_feat = (const float*)d_in[0];
    const float* v_feat = (const float*)d_in[1];
    const float* Ww1  = (const float*)d_in[2];
    const float* bw1  = (const float*)d_in[3];
    const float* Wv1  = (const float*)d_in[4];
    const float* bv1  = (const float*)d_in[5];
    const float* Wv2  = (const float*)d_in[6];
    const float* bv2  = (const float*)d_in[7];
    const float* Wv3  = (const float*)d_in[8];
    const float* bv3  = (const float*)d_in[9];
    const float* Wv4  = (const float*)d_in[10];
    const float* bv4  = (const float*)d_in[11];
    const float* Wout = (const float*)d_in[12];
    const float* bout = (const float*)d_in[13];
    float* out = (float*)d_out;

    float *w1p, *v1p, *v2p, *v3p, *v4p, *Sp, *crp, *ctxp;
    cudaGetSymbolAddress((void**)&w1p, g_w1);
    cudaGetSymbolAddress((void**)&v1p, g_v1);
    cudaGetSymbolAddress((void**)&v2p, g_v2);
    cudaGetSymbolAddress((void**)&v3p, g_v3);
    cudaGetSymbolAddress((void**)&v4p, g_v4);
    cudaGetSymbolAddress((void**)&Sp,  g_S);
    cudaGetSymbolAddress((void**)&crp, g_cr);
    cudaGetSymbolAddress((void**)&ctxp, g_ctx);

    __nv_bfloat16 *Ahv, *Alv, *Ahw, *Alw, *Whp, *Wlp, *Chp, *Clp;
    cudaGetSymbolAddress((void**)&Ahv, g_Ahv);
    cudaGetSymbolAddress((void**)&Alv, g_Alv);
    cudaGetSymbolAddress((void**)&Ahw, g_Ahw);
    cudaGetSymbolAddress((void**)&Alw, g_Alw);
    cudaGetSymbolAddress((void**)&Whp, g_Wh);
    cudaGetSymbolAddress((void**)&Wlp, g_Wl);
    cudaGetSymbolAddress((void**)&Chp, g_Ch);
    cudaGetSymbolAddress((void**)&Clp, g_Cl);

    cudaFuncSetAttribute(hmma_gemm, cudaFuncAttributeMaxDynamicSharedMemorySize,
                         GEMM_SMEM_BYTES);

    // hi/lo splits
    split_kernel<<<4096, 256>>>(v_feat, Ahv, Alv, 1048576);
    split_kernel<<<512,  256>>>(w_feat, Ahw, Alw, 131072);
    const float* Ws[6] = {Wv1, Wv2, Wv3, Wv4, Ww1, Wout};
    for (int i = 0; i < 6; i++)
        split_kernel<<<1024, 256>>>(Ws[i], Whp + (size_t)i * 1048576,
                                    Wlp + (size_t)i * 1048576, 262144);

    // projections (HMMA)
    hmma_gemm<<<dim3(8, 32), 256, GEMM_SMEM_BYTES>>>(Ahv, Alv, Whp + 0*1048576, Wlp + 0*1048576, bv1, v1p, 1024, 0);
    hmma_gemm<<<dim3(8, 32), 256, GEMM_SMEM_BYTES>>>(Ahv, Alv, Whp + 1*1048576, Wlp + 1*1048576, bv2, v2p, 1024, 0);
    hmma_gemm<<<dim3(8, 32), 256, GEMM_SMEM_BYTES>>>(Ahv, Alv, Whp + 2*1048576, Wlp + 2*1048576, bv3, v3p, 1024, 0);
    hmma_gemm<<<dim3(8, 32), 256, GEMM_SMEM_BYTES>>>(Ahv, Alv, Whp + 3*1048576, Wlp + 3*1048576, bv4, v4p, 1024, 0);
    hmma_gemm<<<dim3(8, 4),  256, GEMM_SMEM_BYTES>>>(Ahw, Alw, Whp + 4*1048576, Wlp + 4*1048576, bw1, w1p, 128, 0);

    // cross-attention bias path
    cross_scores<<<dim3(8, 64), 256>>>(w1p, v3p, Sp);
    softmax_rows<<<8192, 256>>>(Sp);
    cross_colsum<<<64, 1024>>>(Sp, crp);

    // fused self-attention
    attn_kernel<<<dim3(8, 64), 128>>>(v1p, v2p, v4p, crp, ctxp);

    // output projection
    split_kernel<<<4096, 256>>>(ctxp, Chp, Clp, 1048576);
    hmma_gemm<<<dim3(8, 32), 256, GEMM_SMEM_BYTES>>>(Chp, Clp, Whp + 5*1048576, Wlp + 5*1048576, bout, out, 1024, 1);
}

// round 4
// speedup vs baseline: 2.7845x; 1.8155x over previous
#include <cuda_runtime.h>
#include <cuda_bf16.h>
#include <cstdint>
#include <math.h>

// ---------------------------------------------------------------------------
// Shapes: bs=4, H=16, DK=64, D=1024, n_w=128, n_v=1024
// GEMMs + self-attention on HMMA (mma.sync bf16x3 error-compensated).
// Base sm_103 target: no tcgen05; mma.sync/ldmatrix/cp.async only.
// ---------------------------------------------------------------------------

__device__ __forceinline__ uint32_t smem_u32(const void* p) {
    uint32_t a;
    asm("{ .reg .u64 t; cvta.to.shared.u64 t, %1; cvt.u32.u64 %0, t; }"
        : "=r"(a) : "l"(p));
    return a;
}

__device__ __forceinline__ void cp_async16(uint32_t dst, const void* src) {
    asm volatile("cp.async.cg.shared.global [%0], [%1], 16;"
                 :: "r"(dst), "l"(src) : "memory");
}
__device__ __forceinline__ void cp_commit() {
    asm volatile("cp.async.commit_group;" ::: "memory");
}
__device__ __forceinline__ void cp_wait0() {
    asm volatile("cp.async.wait_group 0;" ::: "memory");
}

__device__ __forceinline__ void ldmatrix_x4(uint32_t* r, uint32_t addr) {
    asm volatile("ldmatrix.sync.aligned.m8n8.x4.shared.b16 {%0,%1,%2,%3}, [%4];"
                 : "=r"(r[0]), "=r"(r[1]), "=r"(r[2]), "=r"(r[3]) : "r"(addr));
}
__device__ __forceinline__ void ldmatrix_x2(uint32_t* r, uint32_t addr) {
    asm volatile("ldmatrix.sync.aligned.m8n8.x2.shared.b16 {%0,%1}, [%2];"
                 : "=r"(r[0]), "=r"(r[1]) : "r"(addr));
}
__device__ __forceinline__ void ldmatrix_x2_trans(uint32_t* r, uint32_t addr) {
    asm volatile("ldmatrix.sync.aligned.m8n8.x2.trans.shared.b16 {%0,%1}, [%2];"
                 : "=r"(r[0]), "=r"(r[1]) : "r"(addr));
}

__device__ __forceinline__ void mma_bf16(float* c, const uint32_t* a, const uint32_t* b) {
    asm volatile(
        "mma.sync.aligned.m16n8k16.row.col.f32.bf16.bf16.f32 "
        "{%0,%1,%2,%3}, {%4,%5,%6,%7}, {%8,%9}, {%0,%1,%2,%3};"
        : "+f"(c[0]), "+f"(c[1]), "+f"(c[2]), "+f"(c[3])
        : "r"(a[0]), "r"(a[1]), "r"(a[2]), "r"(a[3]), "r"(b[0]), "r"(b[1]));
}

__device__ __forceinline__ uint32_t pack_bf16_hi(float a, float b) {
    __nv_bfloat162 h = __floats2bfloat162_rn(a, b);
    return *(uint32_t*)&h;
}

// ----------------------------- scratch ------------------------------------
__device__ __align__(256) float g_w1[4 * 16 * 128 * 64];
__device__ __align__(256) float g_v3[4 * 16 * 1024 * 64];
__device__ __align__(256) float g_S [4 * 16 * 128 * 1024];
__device__ __align__(256) float g_cr[4 * 16 * 1024];

// bf16 hi/lo tensors for attention
__device__ __align__(256) __nv_bfloat16 g_Qh[4194304], g_Ql[4194304];   // v1
__device__ __align__(256) __nv_bfloat16 g_Kh[4194304], g_Kl[4194304];   // v2
__device__ __align__(256) __nv_bfloat16 g_V4h[4194304], g_V4l[4194304]; // v4

// split inputs
__device__ __align__(256) __nv_bfloat16 g_Ahv[4194304], g_Alv[4194304];
__device__ __align__(256) __nv_bfloat16 g_Ahw[524288],  g_Alw[524288];
__device__ __align__(256) __nv_bfloat16 g_Wh[6 * 1048576], g_Wl[6 * 1048576];
__device__ __align__(256) __nv_bfloat16 g_Ch[4194304],  g_Cl[4194304];   // ctx

// ----------------------------- split fp32 -> bf16 hi/lo -------------------
__global__ void __launch_bounds__(256) split_kernel(
    const float* __restrict__ x, __nv_bfloat16* __restrict__ hi,
    __nv_bfloat16* __restrict__ lo, int n4)
{
    int i = blockIdx.x * 256 + threadIdx.x;
    if (i >= n4) return;
    float4 v = ((const float4*)x)[i];
    __nv_bfloat16 h0 = __float2bfloat16(v.x);
    __nv_bfloat16 h1 = __float2bfloat16(v.y);
    __nv_bfloat16 h2 = __float2bfloat16(v.z);
    __nv_bfloat16 h3 = __float2bfloat16(v.w);
    __nv_bfloat16 l0 = __float2bfloat16(v.x - __bfloat162float(h0));
    __nv_bfloat16 l1 = __float2bfloat16(v.y - __bfloat162float(h1));
    __nv_bfloat16 l2 = __float2bfloat16(v.z - __bfloat162float(h2));
    __nv_bfloat16 l3 = __float2bfloat16(v.w - __bfloat162float(h3));
    __nv_bfloat162* hp = (__nv_bfloat162*)hi;
    __nv_bfloat162* lp = (__nv_bfloat162*)lo;
    hp[2 * i]     = __nv_bfloat162{h0, h1};
    hp[2 * i + 1] = __nv_bfloat162{h2, h3};
    lp[2 * i]     = __nv_bfloat162{l0, l1};
    lp[2 * i + 1] = __nv_bfloat162{l2, l3};
}

// ----------------------------- HMMA GEMM ----------------------------------
// C[m][o] = sum_k A[m][k]*W[o][k] + bias[o]; K=1024.
// mode 0: head-scatter fp32; mode 1: flat fp32; mode 2: head-scatter bf16 hi/lo
static constexpr int GPITCH = 80;
static constexpr int TILE_BYTES = 128 * GPITCH;
static constexpr int STAGE_BYTES = 4 * TILE_BYTES;
static constexpr int GEMM_SMEM_BYTES = 2 * STAGE_BYTES;

__global__ void __launch_bounds__(256) hmma_gemm(
    const __nv_bfloat16* __restrict__ Ah, const __nv_bfloat16* __restrict__ Al,
    const __nv_bfloat16* __restrict__ Wh, const __nv_bfloat16* __restrict__ Wl,
    const float* __restrict__ bias, float* __restrict__ outf,
    __nv_bfloat16* __restrict__ outh, __nv_bfloat16* __restrict__ outl,
    int n_per_b, int mode)
{
    extern __shared__ char smem[];
    const uint32_t sb = smem_u32(smem);
    int t = threadIdx.x;
    int lane = t & 31, wid = t >> 5;
    int bm = blockIdx.y * 128, bn = blockIdx.x * 128;
    int wm = (wid & 1) * 64;
    int wn = (wid >> 1) * 32;

    float acc[4][4][4];
#pragma unroll
    for (int i = 0; i < 4; i++)
#pragma unroll
        for (int j = 0; j < 4; j++)
#pragma unroll
            for (int k = 0; k < 4; k++) acc[i][j][k] = 0.f;

    int r0 = t >> 2, c0 = t & 3;
    int r1 = (t + 256) >> 2, c1 = t & 3;

    const __nv_bfloat16* srcs[4] = {Ah, Al, Wh, Wl};
    int rowoff[4] = {bm, bm, bn, bn};

    auto stage_load = [&](int s, int k0) {
        uint32_t base = sb + s * STAGE_BYTES;
#pragma unroll
        for (int tile = 0; tile < 4; tile++) {
            const __nv_bfloat16* g = srcs[tile] + (size_t)rowoff[tile] * 1024 + k0;
            uint32_t tb = base + tile * TILE_BYTES;
            cp_async16(tb + r0 * GPITCH + c0 * 16, g + (size_t)r0 * 1024 + c0 * 8);
            cp_async16(tb + r1 * GPITCH + c1 * 16, g + (size_t)r1 * 1024 + c1 * 8);
        }
        cp_commit();
    };

    stage_load(0, 0);

    int a_r = (lane & 15);
    int a_c = (lane >> 4) << 3;
    int b_r = (lane & 7);
    int b_c = ((lane >> 3) & 1) << 3;

    for (int c = 0; c < 32; c++) {
        cp_wait0();
        __syncthreads();
        if (c + 1 < 32) stage_load((c + 1) & 1, (c + 1) * 32);

        uint32_t base = sb + (c & 1) * STAGE_BYTES;
        uint32_t tAh = base, tAl = base + TILE_BYTES;
        uint32_t tWh = base + 2 * TILE_BYTES, tWl = base + 3 * TILE_BYTES;

#pragma unroll
        for (int kk = 0; kk < 32; kk += 16) {
            uint32_t ah[4][4], al[4][4], bh[4][2], bl[4][2];
#pragma unroll
            for (int mt = 0; mt < 4; mt++) {
                uint32_t off = (uint32_t)((wm + mt * 16 + a_r) * GPITCH + (kk + a_c) * 2);
                ldmatrix_x4(ah[mt], tAh + off);
                ldmatrix_x4(al[mt], tAl + off);
            }
#pragma unroll
            for (int nt = 0; nt < 4; nt++) {
                uint32_t off = (uint32_t)((wn + nt * 8 + b_r) * GPITCH + (kk + b_c) * 2);
                ldmatrix_x2(bh[nt], tWh + off);
                ldmatrix_x2(bl[nt], tWl + off);
            }
#pragma unroll
            for (int mt = 0; mt < 4; mt++)
#pragma unroll
                for (int nt = 0; nt < 4; nt++) {
                    mma_bf16(acc[mt][nt], ah[mt], bh[nt]);
                    mma_bf16(acc[mt][nt], ah[mt], bl[nt]);
                    mma_bf16(acc[mt][nt], al[mt], bh[nt]);
                }
        }
        __syncthreads();
    }

#pragma unroll
    for (int mt = 0; mt < 4; mt++) {
        int row_a = bm + wm + mt * 16 + (lane >> 2);
#pragma unroll
        for (int rr = 0; rr < 2; rr++) {
            int row = row_a + rr * 8;
            int b = row / n_per_b;
            int ii = row % n_per_b;
#pragma unroll
            for (int nt = 0; nt < 4; nt++) {
                int o = bn + wn + nt * 8 + (lane & 3) * 2;
                float vx = acc[mt][nt][rr * 2 + 0] + bias[o];
                float vy = acc[mt][nt][rr * 2 + 1] + bias[o + 1];
                if (mode == 2) {
                    int h = o >> 6, d = o & 63;
                    size_t idx = ((((size_t)(b * 16 + h) * n_per_b + ii) << 6) + d) >> 1;
                    __nv_bfloat162 h2 = __floats2bfloat162_rn(vx, vy);
                    __nv_bfloat162 l2 = __floats2bfloat162_rn(
                        vx - __bfloat162float(h2.x), vy - __bfloat162float(h2.y));
                    ((__nv_bfloat162*)outh)[idx] = h2;
                    ((__nv_bfloat162*)outl)[idx] = l2;
                } else if (mode == 0) {
                    int h = o >> 6, d = o & 63;
                    *(float2*)&outf[(((size_t)(b * 16 + h) * n_per_b + ii) << 6) + d]
                        = float2{vx, vy};
                } else {
                    *(float2*)&outf[(size_t)row * 1024 + o] = float2{vx, vy};
                }
            }
        }
    }
}

// ---------------------------------------------------------------------------
// Cross scores (scalar fp32, small): S[w][v] = w1 . v3, K=64
// ---------------------------------------------------------------------------
__global__ void __launch_bounds__(256) cross_scores(
    const float* __restrict__ w1, const float* __restrict__ v3,
    float* __restrict__ S)
{
    __shared__ float As[8][128];
    __shared__ float Bs[8][128];

    int bh = blockIdx.y, vt = blockIdx.x;
    int t  = threadIdx.x;
    int tx = t & 15, ty = t >> 4;
    int lr = t >> 1;
    int lk = (t & 1) << 2;

    const float* Ap = w1 + (size_t)bh * 8192  + (size_t)lr * 64 + lk;
    const float* Bp = v3 + (size_t)bh * 65536 + (size_t)vt * 8192 + (size_t)lr * 64 + lk;

    float acc[8][8];
#pragma unroll
    for (int i = 0; i < 8; i++)
#pragma unroll
        for (int j = 0; j < 8; j++) acc[i][j] = 0.f;

    for (int k0 = 0; k0 < 64; k0 += 8) {
        float4 a4 = *(const float4*)(Ap + k0);
        float4 b4 = *(const float4*)(Bp + k0);
        __syncthreads();
        As[lk + 0][lr] = a4.x; As[lk + 1][lr] = a4.y;
        As[lk + 2][lr] = a4.z; As[lk + 3][lr] = a4.w;
        Bs[lk + 0][lr] = b4.x; Bs[lk + 1][lr] = b4.y;
        Bs[lk + 2][lr] = b4.z; Bs[lk + 3][lr] = b4.w;
        __syncthreads();
#pragma unroll
        for (int kk = 0; kk < 8; kk++) {
            float ar[8], br[8];
#pragma unroll
            for (int i = 0; i < 4; i++) {
                ar[i]     = As[kk][ty * 4 + i];
                ar[4 + i] = As[kk][64 + ty * 4 + i];
                br[i]     = Bs[kk][tx * 4 + i];
                br[4 + i] = Bs[kk][64 + tx * 4 + i];
            }
#pragma unroll
            for (int i = 0; i < 8; i++)
#pragma unroll
                for (int j = 0; j < 8; j++)
                    acc[i][j] += ar[i] * br[j];
        }
    }

    float* Sb = S + (size_t)bh * 131072;
#pragma unroll
    for (int i = 0; i < 8; i++) {
        int wv = (i < 4) ? (ty * 4 + i) : (64 + ty * 4 + (i - 4));
#pragma unroll
        for (int j = 0; j < 8; j++) {
            int v = vt * 128 + ((j < 4) ? (tx * 4 + j) : (64 + tx * 4 + (j - 4)));
            Sb[(size_t)wv * 1024 + v] = acc[i][j];
        }
    }
}

__global__ void __launch_bounds__(256) softmax_rows(float* __restrict__ S)
{
    float* p = S + (size_t)blockIdx.x * 1024;
    int t = threadIdx.x;
    __shared__ float sred[8];

    float x[4];
    float mx = -1e30f;
#pragma unroll
    for (int j = 0; j < 4; j++) { x[j] = p[t + 256 * j]; mx = fmaxf(mx, x[j]); }
#pragma unroll
    for (int o = 16; o; o >>= 1) mx = fmaxf(mx, __shfl_xor_sync(0xffffffffu, mx, o));
    if ((t & 31) == 0) sred[t >> 5] = mx;
    __syncthreads();
    float bm = sred[0];
#pragma unroll
    for (int w = 1; w < 8; w++) bm = fmaxf(bm, sred[w]);
    __syncthreads();

    float sum = 0.f;
#pragma unroll
    for (int j = 0; j < 4; j++) { x[j] = __expf(x[j] - bm); sum += x[j]; }
#pragma unroll
    for (int o = 16; o; o >>= 1) sum += __shfl_xor_sync(0xffffffffu, sum, o);
    if ((t & 31) == 0) sred[t >> 5] = sum;
    __syncthreads();
    float tot = 0.f;
#pragma unroll
    for (int w = 0; w < 8; w++) tot += sred[w];
    float inv = 1.f / tot;
#pragma unroll
    for (int j = 0; j < 4; j++) p[t + 256 * j] = x[j] * inv;
}

__global__ void __launch_bounds__(1024) cross_colsum(
    const float* __restrict__ S, float* __restrict__ cross)
{
    int bh = blockIdx.x;
    int v  = threadIdx.x;
    const float* base = S + (size_t)bh * 131072 + v;
    float a = 0.f;
#pragma unroll
    for (int w = 0; w < 128; w++) a += base[(size_t)w * 1024];
    cross[(size_t)bh * 1024 + v] = a;
}

// ---------------------------------------------------------------------------
// HMMA flash self-attention with per-key bias (bf16x3 compensated).
// grid (qt 0..7, bh 0..63), 256 threads (8 warps x 16 q-rows).
// Key blocks of 64, cp.async double-buffered K/V hi/lo (144B pitch).
// Writes ctx directly as bf16 hi/lo in concat layout.
// ---------------------------------------------------------------------------
static constexpr int APITCH = 144;                    // 64 bf16 padded
static constexpr int AQ_BYTES  = 128 * APITCH;        // 18432 per Q tensor
static constexpr int AKV_T     = 64 * APITCH;         // 9216 per KV tensor
static constexpr int AKV_BUF   = 4 * AKV_T + 256;     // + crs (64 floats)
static constexpr int AKV_BASE  = 2 * AQ_BYTES;        // Qh, Ql first
static constexpr int ATTN_SMEM = AKV_BASE + 2 * AKV_BUF;  // 111104

__global__ void __launch_bounds__(256) attn_hmma(
    const __nv_bfloat16* __restrict__ Qh_g, const __nv_bfloat16* __restrict__ Ql_g,
    const __nv_bfloat16* __restrict__ Kh_g, const __nv_bfloat16* __restrict__ Kl_g,
    const __nv_bfloat16* __restrict__ Vh_g, const __nv_bfloat16* __restrict__ Vl_g,
    const float* __restrict__ cross,
    __nv_bfloat16* __restrict__ Ch, __nv_bfloat16* __restrict__ Cl)
{
    extern __shared__ char smem[];
    const uint32_t sb = smem_u32(smem);
    int t = threadIdx.x;
    int lane = t & 31, w = t >> 5;
    int bh = blockIdx.y, qt = blockIdx.x;
    int b = bh >> 4, h = bh & 15;

    const __nv_bfloat16* qh_g = Qh_g + (size_t)bh * 65536 + (size_t)qt * 8192;
    const __nv_bfloat16* ql_g = Ql_g + (size_t)bh * 65536 + (size_t)qt * 8192;
    const __nv_bfloat16* kh_g = Kh_g + (size_t)bh * 65536;
    const __nv_bfloat16* kl_g = Kl_g + (size_t)bh * 65536;
    const __nv_bfloat16* vh_g = Vh_g + (size_t)bh * 65536;
    const __nv_bfloat16* vl_g = Vl_g + (size_t)bh * 65536;
    const float* cr = cross + (size_t)bh * 1024;

    // ---- stage Q (once): 128 rows x 64 bf16, 8 chunks/row, 2 tensors ----
    {
#pragma unroll
        for (int it = 0; it < 4; it++) {
            int ch = t + it * 256;           // 0..1023
            int row = ch >> 3, cc = ch & 7;
            cp_async16(sb + row * APITCH + cc * 16, qh_g + (size_t)row * 64 + cc * 8);
            cp_async16(sb + AQ_BYTES + row * APITCH + cc * 16,
                       ql_g + (size_t)row * 64 + cc * 8);
        }
    }

    auto stage_kv = [&](int s, int kb) {
        uint32_t base = sb + AKV_BASE + s * AKV_BUF;
        int krow0 = kb * 64;
#pragma unroll
        for (int it = 0; it < 2; it++) {
            int ch = t + it * 256;           // 0..511
            int row = ch >> 3, cc = ch & 7;
            size_t g = (size_t)(krow0 + row) * 64 + cc * 8;
            uint32_t d = base + row * APITCH + cc * 16;
            cp_async16(d + 0 * AKV_T, kh_g + g);
            cp_async16(d + 1 * AKV_T, kl_g + g);
            cp_async16(d + 2 * AKV_T, vh_g + g);
            cp_async16(d + 3 * AKV_T, vl_g + g);
        }
        if (t < 16) cp_async16(base + 4 * AKV_T + t * 16, cr + kb * 64 + t * 4);
        cp_commit();
    };

    stage_kv(0, 0);
    cp_wait0();
    __syncthreads();

    // ---- Q fragments (per warp: rows w*16..w*16+15) ----
    uint32_t qh[4][4], ql[4][4];
    {
        int a_r = w * 16 + (lane & 15);
        int a_c = (lane >> 4) << 3;
#pragma unroll
        for (int ks = 0; ks < 4; ks++) {
            uint32_t off = (uint32_t)(a_r * APITCH + (ks * 16 + a_c) * 2);
            ldmatrix_x4(qh[ks], sb + off);
            ldmatrix_x4(ql[ks], sb + AQ_BYTES + off);
        }
    }

    float o[8][4];
#pragma unroll
    for (int i = 0; i < 8; i++)
#pragma unroll
        for (int j = 0; j < 4; j++) o[i][j] = 0.f;
    float m0 = -1e30f, m1 = -1e30f, l0 = 0.f, l1 = 0.f;

    int c2 = (lane & 3) * 2;
    int kb_r = lane & 7;
    int kb_c = ((lane >> 3) & 1) << 3;

    for (int kb = 0; kb < 16; kb++) {
        if (kb + 1 < 16) stage_kv((kb + 1) & 1, kb + 1);

        uint32_t kvb = sb + AKV_BASE + (kb & 1) * AKV_BUF;
        const float* crs = (const float*)(smem + AKV_BASE + (kb & 1) * AKV_BUF + 4 * AKV_T);

        // S init with bias (per-key)
        float s[8][4];
#pragma unroll
        for (int nt = 0; nt < 8; nt++) {
            float b0 = crs[nt * 8 + c2];
            float b1 = crs[nt * 8 + c2 + 1];
            s[nt][0] = b0; s[nt][1] = b1; s[nt][2] = b0; s[nt][3] = b1;
        }

        // S += Qh*Kh + Qh*Kl + Ql*Kh
#pragma unroll
        for (int ks = 0; ks < 4; ks++) {
#pragma unroll
            for (int nt = 0; nt < 8; nt++) {
                uint32_t off = (uint32_t)((nt * 8 + kb_r) * APITCH + (ks * 16 + kb_c) * 2);
                uint32_t kh[2], kl[2];
                ldmatrix_x2(kh, kvb + off);
                ldmatrix_x2(kl, kvb + AKV_T + off);
                mma_bf16(s[nt], qh[ks], kh);
                mma_bf16(s[nt], qh[ks], kl);
                mma_bf16(s[nt], ql[ks], kh);
            }
        }

        // online softmax (two rows per thread: r0=lane>>2, r1=r0+8)
        float mx0 = -1e30f, mx1 = -1e30f;
#pragma unroll
        for (int nt = 0; nt < 8; nt++) {
            mx0 = fmaxf(mx0, fmaxf(s[nt][0], s[nt][1]));
            mx1 = fmaxf(mx1, fmaxf(s[nt][2], s[nt][3]));
        }
        mx0 = fmaxf(mx0, __shfl_xor_sync(0xffffffffu, mx0, 1));
        mx0 = fmaxf(mx0, __shfl_xor_sync(0xffffffffu, mx0, 2));
        mx1 = fmaxf(mx1, __shfl_xor_sync(0xffffffffu, mx1, 1));
        mx1 = fmaxf(mx1, __shfl_xor_sync(0xffffffffu, mx1, 2));
        float mn0 = fmaxf(m0, mx0), mn1 = fmaxf(m1, mx1);
        float sc0 = __expf(m0 - mn0), sc1 = __expf(m1 - mn1);
        m0 = mn0; m1 = mn1;

        float rs0 = 0.f, rs1 = 0.f;
        uint32_t ph0[8], ph1[8], pl0[8], pl1[8];
#pragma unroll
        for (int nt = 0; nt < 8; nt++) {
            float p0 = __expf(s[nt][0] - mn0);
            float p1 = __expf(s[nt][1] - mn0);
            float p2 = __expf(s[nt][2] - mn1);
            float p3 = __expf(s[nt][3] - mn1);
            rs0 += p0 + p1; rs1 += p2 + p3;
            __nv_bfloat162 hA = __floats2bfloat162_rn(p0, p1);
            __nv_bfloat162 hB = __floats2bfloat162_rn(p2, p3);
            ph0[nt] = *(uint32_t*)&hA;
            ph1[nt] = *(uint32_t*)&hB;
            __nv_bfloat162 lA = __floats2bfloat162_rn(
                p0 - __bfloat162float(hA.x), p1 - __bfloat162float(hA.y));
            __nv_bfloat162 lB = __floats2bfloat162_rn(
                p2 - __bfloat162float(hB.x), p3 - __bfloat162float(hB.y));
            pl0[nt] = *(uint32_t*)&lA;
            pl1[nt] = *(uint32_t*)&lB;
        }
        rs0 += __shfl_xor_sync(0xffffffffu, rs0, 1);
        rs0 += __shfl_xor_sync(0xffffffffu, rs0, 2);
        rs1 += __shfl_xor_sync(0xffffffffu, rs1, 1);
        rs1 += __shfl_xor_sync(0xffffffffu, rs1, 2);
        l0 = l0 * sc0 + rs0;
        l1 = l1 * sc1 + rs1;
#pragma unroll
        for (int nt = 0; nt < 8; nt++) {
            o[nt][0] *= sc0; o[nt][1] *= sc0;
            o[nt][2] *= sc1; o[nt][3] *= sc1;
        }

        // O += Ph*Vh + Ph*Vl + Pl*Vh  (ldmatrix.trans on V)
        int v_r = (lane & 7) + ((lane >> 3) & 1) * 8;
#pragma unroll
        for (int kt = 0; kt < 4; kt++) {
            uint32_t ah[4] = {ph0[2 * kt], ph1[2 * kt], ph0[2 * kt + 1], ph1[2 * kt + 1]};
            uint32_t al[4] = {pl0[2 * kt], pl1[2 * kt], pl0[2 * kt + 1], pl1[2 * kt + 1]};
#pragma unroll
            for (int nt = 0; nt < 8; nt++) {
                uint32_t voff = (uint32_t)((kt * 16 + v_r) * APITCH + nt * 16);
                uint32_t vh[2], vl[2];
                ldmatrix_x2_trans(vh, kvb + 2 * AKV_T + voff);
                ldmatrix_x2_trans(vl, kvb + 3 * AKV_T + voff);
                mma_bf16(o[nt], ah, vh);
                mma_bf16(o[nt], ah, vl);
                mma_bf16(o[nt], al, vh);
            }
        }

        if (kb + 1 < 16) {
            __syncthreads();   // all warps done with this buffer
            cp_wait0();
            __syncthreads();   // next buffer visible to all
        }
    }

    // epilogue: ctx rows, write bf16 hi/lo in concat layout
    float inv0 = 1.f / l0, inv1 = 1.f / l1;
    int row0 = qt * 128 + w * 16 + (lane >> 2);
    __nv_bfloat162* Ch2 = (__nv_bfloat162*)Ch;
    __nv_bfloat162* Cl2 = (__nv_bfloat162*)Cl;
#pragma unroll
    for (int nt = 0; nt < 8; nt++) {
        int d = nt * 8 + c2;
        {
            float x0 = o[nt][0] * inv0, x1 = o[nt][1] * inv0;
            __nv_bfloat162 h2 = __floats2bfloat162_rn(x0, x1);
            __nv_bfloat162 l2 = __floats2bfloat162_rn(
                x0 - __bfloat162float(h2.x), x1 - __bfloat162float(h2.y));
            size_t idx = (((size_t)b * 1024 + row0) * 1024 + h * 64 + d) >> 1;
            Ch2[idx] = h2; Cl2[idx] = l2;
        }
        {
            float x0 = o[nt][2] * inv1, x1 = o[nt][3] * inv1;
            __nv_bfloat162 h2 = __floats2bfloat162_rn(x0, x1);
            __nv_bfloat162 l2 = __floats2bfloat162_rn(
                x0 - __bfloat162float(h2.x), x1 - __bfloat162float(h2.y));
            size_t idx = (((size_t)b * 1024 + row0 + 8) * 1024 + h * 64 + d) >> 1;
            Ch2[idx] = h2; Cl2[idx] = l2;
        }
    }
}

// ---------------------------------------------------------------------------
// Launch
// ---------------------------------------------------------------------------
extern "C" void kernel_launch(void* const* d_in, const int* in_sizes, int n_in,
                              void* d_out, int out_size)
{
    const float* w_feat = (const float*)d_in[0];
    const float* v_feat = (const float*)d_in[1];
    const float* Ww1  = (const float*)d_in[2];
    const float* bw1  = (const float*)d_in[3];
    const float* Wv1  = (const float*)d_in[4];
    const float* bv1  = (const float*)d_in[5];
    const float* Wv2  = (const float*)d_in[6];
    const float* bv2  = (const float*)d_in[7];
    const float* Wv3  = (const float*)d_in[8];
    const float* bv3  = (const float*)d_in[9];
    const float* Wv4  = (const float*)d_in[10];
    const float* bv4  = (const float*)d_in[11];
    const float* Wout = (const float*)d_in[12];
    const float* bout = (const float*)d_in[13];
    float* out = (float*)d_out;

    float *w1p, *v3p, *Sp, *crp;
    cudaGetSymbolAddress((void**)&w1p, g_w1);
    cudaGetSymbolAddress((void**)&v3p, g_v3);
    cudaGetSymbolAddress((void**)&Sp,  g_S);
    cudaGetSymbolAddress((void**)&crp, g_cr);

    __nv_bfloat16 *Qh, *Ql, *Kh, *Kl, *V4h, *V4l;
    cudaGetSymbolAddress((void**)&Qh,  g_Qh);
    cudaGetSymbolAddress((void**)&Ql,  g_Ql);
    cudaGetSymbolAddress((void**)&Kh,  g_Kh);
    cudaGetSymbolAddress((void**)&Kl,  g_Kl);
    cudaGetSymbolAddress((void**)&V4h, g_V4h);
    cudaGetSymbolAddress((void**)&V4l, g_V4l);

    __nv_bfloat16 *Ahv, *Alv, *Ahw, *Alw, *Whp, *Wlp, *Chp, *Clp;
    cudaGetSymbolAddress((void**)&Ahv, g_Ahv);
    cudaGetSymbolAddress((void**)&Alv, g_Alv);
    cudaGetSymbolAddress((void**)&Ahw, g_Ahw);
    cudaGetSymbolAddress((void**)&Alw, g_Alw);
    cudaGetSymbolAddress((void**)&Whp, g_Wh);
    cudaGetSymbolAddress((void**)&Wlp, g_Wl);
    cudaGetSymbolAddress((void**)&Chp, g_Ch);
    cudaGetSymbolAddress((void**)&Clp, g_Cl);

    cudaFuncSetAttribute(hmma_gemm, cudaFuncAttributeMaxDynamicSharedMemorySize,
                         GEMM_SMEM_BYTES);
    cudaFuncSetAttribute(attn_hmma, cudaFuncAttributeMaxDynamicSharedMemorySize,
                         ATTN_SMEM);

    // hi/lo splits of inputs
    split_kernel<<<4096, 256>>>(v_feat, Ahv, Alv, 1048576);
    split_kernel<<<512,  256>>>(w_feat, Ahw, Alw, 131072);
    const float* Ws[6] = {Wv1, Wv2, Wv3, Wv4, Ww1, Wout};
    for (int i = 0; i < 6; i++)
        split_kernel<<<1024, 256>>>(Ws[i], Whp + (size_t)i * 1048576,
                                    Wlp + (size_t)i * 1048576, 262144);

    // projections
    hmma_gemm<<<dim3(8, 32), 256, GEMM_SMEM_BYTES>>>(Ahv, Alv, Whp + 0*1048576, Wlp + 0*1048576, bv1, nullptr, Qh,  Ql,  1024, 2);
    hmma_gemm<<<dim3(8, 32), 256, GEMM_SMEM_BYTES>>>(Ahv, Alv, Whp + 1*1048576, Wlp + 1*1048576, bv2, nullptr, Kh,  Kl,  1024, 2);
    hmma_gemm<<<dim3(8, 32), 256, GEMM_SMEM_BYTES>>>(Ahv, Alv, Whp + 2*1048576, Wlp + 2*1048576, bv3, v3p, nullptr, nullptr, 1024, 0);
    hmma_gemm<<<dim3(8, 32), 256, GEMM_SMEM_BYTES>>>(Ahv, Alv, Whp + 3*1048576, Wlp + 3*1048576, bv4, nullptr, V4h, V4l, 1024, 2);
    hmma_gemm<<<dim3(8, 4),  256, GEMM_SMEM_BYTES>>>(Ahw, Alw, Whp + 4*1048576, Wlp + 4*1048576, bw1, w1p, nullptr, nullptr, 128, 0);

    // cross-attention bias path
    cross_scores<<<dim3(8, 64), 256>>>(w1p, v3p, Sp);
    softmax_rows<<<8192, 256>>>(Sp);
    cross_colsum<<<64, 1024>>>(Sp, crp);

    // HMMA flash self-attention -> ctx (bf16 hi/lo, concat layout)
    attn_hmma<<<dim3(8, 64), 256, ATTN_SMEM>>>(Qh, Ql, Kh, Kl, V4h, V4l, crp, Chp, Clp);

    // output projection
    hmma_gemm<<<dim3(8, 32), 256, GEMM_SMEM_BYTES>>>(Chp, Clp, Whp + 5*1048576, Wlp + 5*1048576, bout, out, nullptr, nullptr, 1024, 1);
}

// round 5
// speedup vs baseline: 3.3060x; 1.1873x over previous
#include <cuda_runtime.h>
#include <cuda_bf16.h>
#include <cstdint>
#include <math.h>

// ---------------------------------------------------------------------------
// Shapes: bs=4, H=16, DK=64, D=1024, n_w=128, n_v=1024
// GEMMs + self-attention on HMMA (mma.sync bf16x3 error-compensated).
// Base sm_103 target: no tcgen05; mma.sync/ldmatrix/cp.async only.
// ---------------------------------------------------------------------------

__device__ __forceinline__ uint32_t smem_u32(const void* p) {
    uint32_t a;
    asm("{ .reg .u64 t; cvta.to.shared.u64 t, %1; cvt.u32.u64 %0, t; }"
        : "=r"(a) : "l"(p));
    return a;
}

__device__ __forceinline__ void cp_async16(uint32_t dst, const void* src) {
    asm volatile("cp.async.cg.shared.global [%0], [%1], 16;"
                 :: "r"(dst), "l"(src) : "memory");
}
__device__ __forceinline__ void cp_commit() {
    asm volatile("cp.async.commit_group;" ::: "memory");
}
__device__ __forceinline__ void cp_wait0() {
    asm volatile("cp.async.wait_group 0;" ::: "memory");
}

__device__ __forceinline__ void ldmatrix_x4(uint32_t* r, uint32_t addr) {
    asm volatile("ldmatrix.sync.aligned.m8n8.x4.shared.b16 {%0,%1,%2,%3}, [%4];"
                 : "=r"(r[0]), "=r"(r[1]), "=r"(r[2]), "=r"(r[3]) : "r"(addr));
}
__device__ __forceinline__ void ldmatrix_x2(uint32_t* r, uint32_t addr) {
    asm volatile("ldmatrix.sync.aligned.m8n8.x2.shared.b16 {%0,%1}, [%2];"
                 : "=r"(r[0]), "=r"(r[1]) : "r"(addr));
}
__device__ __forceinline__ void ldmatrix_x2_trans(uint32_t* r, uint32_t addr) {
    asm volatile("ldmatrix.sync.aligned.m8n8.x2.trans.shared.b16 {%0,%1}, [%2];"
                 : "=r"(r[0]), "=r"(r[1]) : "r"(addr));
}

__device__ __forceinline__ void mma_bf16(float* c, const uint32_t* a, const uint32_t* b) {
    asm volatile(
        "mma.sync.aligned.m16n8k16.row.col.f32.bf16.bf16.f32 "
        "{%0,%1,%2,%3}, {%4,%5,%6,%7}, {%8,%9}, {%0,%1,%2,%3};"
        : "+f"(c[0]), "+f"(c[1]), "+f"(c[2]), "+f"(c[3])
        : "r"(a[0]), "r"(a[1]), "r"(a[2]), "r"(a[3]), "r"(b[0]), "r"(b[1]));
}

// ----------------------------- scratch ------------------------------------
__device__ __align__(256) float g_w1[4 * 16 * 128 * 64];
__device__ __align__(256) float g_v3[4 * 16 * 1024 * 64];
__device__ __align__(256) float g_S [4 * 16 * 128 * 1024];
__device__ __align__(256) float g_cr[4 * 16 * 1024];

// bf16 hi/lo tensors for attention
__device__ __align__(256) __nv_bfloat16 g_Qh[4194304], g_Ql[4194304];   // v1
__device__ __align__(256) __nv_bfloat16 g_Kh[4194304], g_Kl[4194304];   // v2
__device__ __align__(256) __nv_bfloat16 g_V4h[4194304], g_V4l[4194304]; // v4

// split inputs
__device__ __align__(256) __nv_bfloat16 g_Ahv[4194304], g_Alv[4194304];
__device__ __align__(256) __nv_bfloat16 g_Ahw[524288],  g_Alw[524288];
__device__ __align__(256) __nv_bfloat16 g_Wh[6 * 1048576], g_Wl[6 * 1048576];
__device__ __align__(256) __nv_bfloat16 g_Ch[4194304],  g_Cl[4194304];   // ctx

// ----------------------------- split fp32 -> bf16 hi/lo -------------------
__global__ void __launch_bounds__(256) split_kernel(
    const float* __restrict__ x, __nv_bfloat16* __restrict__ hi,
    __nv_bfloat16* __restrict__ lo, int n4)
{
    int i = blockIdx.x * 256 + threadIdx.x;
    if (i >= n4) return;
    float4 v = ((const float4*)x)[i];
    __nv_bfloat16 h0 = __float2bfloat16(v.x);
    __nv_bfloat16 h1 = __float2bfloat16(v.y);
    __nv_bfloat16 h2 = __float2bfloat16(v.z);
    __nv_bfloat16 h3 = __float2bfloat16(v.w);
    __nv_bfloat16 l0 = __float2bfloat16(v.x - __bfloat162float(h0));
    __nv_bfloat16 l1 = __float2bfloat16(v.y - __bfloat162float(h1));
    __nv_bfloat16 l2 = __float2bfloat16(v.z - __bfloat162float(h2));
    __nv_bfloat16 l3 = __float2bfloat16(v.w - __bfloat162float(h3));
    __nv_bfloat162* hp = (__nv_bfloat162*)hi;
    __nv_bfloat162* lp = (__nv_bfloat162*)lo;
    hp[2 * i]     = __nv_bfloat162{h0, h1};
    hp[2 * i + 1] = __nv_bfloat162{h2, h3};
    lp[2 * i]     = __nv_bfloat162{l0, l1};
    lp[2 * i + 1] = __nv_bfloat162{l2, l3};
}

// split 4 v-weights in one launch: i4 in [0, 4*262144)
__global__ void __launch_bounds__(256) split4_kernel(
    const float* __restrict__ p0, const float* __restrict__ p1,
    const float* __restrict__ p2, const float* __restrict__ p3,
    __nv_bfloat16* __restrict__ hi, __nv_bfloat16* __restrict__ lo)
{
    int i = blockIdx.x * 256 + threadIdx.x;       // per-weight quad index
    int wsel = i >> 18;                            // 262144 quads per weight
    int j = i & 262143;
    const float* x = (wsel == 0) ? p0 : (wsel == 1) ? p1 : (wsel == 2) ? p2 : p3;
    float4 v = ((const float4*)x)[j];
    __nv_bfloat16 h0 = __float2bfloat16(v.x);
    __nv_bfloat16 h1 = __float2bfloat16(v.y);
    __nv_bfloat16 h2 = __float2bfloat16(v.z);
    __nv_bfloat16 h3 = __float2bfloat16(v.w);
    __nv_bfloat16 l0 = __float2bfloat16(v.x - __bfloat162float(h0));
    __nv_bfloat16 l1 = __float2bfloat16(v.y - __bfloat162float(h1));
    __nv_bfloat16 l2 = __float2bfloat16(v.z - __bfloat162float(h2));
    __nv_bfloat16 l3 = __float2bfloat16(v.w - __bfloat162float(h3));
    __nv_bfloat162* hp = (__nv_bfloat162*)hi;
    __nv_bfloat162* lp = (__nv_bfloat162*)lo;
    hp[2 * i]     = __nv_bfloat162{h0, h1};
    hp[2 * i + 1] = __nv_bfloat162{h2, h3};
    lp[2 * i]     = __nv_bfloat162{l0, l1};
    lp[2 * i + 1] = __nv_bfloat162{l2, l3};
}

// split 2 weights (Ww1, Wout) in one launch
__global__ void __launch_bounds__(256) split2_kernel(
    const float* __restrict__ p0, const float* __restrict__ p1,
    __nv_bfloat16* __restrict__ hi, __nv_bfloat16* __restrict__ lo)
{
    int i = blockIdx.x * 256 + threadIdx.x;
    int wsel = i >> 18;
    int j = i & 262143;
    const float* x = (wsel == 0) ? p0 : p1;
    float4 v = ((const float4*)x)[j];
    __nv_bfloat16 h0 = __float2bfloat16(v.x);
    __nv_bfloat16 h1 = __float2bfloat16(v.y);
    __nv_bfloat16 h2 = __float2bfloat16(v.z);
    __nv_bfloat16 h3 = __float2bfloat16(v.w);
    __nv_bfloat16 l0 = __float2bfloat16(v.x - __bfloat162float(h0));
    __nv_bfloat16 l1 = __float2bfloat16(v.y - __bfloat162float(h1));
    __nv_bfloat16 l2 = __float2bfloat16(v.z - __bfloat162float(h2));
    __nv_bfloat16 l3 = __float2bfloat16(v.w - __bfloat162float(h3));
    __nv_bfloat162* hp = (__nv_bfloat162*)hi;
    __nv_bfloat162* lp = (__nv_bfloat162*)lo;
    hp[2 * i]     = __nv_bfloat162{h0, h1};
    hp[2 * i + 1] = __nv_bfloat162{h2, h3};
    lp[2 * i]     = __nv_bfloat162{l0, l1};
    lp[2 * i + 1] = __nv_bfloat162{l2, l3};
}

// ----------------------------- HMMA GEMM core ------------------------------
static constexpr int GPITCH = 80;
static constexpr int TILE_BYTES = 128 * GPITCH;
static constexpr int STAGE_BYTES = 4 * TILE_BYTES;
static constexpr int GEMM_SMEM_BYTES = 2 * STAGE_BYTES;   // 81920

struct GemmAcc { float a[4][4][4]; };

// mainloop: fills acc for C tile (bm, bn) of A(.,1024) x W(.,1024)^T
__device__ __forceinline__ void gemm_mainloop(
    const __nv_bfloat16* __restrict__ Ah, const __nv_bfloat16* __restrict__ Al,
    const __nv_bfloat16* __restrict__ Wh, const __nv_bfloat16* __restrict__ Wl,
    char* smem, uint32_t sb, int bm, int bn, int t, float acc[4][4][4])
{
    int lane = t & 31, wid = t >> 5;
    int wm = (wid & 1) * 64;
    int wn = (wid >> 1) * 32;

    int r0 = t >> 2, c0 = t & 3;
    int r1 = (t + 256) >> 2;

    const __nv_bfloat16* srcs[4] = {Ah, Al, Wh, Wl};
    int rowoff[4] = {bm, bm, bn, bn};

    auto stage_load = [&](int s, int k0) {
        uint32_t base = sb + s * STAGE_BYTES;
#pragma unroll
        for (int tile = 0; tile < 4; tile++) {
            const __nv_bfloat16* g = srcs[tile] + (size_t)rowoff[tile] * 1024 + k0;
            uint32_t tb = base + tile * TILE_BYTES;
            cp_async16(tb + r0 * GPITCH + c0 * 16, g + (size_t)r0 * 1024 + c0 * 8);
            cp_async16(tb + r1 * GPITCH + c0 * 16, g + (size_t)r1 * 1024 + c0 * 8);
        }
        cp_commit();
    };

    stage_load(0, 0);

    int a_r = (lane & 15);
    int a_c = (lane >> 4) << 3;
    int b_r = (lane & 7);
    int b_c = ((lane >> 3) & 1) << 3;

    for (int c = 0; c < 32; c++) {
        cp_wait0();
        __syncthreads();
        if (c + 1 < 32) stage_load((c + 1) & 1, (c + 1) * 32);

        uint32_t base = sb + (c & 1) * STAGE_BYTES;
        uint32_t tAh = base, tAl = base + TILE_BYTES;
        uint32_t tWh = base + 2 * TILE_BYTES, tWl = base + 3 * TILE_BYTES;

#pragma unroll
        for (int kk = 0; kk < 32; kk += 16) {
            uint32_t ah[4][4], al[4][4], bh[4][2], bl[4][2];
#pragma unroll
            for (int mt = 0; mt < 4; mt++) {
                uint32_t off = (uint32_t)((wm + mt * 16 + a_r) * GPITCH + (kk + a_c) * 2);
                ldmatrix_x4(ah[mt], tAh + off);
                ldmatrix_x4(al[mt], tAl + off);
            }
#pragma unroll
            for (int nt = 0; nt < 4; nt++) {
                uint32_t off = (uint32_t)((wn + nt * 8 + b_r) * GPITCH + (kk + b_c) * 2);
                ldmatrix_x2(bh[nt], tWh + off);
                ldmatrix_x2(bl[nt], tWl + off);
            }
#pragma unroll
            for (int mt = 0; mt < 4; mt++)
#pragma unroll
                for (int nt = 0; nt < 4; nt++) {
                    mma_bf16(acc[mt][nt], ah[mt], bh[nt]);
                    mma_bf16(acc[mt][nt], ah[mt], bl[nt]);
                    mma_bf16(acc[mt][nt], al[mt], bh[nt]);
                }
        }
        __syncthreads();
    }
}

// epilogue helpers
__device__ __forceinline__ void epi_head_bf16(
    float acc[4][4][4], const float* bias, __nv_bfloat16* outh, __nv_bfloat16* outl,
    int bm, int bn, int t)
{
    int lane = t & 31, wid = t >> 5;
    int wm = (wid & 1) * 64, wn = (wid >> 1) * 32;
#pragma unroll
    for (int mt = 0; mt < 4; mt++) {
        int row_a = bm + wm + mt * 16 + (lane >> 2);
#pragma unroll
        for (int rr = 0; rr < 2; rr++) {
            int row = row_a + rr * 8;
            int b = row >> 10, ii = row & 1023;
#pragma unroll
            for (int nt = 0; nt < 4; nt++) {
                int o = bn + wn + nt * 8 + (lane & 3) * 2;
                float vx = acc[mt][nt][rr * 2 + 0] + bias[o];
                float vy = acc[mt][nt][rr * 2 + 1] + bias[o + 1];
                int h = o >> 6, d = o & 63;
                size_t idx = ((((size_t)(b * 16 + h) << 10) + ii << 6) + d) >> 1;
                __nv_bfloat162 h2 = __floats2bfloat162_rn(vx, vy);
                __nv_bfloat162 l2 = __floats2bfloat162_rn(
                    vx - __bfloat162float(h2.x), vy - __bfloat162float(h2.y));
                ((__nv_bfloat162*)outh)[idx] = h2;
                ((__nv_bfloat162*)outl)[idx] = l2;
            }
        }
    }
}

__device__ __forceinline__ void epi_head_f32(
    float acc[4][4][4], const float* bias, float* outf,
    int bm, int bn, int t, int n_per_b)
{
    int lane = t & 31, wid = t >> 5;
    int wm = (wid & 1) * 64, wn = (wid >> 1) * 32;
#pragma unroll
    for (int mt = 0; mt < 4; mt++) {
        int row_a = bm + wm + mt * 16 + (lane >> 2);
#pragma unroll
        for (int rr = 0; rr < 2; rr++) {
            int row = row_a + rr * 8;
            int b = row / n_per_b, ii = row % n_per_b;
#pragma unroll
            for (int nt = 0; nt < 4; nt++) {
                int o = bn + wn + nt * 8 + (lane & 3) * 2;
                float vx = acc[mt][nt][rr * 2 + 0] + bias[o];
                float vy = acc[mt][nt][rr * 2 + 1] + bias[o + 1];
                int h = o >> 6, d = o & 63;
                *(float2*)&outf[(((size_t)(b * 16 + h) * n_per_b + ii) << 6) + d]
                    = float2{vx, vy};
            }
        }
    }
}

// batched v-projection: grid.x = bn*4 + wsel (wsel fastest -> A-tile L2 reuse)
__global__ void __launch_bounds__(256, 2) hmma_gemm_v4(
    const __nv_bfloat16* __restrict__ Ah, const __nv_bfloat16* __restrict__ Al,
    const __nv_bfloat16* __restrict__ WhB, const __nv_bfloat16* __restrict__ WlB,
    const float* __restrict__ bv1, const float* __restrict__ bv2,
    const float* __restrict__ bv3, const float* __restrict__ bv4,
    __nv_bfloat16* __restrict__ Qh, __nv_bfloat16* __restrict__ Ql,
    __nv_bfloat16* __restrict__ Kh, __nv_bfloat16* __restrict__ Kl,
    float* __restrict__ v3, __nv_bfloat16* __restrict__ V4h,
    __nv_bfloat16* __restrict__ V4l)
{
    extern __shared__ char smem[];
    const uint32_t sb = smem_u32(smem);
    int t = threadIdx.x;
    int wsel = blockIdx.x & 3;
    int bn = (blockIdx.x >> 2) * 128;
    int bm = blockIdx.y * 128;

    float acc[4][4][4];
#pragma unroll
    for (int i = 0; i < 4; i++)
#pragma unroll
        for (int j = 0; j < 4; j++)
#pragma unroll
            for (int k = 0; k < 4; k++) acc[i][j][k] = 0.f;

    const __nv_bfloat16* Wh = WhB + (size_t)wsel * 1048576;
    const __nv_bfloat16* Wl = WlB + (size_t)wsel * 1048576;
    gemm_mainloop(Ah, Al, Wh, Wl, smem, sb, bm, bn, t, acc);

    const float* bias = (wsel == 0) ? bv1 : (wsel == 1) ? bv2 : (wsel == 2) ? bv3 : bv4;
    if (wsel == 0)      epi_head_bf16(acc, bias, Qh,  Ql,  bm, bn, t);
    else if (wsel == 1) epi_head_bf16(acc, bias, Kh,  Kl,  bm, bn, t);
    else if (wsel == 3) epi_head_bf16(acc, bias, V4h, V4l, bm, bn, t);
    else                epi_head_f32(acc, bias, v3, bm, bn, t, 1024);
}

// w1 projection (small, head-scatter fp32)
__global__ void __launch_bounds__(256, 2) hmma_gemm_w1(
    const __nv_bfloat16* __restrict__ Ah, const __nv_bfloat16* __restrict__ Al,
    const __nv_bfloat16* __restrict__ Wh, const __nv_bfloat16* __restrict__ Wl,
    const float* __restrict__ bias, float* __restrict__ outf)
{
    extern __shared__ char smem[];
    const uint32_t sb = smem_u32(smem);
    int t = threadIdx.x;
    int bn = blockIdx.x * 128, bm = blockIdx.y * 128;
    float acc[4][4][4];
#pragma unroll
    for (int i = 0; i < 4; i++)
#pragma unroll
        for (int j = 0; j < 4; j++)
#pragma unroll
            for (int k = 0; k < 4; k++) acc[i][j][k] = 0.f;
    gemm_mainloop(Ah, Al, Wh, Wl, smem, sb, bm, bn, t, acc);
    epi_head_f32(acc, bias, outf, bm, bn, t, 128);
}

// output projection (flat fp32)
__global__ void __launch_bounds__(256, 2) hmma_gemm_out(
    const __nv_bfloat16* __restrict__ Ah, const __nv_bfloat16* __restrict__ Al,
    const __nv_bfloat16* __restrict__ Wh, const __nv_bfloat16* __restrict__ Wl,
    const float* __restrict__ bias, float* __restrict__ outf)
{
    extern __shared__ char smem[];
    const uint32_t sb = smem_u32(smem);
    int t = threadIdx.x;
    int bn = blockIdx.x * 128, bm = blockIdx.y * 128;
    float acc[4][4][4];
#pragma unroll
    for (int i = 0; i < 4; i++)
#pragma unroll
        for (int j = 0; j < 4; j++)
#pragma unroll
            for (int k = 0; k < 4; k++) acc[i][j][k] = 0.f;
    gemm_mainloop(Ah, Al, Wh, Wl, smem, sb, bm, bn, t, acc);

    int lane = t & 31, wid = t >> 5;
    int wm = (wid & 1) * 64, wn = (wid >> 1) * 32;
#pragma unroll
    for (int mt = 0; mt < 4; mt++) {
        int row_a = bm + wm + mt * 16 + (lane >> 2);
#pragma unroll
        for (int rr = 0; rr < 2; rr++) {
            int row = row_a + rr * 8;
#pragma unroll
            for (int nt = 0; nt < 4; nt++) {
                int o = bn + wn + nt * 8 + (lane & 3) * 2;
                float vx = acc[mt][nt][rr * 2 + 0] + bias[o];
                float vy = acc[mt][nt][rr * 2 + 1] + bias[o + 1];
                *(float2*)&outf[(size_t)row * 1024 + o] = float2{vx, vy};
            }
        }
    }
}

// ---------------------------------------------------------------------------
// Cross scores path (scalar fp32, small)
// ---------------------------------------------------------------------------
__global__ void __launch_bounds__(256) cross_scores(
    const float* __restrict__ w1, const float* __restrict__ v3,
    float* __restrict__ S)
{
    __shared__ float As[8][128];
    __shared__ float Bs[8][128];

    int bh = blockIdx.y, vt = blockIdx.x;
    int t  = threadIdx.x;
    int tx = t & 15, ty = t >> 4;
    int lr = t >> 1;
    int lk = (t & 1) << 2;

    const float* Ap = w1 + (size_t)bh * 8192  + (size_t)lr * 64 + lk;
    const float* Bp = v3 + (size_t)bh * 65536 + (size_t)vt * 8192 + (size_t)lr * 64 + lk;

    float acc[8][8];
#pragma unroll
    for (int i = 0; i < 8; i++)
#pragma unroll
        for (int j = 0; j < 8; j++) acc[i][j] = 0.f;

    for (int k0 = 0; k0 < 64; k0 += 8) {
        float4 a4 = *(const float4*)(Ap + k0);
        float4 b4 = *(const float4*)(Bp + k0);
        __syncthreads();
        As[lk + 0][lr] = a4.x; As[lk + 1][lr] = a4.y;
        As[lk + 2][lr] = a4.z; As[lk + 3][lr] = a4.w;
        Bs[lk + 0][lr] = b4.x; Bs[lk + 1][lr] = b4.y;
        Bs[lk + 2][lr] = b4.z; Bs[lk + 3][lr] = b4.w;
        __syncthreads();
#pragma unroll
        for (int kk = 0; kk < 8; kk++) {
            float ar[8], br[8];
#pragma unroll
            for (int i = 0; i < 4; i++) {
                ar[i]     = As[kk][ty * 4 + i];
                ar[4 + i] = As[kk][64 + ty * 4 + i];
                br[i]     = Bs[kk][tx * 4 + i];
                br[4 + i] = Bs[kk][64 + tx * 4 + i];
            }
#pragma unroll
            for (int i = 0; i < 8; i++)
#pragma unroll
                for (int j = 0; j < 8; j++)
                    acc[i][j] += ar[i] * br[j];
        }
    }

    float* Sb = S + (size_t)bh * 131072;
#pragma unroll
    for (int i = 0; i < 8; i++) {
        int wv = (i < 4) ? (ty * 4 + i) : (64 + ty * 4 + (i - 4));
#pragma unroll
        for (int j = 0; j < 8; j++) {
            int v = vt * 128 + ((j < 4) ? (tx * 4 + j) : (64 + tx * 4 + (j - 4)));
            Sb[(size_t)wv * 1024 + v] = acc[i][j];
        }
    }
}

__global__ void __launch_bounds__(256) softmax_rows(float* __restrict__ S)
{
    float* p = S + (size_t)blockIdx.x * 1024;
    int t = threadIdx.x;
    __shared__ float sred[8];

    float x[4];
    float mx = -1e30f;
#pragma unroll
    for (int j = 0; j < 4; j++) { x[j] = p[t + 256 * j]; mx = fmaxf(mx, x[j]); }
#pragma unroll
    for (int o = 16; o; o >>= 1) mx = fmaxf(mx, __shfl_xor_sync(0xffffffffu, mx, o));
    if ((t & 31) == 0) sred[t >> 5] = mx;
    __syncthreads();
    float bm = sred[0];
#pragma unroll
    for (int w = 1; w < 8; w++) bm = fmaxf(bm, sred[w]);
    __syncthreads();

    float sum = 0.f;
#pragma unroll
    for (int j = 0; j < 4; j++) { x[j] = __expf(x[j] - bm); sum += x[j]; }
#pragma unroll
    for (int o = 16; o; o >>= 1) sum += __shfl_xor_sync(0xffffffffu, sum, o);
    if ((t & 31) == 0) sred[t >> 5] = sum;
    __syncthreads();
    float tot = 0.f;
#pragma unroll
    for (int w = 0; w < 8; w++) tot += sred[w];
    float inv = 1.f / tot;
#pragma unroll
    for (int j = 0; j < 4; j++) p[t + 256 * j] = x[j] * inv;
}

__global__ void __launch_bounds__(1024) cross_colsum(
    const float* __restrict__ S, float* __restrict__ cross)
{
    int bh = blockIdx.x;
    int v  = threadIdx.x;
    const float* base = S + (size_t)bh * 131072 + v;
    float a = 0.f;
#pragma unroll
    for (int w = 0; w < 128; w++) a += base[(size_t)w * 1024];
    cross[(size_t)bh * 1024 + v] = a;
}

// ---------------------------------------------------------------------------
// HMMA flash self-attention with per-key bias (bf16x3 compensated).
// ---------------------------------------------------------------------------
static constexpr int APITCH = 144;
static constexpr int AQ_BYTES  = 128 * APITCH;
static constexpr int AKV_T     = 64 * APITCH;
static constexpr int AKV_BUF   = 4 * AKV_T + 256;
static constexpr int AKV_BASE  = 2 * AQ_BYTES;
static constexpr int ATTN_SMEM = AKV_BASE + 2 * AKV_BUF;

__global__ void __launch_bounds__(256, 1) attn_hmma(
    const __nv_bfloat16* __restrict__ Qh_g, const __nv_bfloat16* __restrict__ Ql_g,
    const __nv_bfloat16* __restrict__ Kh_g, const __nv_bfloat16* __restrict__ Kl_g,
    const __nv_bfloat16* __restrict__ Vh_g, const __nv_bfloat16* __restrict__ Vl_g,
    const float* __restrict__ cross,
    __nv_bfloat16* __restrict__ Ch, __nv_bfloat16* __restrict__ Cl)
{
    extern __shared__ char smem[];
    const uint32_t sb = smem_u32(smem);
    int t = threadIdx.x;
    int lane = t & 31, w = t >> 5;
    int bh = blockIdx.y, qt = blockIdx.x;
    int b = bh >> 4, h = bh & 15;

    const __nv_bfloat16* qh_g = Qh_g + (size_t)bh * 65536 + (size_t)qt * 8192;
    const __nv_bfloat16* ql_g = Ql_g + (size_t)bh * 65536 + (size_t)qt * 8192;
    const __nv_bfloat16* kh_g = Kh_g + (size_t)bh * 65536;
    const __nv_bfloat16* kl_g = Kl_g + (size_t)bh * 65536;
    const __nv_bfloat16* vh_g = Vh_g + (size_t)bh * 65536;
    const __nv_bfloat16* vl_g = Vl_g + (size_t)bh * 65536;
    const float* cr = cross + (size_t)bh * 1024;

    {
#pragma unroll
        for (int it = 0; it < 4; it++) {
            int ch = t + it * 256;
            int row = ch >> 3, cc = ch & 7;
            cp_async16(sb + row * APITCH + cc * 16, qh_g + (size_t)row * 64 + cc * 8);
            cp_async16(sb + AQ_BYTES + row * APITCH + cc * 16,
                       ql_g + (size_t)row * 64 + cc * 8);
        }
    }

    auto stage_kv = [&](int s, int kb) {
        uint32_t base = sb + AKV_BASE + s * AKV_BUF;
        int krow0 = kb * 64;
#pragma unroll
        for (int it = 0; it < 2; it++) {
            int ch = t + it * 256;
            int row = ch >> 3, cc = ch & 7;
            size_t g = (size_t)(krow0 + row) * 64 + cc * 8;
            uint32_t d = base + row * APITCH + cc * 16;
            cp_async16(d + 0 * AKV_T, kh_g + g);
            cp_async16(d + 1 * AKV_T, kl_g + g);
            cp_async16(d + 2 * AKV_T, vh_g + g);
            cp_async16(d + 3 * AKV_T, vl_g + g);
        }
        if (t < 16) cp_async16(base + 4 * AKV_T + t * 16, cr + kb * 64 + t * 4);
        cp_commit();
    };

    stage_kv(0, 0);
    cp_wait0();
    __syncthreads();

    uint32_t qh[4][4], ql[4][4];
    {
        int a_r = w * 16 + (lane & 15);
        int a_c = (lane >> 4) << 3;
#pragma unroll
        for (int ks = 0; ks < 4; ks++) {
            uint32_t off = (uint32_t)(a_r * APITCH + (ks * 16 + a_c) * 2);
            ldmatrix_x4(qh[ks], sb + off);
            ldmatrix_x4(ql[ks], sb + AQ_BYTES + off);
        }
    }

    float o[8][4];
#pragma unroll
    for (int i = 0; i < 8; i++)
#pragma unroll
        for (int j = 0; j < 4; j++) o[i][j] = 0.f;
    float m0 = -1e30f, m1 = -1e30f, l0 = 0.f, l1 = 0.f;

    int c2 = (lane & 3) * 2;
    int kb_r = lane & 7;
    int kb_c = ((lane >> 3) & 1) << 3;

    for (int kb = 0; kb < 16; kb++) {
        if (kb + 1 < 16) stage_kv((kb + 1) & 1, kb + 1);

        uint32_t kvb = sb + AKV_BASE + (kb & 1) * AKV_BUF;
        const float* crs = (const float*)(smem + AKV_BASE + (kb & 1) * AKV_BUF + 4 * AKV_T);

        float s[8][4];
#pragma unroll
        for (int nt = 0; nt < 8; nt++) {
            float b0 = crs[nt * 8 + c2];
            float b1 = crs[nt * 8 + c2 + 1];
            s[nt][0] = b0; s[nt][1] = b1; s[nt][2] = b0; s[nt][3] = b1;
        }

#pragma unroll
        for (int ks = 0; ks < 4; ks++) {
#pragma unroll
            for (int nt = 0; nt < 8; nt++) {
                uint32_t off = (uint32_t)((nt * 8 + kb_r) * APITCH + (ks * 16 + kb_c) * 2);
                uint32_t kh[2], kl[2];
                ldmatrix_x2(kh, kvb + off);
                ldmatrix_x2(kl, kvb + AKV_T + off);
                mma_bf16(s[nt], qh[ks], kh);
                mma_bf16(s[nt], qh[ks], kl);
                mma_bf16(s[nt], ql[ks], kh);
            }
        }

        float mx0 = -1e30f, mx1 = -1e30f;
#pragma unroll
        for (int nt = 0; nt < 8; nt++) {
            mx0 = fmaxf(mx0, fmaxf(s[nt][0], s[nt][1]));
            mx1 = fmaxf(mx1, fmaxf(s[nt][2], s[nt][3]));
        }
        mx0 = fmaxf(mx0, __shfl_xor_sync(0xffffffffu, mx0, 1));
        mx0 = fmaxf(mx0, __shfl_xor_sync(0xffffffffu, mx0, 2));
        mx1 = fmaxf(mx1, __shfl_xor_sync(0xffffffffu, mx1, 1));
        mx1 = fmaxf(mx1, __shfl_xor_sync(0xffffffffu, mx1, 2));
        float mn0 = fmaxf(m0, mx0), mn1 = fmaxf(m1, mx1);
        float sc0 = __expf(m0 - mn0), sc1 = __expf(m1 - mn1);
        m0 = mn0; m1 = mn1;

        float rs0 = 0.f, rs1 = 0.f;
        uint32_t ph0[8], ph1[8], pl0[8], pl1[8];
#pragma unroll
        for (int nt = 0; nt < 8; nt++) {
            float p0 = __expf(s[nt][0] - mn0);
            float p1 = __expf(s[nt][1] - mn0);
            float p2 = __expf(s[nt][2] - mn1);
            float p3 = __expf(s[nt][3] - mn1);
            rs0 += p0 + p1; rs1 += p2 + p3;
            __nv_bfloat162 hA = __floats2bfloat162_rn(p0, p1);
            __nv_bfloat162 hB = __floats2bfloat162_rn(p2, p3);
            ph0[nt] = *(uint32_t*)&hA;
            ph1[nt] = *(uint32_t*)&hB;
            __nv_bfloat162 lA = __floats2bfloat162_rn(
                p0 - __bfloat162float(hA.x), p1 - __bfloat162float(hA.y));
            __nv_bfloat162 lB = __floats2bfloat162_rn(
                p2 - __bfloat162float(hB.x), p3 - __bfloat162float(hB.y));
            pl0[nt] = *(uint32_t*)&lA;
            pl1[nt] = *(uint32_t*)&lB;
        }
        rs0 += __shfl_xor_sync(0xffffffffu, rs0, 1);
        rs0 += __shfl_xor_sync(0xffffffffu, rs0, 2);
        rs1 += __shfl_xor_sync(0xffffffffu, rs1, 1);
        rs1 += __shfl_xor_sync(0xffffffffu, rs1, 2);
        l0 = l0 * sc0 + rs0;
        l1 = l1 * sc1 + rs1;
#pragma unroll
        for (int nt = 0; nt < 8; nt++) {
            o[nt][0] *= sc0; o[nt][1] *= sc0;
            o[nt][2] *= sc1; o[nt][3] *= sc1;
        }

        int v_r = (lane & 7) + ((lane >> 3) & 1) * 8;
#pragma unroll
        for (int kt = 0; kt < 4; kt++) {
            uint32_t ah[4] = {ph0[2 * kt], ph1[2 * kt], ph0[2 * kt + 1], ph1[2 * kt + 1]};
            uint32_t al[4] = {pl0[2 * kt], pl1[2 * kt], pl0[2 * kt + 1], pl1[2 * kt + 1]};
#pragma unroll
            for (int nt = 0; nt < 8; nt++) {
                uint32_t voff = (uint32_t)((kt * 16 + v_r) * APITCH + nt * 16);
                uint32_t vh[2], vl[2];
                ldmatrix_x2_trans(vh, kvb + 2 * AKV_T + voff);
                ldmatrix_x2_trans(vl, kvb + 3 * AKV_T + voff);
                mma_bf16(o[nt], ah, vh);
                mma_bf16(o[nt], ah, vl);
                mma_bf16(o[nt], al, vh);
            }
        }

        if (kb + 1 < 16) {
            cp_wait0();
            __syncthreads();
        }
    }

    float inv0 = 1.f / l0, inv1 = 1.f / l1;
    int row0 = qt * 128 + w * 16 + (lane >> 2);
    __nv_bfloat162* Ch2 = (__nv_bfloat162*)Ch;
    __nv_bfloat162* Cl2 = (__nv_bfloat162*)Cl;
#pragma unroll
    for (int nt = 0; nt < 8; nt++) {
        int d = nt * 8 + c2;
        {
            float x0 = o[nt][0] * inv0, x1 = o[nt][1] * inv0;
            __nv_bfloat162 h2 = __floats2bfloat162_rn(x0, x1);
            __nv_bfloat162 l2 = __floats2bfloat162_rn(
                x0 - __bfloat162float(h2.x), x1 - __bfloat162float(h2.y));
            size_t idx = (((size_t)b * 1024 + row0) * 1024 + h * 64 + d) >> 1;
            Ch2[idx] = h2; Cl2[idx] = l2;
        }
        {
            float x0 = o[nt][2] * inv1, x1 = o[nt][3] * inv1;
            __nv_bfloat162 h2 = __floats2bfloat162_rn(x0, x1);
            __nv_bfloat162 l2 = __floats2bfloat162_rn(
                x0 - __bfloat162float(h2.x), x1 - __bfloat162float(h2.y));
            size_t idx = (((size_t)b * 1024 + row0 + 8) * 1024 + h * 64 + d) >> 1;
            Ch2[idx] = h2; Cl2[idx] = l2;
        }
    }
}

// ---------------------------------------------------------------------------
// Launch
// ---------------------------------------------------------------------------
extern "C" void kernel_launch(void* const* d_in, const int* in_sizes, int n_in,
                              void* d_out, int out_size)
{
    const float* w_feat = (const float*)d_in[0];
    const float* v_feat = (const float*)d_in[1];
    const float* Ww1  = (const float*)d_in[2];
    const float* bw1  = (const float*)d_in[3];
    const float* Wv1  = (const float*)d_in[4];
    const float* bv1  = (const float*)d_in[5];
    const float* Wv2  = (const float*)d_in[6];
    const float* bv2  = (const float*)d_in[7];
    const float* Wv3  = (const float*)d_in[8];
    const float* bv3  = (const float*)d_in[9];
    const float* Wv4  = (const float*)d_in[10];
    const float* bv4  = (const float*)d_in[11];
    const float* Wout = (const float*)d_in[12];
    const float* bout = (const float*)d_in[13];
    float* out = (float*)d_out;

    float *w1p, *v3p, *Sp, *crp;
    cudaGetSymbolAddress((void**)&w1p, g_w1);
    cudaGetSymbolAddress((void**)&v3p, g_v3);
    cudaGetSymbolAddress((void**)&Sp,  g_S);
    cudaGetSymbolAddress((void**)&crp, g_cr);

    __nv_bfloat16 *Qh, *Ql, *Kh, *Kl, *V4h, *V4l;
    cudaGetSymbolAddress((void**)&Qh,  g_Qh);
    cudaGetSymbolAddress((void**)&Ql,  g_Ql);
    cudaGetSymbolAddress((void**)&Kh,  g_Kh);
    cudaGetSymbolAddress((void**)&Kl,  g_Kl);
    cudaGetSymbolAddress((void**)&V4h, g_V4h);
    cudaGetSymbolAddress((void**)&V4l, g_V4l);

    __nv_bfloat16 *Ahv, *Alv, *Ahw, *Alw, *Whp, *Wlp, *Chp, *Clp;
    cudaGetSymbolAddress((void**)&Ahv, g_Ahv);
    cudaGetSymbolAddress((void**)&Alv, g_Alv);
    cudaGetSymbolAddress((void**)&Ahw, g_Ahw);
    cudaGetSymbolAddress((void**)&Alw, g_Alw);
    cudaGetSymbolAddress((void**)&Whp, g_Wh);
    cudaGetSymbolAddress((void**)&Wlp, g_Wl);
    cudaGetSymbolAddress((void**)&Chp, g_Ch);
    cudaGetSymbolAddress((void**)&Clp, g_Cl);

    cudaFuncSetAttribute(hmma_gemm_v4, cudaFuncAttributeMaxDynamicSharedMemorySize, GEMM_SMEM_BYTES);
    cudaFuncSetAttribute(hmma_gemm_w1, cudaFuncAttributeMaxDynamicSharedMemorySize, GEMM_SMEM_BYTES);
    cudaFuncSetAttribute(hmma_gemm_out, cudaFuncAttributeMaxDynamicSharedMemorySize, GEMM_SMEM_BYTES);
    cudaFuncSetAttribute(attn_hmma, cudaFuncAttributeMaxDynamicSharedMemorySize, ATTN_SMEM);

    // launch 0..3: splits
    split_kernel<<<4096, 256>>>(v_feat, Ahv, Alv, 1048576);
    split_kernel<<<512,  256>>>(w_feat, Ahw, Alw, 131072);
    // v-weights -> slots 0..3 of g_Wh/g_Wl
    split4_kernel<<<4096, 256>>>(Wv1, Wv2, Wv3, Wv4, Whp, Wlp);
    // Ww1 -> slot 4, Wout -> slot 5
    split2_kernel<<<2048, 256>>>(Ww1, Wout, Whp + 4ull * 1048576, Wlp + 4ull * 1048576);

    // launch 4: w1 projection (small)
    hmma_gemm_w1<<<dim3(8, 4), 256, GEMM_SMEM_BYTES>>>(
        Ahw, Alw, Whp + 4ull * 1048576, Wlp + 4ull * 1048576, bw1, w1p);

    // launch 5 (ncu profile target): batched v-projections
    hmma_gemm_v4<<<dim3(32, 32), 256, GEMM_SMEM_BYTES>>>(
        Ahv, Alv, Whp, Wlp, bv1, bv2, bv3, bv4,
        Qh, Ql, Kh, Kl, v3p, V4h, V4l);

    // cross-attention bias path
    cross_scores<<<dim3(8, 64), 256>>>(w1p, v3p, Sp);
    softmax_rows<<<8192, 256>>>(Sp);
    cross_colsum<<<64, 1024>>>(Sp, crp);

    // HMMA flash self-attention
    attn_hmma<<<dim3(8, 64), 256, ATTN_SMEM>>>(Qh, Ql, Kh, Kl, V4h, V4l, crp, Chp, Clp);

    // output projection
    hmma_gemm_out<<<dim3(8, 32), 256, GEMM_SMEM_BYTES>>>(
        Chp, Clp, Whp + 5ull * 1048576, Wlp + 5ull * 1048576, bout, out);
}

// round 6
// speedup vs baseline: 3.3673x; 1.0186x over previous
#include <cuda_runtime.h>
#include <cuda_bf16.h>
#include <cstdint>
#include <math.h>

// ---------------------------------------------------------------------------
// Shapes: bs=4, H=16, DK=64, D=1024, n_w=128, n_v=1024
// GEMMs + self-attention on HMMA (mma.sync bf16x3 error-compensated).
// ---------------------------------------------------------------------------

__device__ __forceinline__ uint32_t smem_u32(const void* p) {
    uint32_t a;
    asm("{ .reg .u64 t; cvta.to.shared.u64 t, %1; cvt.u32.u64 %0, t; }"
        : "=r"(a) : "l"(p));
    return a;
}

__device__ __forceinline__ void cp_async16(uint32_t dst, const void* src) {
    asm volatile("cp.async.cg.shared.global [%0], [%1], 16;"
                 :: "r"(dst), "l"(src) : "memory");
}
__device__ __forceinline__ void cp_commit() {
    asm volatile("cp.async.commit_group;" ::: "memory");
}
__device__ __forceinline__ void cp_wait0() {
    asm volatile("cp.async.wait_group 0;" ::: "memory");
}
__device__ __forceinline__ void cp_wait1() {
    asm volatile("cp.async.wait_group 1;" ::: "memory");
}

__device__ __forceinline__ void ldmatrix_x4(uint32_t* r, uint32_t addr) {
    asm volatile("ldmatrix.sync.aligned.m8n8.x4.shared.b16 {%0,%1,%2,%3}, [%4];"
                 : "=r"(r[0]), "=r"(r[1]), "=r"(r[2]), "=r"(r[3]) : "r"(addr));
}
__device__ __forceinline__ void ldmatrix_x2(uint32_t* r, uint32_t addr) {
    asm volatile("ldmatrix.sync.aligned.m8n8.x2.shared.b16 {%0,%1}, [%2];"
                 : "=r"(r[0]), "=r"(r[1]) : "r"(addr));
}
__device__ __forceinline__ void ldmatrix_x2_trans(uint32_t* r, uint32_t addr) {
    asm volatile("ldmatrix.sync.aligned.m8n8.x2.trans.shared.b16 {%0,%1}, [%2];"
                 : "=r"(r[0]), "=r"(r[1]) : "r"(addr));
}

__device__ __forceinline__ void mma_bf16(float* c, const uint32_t* a, const uint32_t* b) {
    asm volatile(
        "mma.sync.aligned.m16n8k16.row.col.f32.bf16.bf16.f32 "
        "{%0,%1,%2,%3}, {%4,%5,%6,%7}, {%8,%9}, {%0,%1,%2,%3};"
        : "+f"(c[0]), "+f"(c[1]), "+f"(c[2]), "+f"(c[3])
        : "r"(a[0]), "r"(a[1]), "r"(a[2]), "r"(a[3]), "r"(b[0]), "r"(b[1]));
}

// ----------------------------- scratch ------------------------------------
__device__ __align__(256) float g_w1[4 * 16 * 128 * 64];
__device__ __align__(256) float g_v3[4 * 16 * 1024 * 64];
__device__ __align__(256) float g_S [4 * 16 * 128 * 1024];
__device__ __align__(256) float g_cr[4 * 16 * 1024];

__device__ __align__(256) __nv_bfloat16 g_Qh[4194304], g_Ql[4194304];
__device__ __align__(256) __nv_bfloat16 g_Kh[4194304], g_Kl[4194304];
__device__ __align__(256) __nv_bfloat16 g_V4h[4194304], g_V4l[4194304];

__device__ __align__(256) __nv_bfloat16 g_Ahv[4194304], g_Alv[4194304];
__device__ __align__(256) __nv_bfloat16 g_Ahw[524288],  g_Alw[524288];
__device__ __align__(256) __nv_bfloat16 g_Wh[6 * 1048576], g_Wl[6 * 1048576];
__device__ __align__(256) __nv_bfloat16 g_Ch[4194304],  g_Cl[4194304];

// ----------------------------- split fp32 -> bf16 hi/lo -------------------
__global__ void __launch_bounds__(256) split_kernel(
    const float* __restrict__ x, __nv_bfloat16* __restrict__ hi,
    __nv_bfloat16* __restrict__ lo, int n4)
{
    int i = blockIdx.x * 256 + threadIdx.x;
    if (i >= n4) return;
    float4 v = ((const float4*)x)[i];
    __nv_bfloat16 h0 = __float2bfloat16(v.x);
    __nv_bfloat16 h1 = __float2bfloat16(v.y);
    __nv_bfloat16 h2 = __float2bfloat16(v.z);
    __nv_bfloat16 h3 = __float2bfloat16(v.w);
    __nv_bfloat16 l0 = __float2bfloat16(v.x - __bfloat162float(h0));
    __nv_bfloat16 l1 = __float2bfloat16(v.y - __bfloat162float(h1));
    __nv_bfloat16 l2 = __float2bfloat16(v.z - __bfloat162float(h2));
    __nv_bfloat16 l3 = __float2bfloat16(v.w - __bfloat162float(h3));
    __nv_bfloat162* hp = (__nv_bfloat162*)hi;
    __nv_bfloat162* lp = (__nv_bfloat162*)lo;
    hp[2 * i]     = __nv_bfloat162{h0, h1};
    hp[2 * i + 1] = __nv_bfloat162{h2, h3};
    lp[2 * i]     = __nv_bfloat162{l0, l1};
    lp[2 * i + 1] = __nv_bfloat162{l2, l3};
}

__global__ void __launch_bounds__(256) split4_kernel(
    const float* __restrict__ p0, const float* __restrict__ p1,
    const float* __restrict__ p2, const float* __restrict__ p3,
    __nv_bfloat16* __restrict__ hi, __nv_bfloat16* __restrict__ lo)
{
    int i = blockIdx.x * 256 + threadIdx.x;
    int wsel = i >> 18;
    int j = i & 262143;
    const float* x = (wsel == 0) ? p0 : (wsel == 1) ? p1 : (wsel == 2) ? p2 : p3;
    float4 v = ((const float4*)x)[j];
    __nv_bfloat16 h0 = __float2bfloat16(v.x);
    __nv_bfloat16 h1 = __float2bfloat16(v.y);
    __nv_bfloat16 h2 = __float2bfloat16(v.z);
    __nv_bfloat16 h3 = __float2bfloat16(v.w);
    __nv_bfloat16 l0 = __float2bfloat16(v.x - __bfloat162float(h0));
    __nv_bfloat16 l1 = __float2bfloat16(v.y - __bfloat162float(h1));
    __nv_bfloat16 l2 = __float2bfloat16(v.z - __bfloat162float(h2));
    __nv_bfloat16 l3 = __float2bfloat16(v.w - __bfloat162float(h3));
    __nv_bfloat162* hp = (__nv_bfloat162*)hi;
    __nv_bfloat162* lp = (__nv_bfloat162*)lo;
    hp[2 * i]     = __nv_bfloat162{h0, h1};
    hp[2 * i + 1] = __nv_bfloat162{h2, h3};
    lp[2 * i]     = __nv_bfloat162{l0, l1};
    lp[2 * i + 1] = __nv_bfloat162{l2, l3};
}

__global__ void __launch_bounds__(256) split2_kernel(
    const float* __restrict__ p0, const float* __restrict__ p1,
    __nv_bfloat16* __restrict__ hi, __nv_bfloat16* __restrict__ lo)
{
    int i = blockIdx.x * 256 + threadIdx.x;
    int wsel = i >> 18;
    int j = i & 262143;
    const float* x = (wsel == 0) ? p0 : p1;
    float4 v = ((const float4*)x)[j];
    __nv_bfloat16 h0 = __float2bfloat16(v.x);
    __nv_bfloat16 h1 = __float2bfloat16(v.y);
    __nv_bfloat16 h2 = __float2bfloat16(v.z);
    __nv_bfloat16 h3 = __float2bfloat16(v.w);
    __nv_bfloat16 l0 = __float2bfloat16(v.x - __bfloat162float(h0));
    __nv_bfloat16 l1 = __float2bfloat16(v.y - __bfloat162float(h1));
    __nv_bfloat16 l2 = __float2bfloat16(v.z - __bfloat162float(h2));
    __nv_bfloat16 l3 = __float2bfloat16(v.w - __bfloat162float(h3));
    __nv_bfloat162* hp = (__nv_bfloat162*)hi;
    __nv_bfloat162* lp = (__nv_bfloat162*)lo;
    hp[2 * i]     = __nv_bfloat162{h0, h1};
    hp[2 * i + 1] = __nv_bfloat162{h2, h3};
    lp[2 * i]     = __nv_bfloat162{l0, l1};
    lp[2 * i + 1] = __nv_bfloat162{l2, l3};
}

// ----------------------------- HMMA GEMM core ------------------------------
static constexpr int GPITCH = 80;
static constexpr int TILE_BYTES = 128 * GPITCH;
static constexpr int STAGE_BYTES = 4 * TILE_BYTES;
static constexpr int GEMM_SMEM_BYTES = 2 * STAGE_BYTES;   // 81920

// Inner loop restructured for low register pressure:
//   keep all A fragments (32 regs), stream B via x4 pairs (8 regs live).
__device__ __forceinline__ void gemm_mainloop(
    const __nv_bfloat16* __restrict__ Ah, const __nv_bfloat16* __restrict__ Al,
    const __nv_bfloat16* __restrict__ Wh, const __nv_bfloat16* __restrict__ Wl,
    uint32_t sb, int bm, int bn, int t, float acc[4][4][4])
{
    int lane = t & 31, wid = t >> 5;
    int wm = (wid & 1) * 64;
    int wn = (wid >> 1) * 32;

    int r0 = t >> 2, c0 = t & 3;
    int r1 = (t + 256) >> 2;

    const __nv_bfloat16* srcs[4] = {Ah, Al, Wh, Wl};
    int rowoff[4] = {bm, bm, bn, bn};

    auto stage_load = [&](int s, int k0) {
        uint32_t base = sb + s * STAGE_BYTES;
#pragma unroll
        for (int tile = 0; tile < 4; tile++) {
            const __nv_bfloat16* g = srcs[tile] + (size_t)rowoff[tile] * 1024 + k0;
            uint32_t tb = base + tile * TILE_BYTES;
            cp_async16(tb + r0 * GPITCH + c0 * 16, g + (size_t)r0 * 1024 + c0 * 8);
            cp_async16(tb + r1 * GPITCH + c0 * 16, g + (size_t)r1 * 1024 + c0 * 8);
        }
        cp_commit();
    };

    stage_load(0, 0);

    // A fragment lane address
    int a_r = (lane & 15);
    int a_c = (lane >> 4) << 3;
    // B x4 lane address: covers n-pair (16 rows) x k16
    int b4_r = (lane & 7) + ((lane >> 4) & 1) * 8;   // n row within 16
    int b4_c = ((lane >> 3) & 1) << 3;               // k offset 0/8

    for (int c = 0; c < 32; c++) {
        if (c + 1 < 32) {
            stage_load((c + 1) & 1, (c + 1) * 32);
            cp_wait1();                 // wait stage c; let c+1 fly
        } else {
            cp_wait0();
        }
        __syncthreads();

        uint32_t base = sb + (c & 1) * STAGE_BYTES;
        uint32_t tAh = base, tAl = base + TILE_BYTES;
        uint32_t tWh = base + 2 * TILE_BYTES, tWl = base + 3 * TILE_BYTES;

#pragma unroll
        for (int kk = 0; kk < 32; kk += 16) {
            uint32_t ah[4][4], al[4][4];
#pragma unroll
            for (int mt = 0; mt < 4; mt++) {
                uint32_t off = (uint32_t)((wm + mt * 16 + a_r) * GPITCH + (kk + a_c) * 2);
                ldmatrix_x4(ah[mt], tAh + off);
                ldmatrix_x4(al[mt], tAl + off);
            }
#pragma unroll
            for (int np = 0; np < 2; np++) {      // nt pairs (0,1) and (2,3)
                uint32_t off = (uint32_t)((wn + np * 16 + b4_r) * GPITCH + (kk + b4_c) * 2);
                uint32_t bh4[4], bl4[4];
                ldmatrix_x4(bh4, tWh + off);
                ldmatrix_x4(bl4, tWl + off);
#pragma unroll
                for (int mt = 0; mt < 4; mt++) {
                    mma_bf16(acc[mt][2 * np + 0], ah[mt], bh4 + 0);
                    mma_bf16(acc[mt][2 * np + 0], ah[mt], bl4 + 0);
                    mma_bf16(acc[mt][2 * np + 0], al[mt], bh4 + 0);
                    mma_bf16(acc[mt][2 * np + 1], ah[mt], bh4 + 2);
                    mma_bf16(acc[mt][2 * np + 1], ah[mt], bl4 + 2);
                    mma_bf16(acc[mt][2 * np + 1], al[mt], bh4 + 2);
                }
            }
        }
        __syncthreads();
    }
}

// epilogue helpers
__device__ __forceinline__ void epi_head_bf16(
    float acc[4][4][4], const float* bias, __nv_bfloat16* outh, __nv_bfloat16* outl,
    int bm, int bn, int t)
{
    int lane = t & 31, wid = t >> 5;
    int wm = (wid & 1) * 64, wn = (wid >> 1) * 32;
#pragma unroll
    for (int mt = 0; mt < 4; mt++) {
        int row_a = bm + wm + mt * 16 + (lane >> 2);
#pragma unroll
        for (int rr = 0; rr < 2; rr++) {
            int row = row_a + rr * 8;
            int b = row >> 10, ii = row & 1023;
#pragma unroll
            for (int nt = 0; nt < 4; nt++) {
                int o = bn + wn + nt * 8 + (lane & 3) * 2;
                float vx = acc[mt][nt][rr * 2 + 0] + bias[o];
                float vy = acc[mt][nt][rr * 2 + 1] + bias[o + 1];
                int h = o >> 6, d = o & 63;
                size_t idx = ((((size_t)(b * 16 + h) << 10) + ii << 6) + d) >> 1;
                __nv_bfloat162 h2 = __floats2bfloat162_rn(vx, vy);
                __nv_bfloat162 l2 = __floats2bfloat162_rn(
                    vx - __bfloat162float(h2.x), vy - __bfloat162float(h2.y));
                ((__nv_bfloat162*)outh)[idx] = h2;
                ((__nv_bfloat162*)outl)[idx] = l2;
            }
        }
    }
}

__device__ __forceinline__ void epi_head_f32(
    float acc[4][4][4], const float* bias, float* outf,
    int bm, int bn, int t, int n_per_b)
{
    int lane = t & 31, wid = t >> 5;
    int wm = (wid & 1) * 64, wn = (wid >> 1) * 32;
#pragma unroll
    for (int mt = 0; mt < 4; mt++) {
        int row_a = bm + wm + mt * 16 + (lane >> 2);
#pragma unroll
        for (int rr = 0; rr < 2; rr++) {
            int row = row_a + rr * 8;
            int b = row / n_per_b, ii = row % n_per_b;
#pragma unroll
            for (int nt = 0; nt < 4; nt++) {
                int o = bn + wn + nt * 8 + (lane & 3) * 2;
                float vx = acc[mt][nt][rr * 2 + 0] + bias[o];
                float vy = acc[mt][nt][rr * 2 + 1] + bias[o + 1];
                int h = o >> 6, d = o & 63;
                *(float2*)&outf[(((size_t)(b * 16 + h) * n_per_b + ii) << 6) + d]
                    = float2{vx, vy};
            }
        }
    }
}

__global__ void __launch_bounds__(256, 2) hmma_gemm_v4(
    const __nv_bfloat16* __restrict__ Ah, const __nv_bfloat16* __restrict__ Al,
    const __nv_bfloat16* __restrict__ WhB, const __nv_bfloat16* __restrict__ WlB,
    const float* __restrict__ bv1, const float* __restrict__ bv2,
    const float* __restrict__ bv3, const float* __restrict__ bv4,
    __nv_bfloat16* __restrict__ Qh, __nv_bfloat16* __restrict__ Ql,
    __nv_bfloat16* __restrict__ Kh, __nv_bfloat16* __restrict__ Kl,
    float* __restrict__ v3, __nv_bfloat16* __restrict__ V4h,
    __nv_bfloat16* __restrict__ V4l)
{
    extern __shared__ char smem[];
    const uint32_t sb = smem_u32(smem);
    int t = threadIdx.x;
    int wsel = blockIdx.x & 3;
    int bn = (blockIdx.x >> 2) * 128;
    int bm = blockIdx.y * 128;

    float acc[4][4][4];
#pragma unroll
    for (int i = 0; i < 4; i++)
#pragma unroll
        for (int j = 0; j < 4; j++)
#pragma unroll
            for (int k = 0; k < 4; k++) acc[i][j][k] = 0.f;

    const __nv_bfloat16* Wh = WhB + (size_t)wsel * 1048576;
    const __nv_bfloat16* Wl = WlB + (size_t)wsel * 1048576;
    gemm_mainloop(Ah, Al, Wh, Wl, sb, bm, bn, t, acc);

    const float* bias = (wsel == 0) ? bv1 : (wsel == 1) ? bv2 : (wsel == 2) ? bv3 : bv4;
    if (wsel == 0)      epi_head_bf16(acc, bias, Qh,  Ql,  bm, bn, t);
    else if (wsel == 1) epi_head_bf16(acc, bias, Kh,  Kl,  bm, bn, t);
    else if (wsel == 3) epi_head_bf16(acc, bias, V4h, V4l, bm, bn, t);
    else                epi_head_f32(acc, bias, v3, bm, bn, t, 1024);
}

__global__ void __launch_bounds__(256, 2) hmma_gemm_w1(
    const __nv_bfloat16* __restrict__ Ah, const __nv_bfloat16* __restrict__ Al,
    const __nv_bfloat16* __restrict__ Wh, const __nv_bfloat16* __restrict__ Wl,
    const float* __restrict__ bias, float* __restrict__ outf)
{
    extern __shared__ char smem[];
    const uint32_t sb = smem_u32(smem);
    int t = threadIdx.x;
    int bn = blockIdx.x * 128, bm = blockIdx.y * 128;
    float acc[4][4][4];
#pragma unroll
    for (int i = 0; i < 4; i++)
#pragma unroll
        for (int j = 0; j < 4; j++)
#pragma unroll
            for (int k = 0; k < 4; k++) acc[i][j][k] = 0.f;
    gemm_mainloop(Ah, Al, Wh, Wl, sb, bm, bn, t, acc);
    epi_head_f32(acc, bias, outf, bm, bn, t, 128);
}

__global__ void __launch_bounds__(256, 2) hmma_gemm_out(
    const __nv_bfloat16* __restrict__ Ah, const __nv_bfloat16* __restrict__ Al,
    const __nv_bfloat16* __restrict__ Wh, const __nv_bfloat16* __restrict__ Wl,
    const float* __restrict__ bias, float* __restrict__ outf)
{
    extern __shared__ char smem[];
    const uint32_t sb = smem_u32(smem);
    int t = threadIdx.x;
    int bn = blockIdx.x * 128, bm = blockIdx.y * 128;
    float acc[4][4][4];
#pragma unroll
    for (int i = 0; i < 4; i++)
#pragma unroll
        for (int j = 0; j < 4; j++)
#pragma unroll
            for (int k = 0; k < 4; k++) acc[i][j][k] = 0.f;
    gemm_mainloop(Ah, Al, Wh, Wl, sb, bm, bn, t, acc);

    int lane = t & 31, wid = t >> 5;
    int wm = (wid & 1) * 64, wn = (wid >> 1) * 32;
#pragma unroll
    for (int mt = 0; mt < 4; mt++) {
        int row_a = bm + wm + mt * 16 + (lane >> 2);
#pragma unroll
        for (int rr = 0; rr < 2; rr++) {
            int row = row_a + rr * 8;
#pragma unroll
            for (int nt = 0; nt < 4; nt++) {
                int o = bn + wn + nt * 8 + (lane & 3) * 2;
                float vx = acc[mt][nt][rr * 2 + 0] + bias[o];
                float vy = acc[mt][nt][rr * 2 + 1] + bias[o + 1];
                *(float2*)&outf[(size_t)row * 1024 + o] = float2{vx, vy};
            }
        }
    }
}

// ---------------------------------------------------------------------------
// Cross scores path (scalar fp32, small)
// ---------------------------------------------------------------------------
__global__ void __launch_bounds__(256) cross_scores(
    const float* __restrict__ w1, const float* __restrict__ v3,
    float* __restrict__ S)
{
    __shared__ float As[8][128];
    __shared__ float Bs[8][128];

    int bh = blockIdx.y, vt = blockIdx.x;
    int t  = threadIdx.x;
    int tx = t & 15, ty = t >> 4;
    int lr = t >> 1;
    int lk = (t & 1) << 2;

    const float* Ap = w1 + (size_t)bh * 8192  + (size_t)lr * 64 + lk;
    const float* Bp = v3 + (size_t)bh * 65536 + (size_t)vt * 8192 + (size_t)lr * 64 + lk;

    float acc[8][8];
#pragma unroll
    for (int i = 0; i < 8; i++)
#pragma unroll
        for (int j = 0; j < 8; j++) acc[i][j] = 0.f;

    for (int k0 = 0; k0 < 64; k0 += 8) {
        float4 a4 = *(const float4*)(Ap + k0);
        float4 b4 = *(const float4*)(Bp + k0);
        __syncthreads();
        As[lk + 0][lr] = a4.x; As[lk + 1][lr] = a4.y;
        As[lk + 2][lr] = a4.z; As[lk + 3][lr] = a4.w;
        Bs[lk + 0][lr] = b4.x; Bs[lk + 1][lr] = b4.y;
        Bs[lk + 2][lr] = b4.z; Bs[lk + 3][lr] = b4.w;
        __syncthreads();
#pragma unroll
        for (int kk = 0; kk < 8; kk++) {
            float ar[8], br[8];
#pragma unroll
            for (int i = 0; i < 4; i++) {
                ar[i]     = As[kk][ty * 4 + i];
                ar[4 + i] = As[kk][64 + ty * 4 + i];
                br[i]     = Bs[kk][tx * 4 + i];
                br[4 + i] = Bs[kk][64 + tx * 4 + i];
            }
#pragma unroll
            for (int i = 0; i < 8; i++)
#pragma unroll
                for (int j = 0; j < 8; j++)
                    acc[i][j] += ar[i] * br[j];
        }
    }

    float* Sb = S + (size_t)bh * 131072;
#pragma unroll
    for (int i = 0; i < 8; i++) {
        int wv = (i < 4) ? (ty * 4 + i) : (64 + ty * 4 + (i - 4));
#pragma unroll
        for (int j = 0; j < 8; j++) {
            int v = vt * 128 + ((j < 4) ? (tx * 4 + j) : (64 + tx * 4 + (j - 4)));
            Sb[(size_t)wv * 1024 + v] = acc[i][j];
        }
    }
}

__global__ void __launch_bounds__(256) softmax_rows(float* __restrict__ S)
{
    float* p = S + (size_t)blockIdx.x * 1024;
    int t = threadIdx.x;
    __shared__ float sred[8];

    float x[4];
    float mx = -1e30f;
#pragma unroll
    for (int j = 0; j < 4; j++) { x[j] = p[t + 256 * j]; mx = fmaxf(mx, x[j]); }
#pragma unroll
    for (int o = 16; o; o >>= 1) mx = fmaxf(mx, __shfl_xor_sync(0xffffffffu, mx, o));
    if ((t & 31) == 0) sred[t >> 5] = mx;
    __syncthreads();
    float bm = sred[0];
#pragma unroll
    for (int w = 1; w < 8; w++) bm = fmaxf(bm, sred[w]);
    __syncthreads();

    float sum = 0.f;
#pragma unroll
    for (int j = 0; j < 4; j++) { x[j] = __expf(x[j] - bm); sum += x[j]; }
#pragma unroll
    for (int o = 16; o; o >>= 1) sum += __shfl_xor_sync(0xffffffffu, sum, o);
    if ((t & 31) == 0) sred[t >> 5] = sum;
    __syncthreads();
    float tot = 0.f;
#pragma unroll
    for (int w = 0; w < 8; w++) tot += sred[w];
    float inv = 1.f / tot;
#pragma unroll
    for (int j = 0; j < 4; j++) p[t + 256 * j] = x[j] * inv;
}

__global__ void __launch_bounds__(1024) cross_colsum(
    const float* __restrict__ S, float* __restrict__ cross)
{
    int bh = blockIdx.x;
    int v  = threadIdx.x;
    const float* base = S + (size_t)bh * 131072 + v;
    float a = 0.f;
#pragma unroll
    for (int w = 0; w < 128; w++) a += base[(size_t)w * 1024];
    cross[(size_t)bh * 1024 + v] = a;
}

// ---------------------------------------------------------------------------
// HMMA flash self-attention with per-key bias (bf16x3 compensated).
// ---------------------------------------------------------------------------
static constexpr int APITCH = 144;
static constexpr int AQ_BYTES  = 128 * APITCH;
static constexpr int AKV_T     = 64 * APITCH;
static constexpr int AKV_BUF   = 4 * AKV_T + 256;
static constexpr int AKV_BASE  = 2 * AQ_BYTES;
static constexpr int ATTN_SMEM = AKV_BASE + 2 * AKV_BUF;

__global__ void __launch_bounds__(256, 1) attn_hmma(
    const __nv_bfloat16* __restrict__ Qh_g, const __nv_bfloat16* __restrict__ Ql_g,
    const __nv_bfloat16* __restrict__ Kh_g, const __nv_bfloat16* __restrict__ Kl_g,
    const __nv_bfloat16* __restrict__ Vh_g, const __nv_bfloat16* __restrict__ Vl_g,
    const float* __restrict__ cross,
    __nv_bfloat16* __restrict__ Ch, __nv_bfloat16* __restrict__ Cl)
{
    extern __shared__ char smem[];
    const uint32_t sb = smem_u32(smem);
    int t = threadIdx.x;
    int lane = t & 31, w = t >> 5;
    int bh = blockIdx.y, qt = blockIdx.x;
    int b = bh >> 4, h = bh & 15;

    const __nv_bfloat16* qh_g = Qh_g + (size_t)bh * 65536 + (size_t)qt * 8192;
    const __nv_bfloat16* ql_g = Ql_g + (size_t)bh * 65536 + (size_t)qt * 8192;
    const __nv_bfloat16* kh_g = Kh_g + (size_t)bh * 65536;
    const __nv_bfloat16* kl_g = Kl_g + (size_t)bh * 65536;
    const __nv_bfloat16* vh_g = Vh_g + (size_t)bh * 65536;
    const __nv_bfloat16* vl_g = Vl_g + (size_t)bh * 65536;
    const float* cr = cross + (size_t)bh * 1024;

    {
#pragma unroll
        for (int it = 0; it < 4; it++) {
            int ch = t + it * 256;
            int row = ch >> 3, cc = ch & 7;
            cp_async16(sb + row * APITCH + cc * 16, qh_g + (size_t)row * 64 + cc * 8);
            cp_async16(sb + AQ_BYTES + row * APITCH + cc * 16,
                       ql_g + (size_t)row * 64 + cc * 8);
        }
    }

    auto stage_kv = [&](int s, int kb) {
        uint32_t base = sb + AKV_BASE + s * AKV_BUF;
        int krow0 = kb * 64;
#pragma unroll
        for (int it = 0; it < 2; it++) {
            int ch = t + it * 256;
            int row = ch >> 3, cc = ch & 7;
            size_t g = (size_t)(krow0 + row) * 64 + cc * 8;
            uint32_t d = base + row * APITCH + cc * 16;
            cp_async16(d + 0 * AKV_T, kh_g + g);
            cp_async16(d + 1 * AKV_T, kl_g + g);
            cp_async16(d + 2 * AKV_T, vh_g + g);
            cp_async16(d + 3 * AKV_T, vl_g + g);
        }
        if (t < 16) cp_async16(base + 4 * AKV_T + t * 16, cr + kb * 64 + t * 4);
        cp_commit();
    };

    stage_kv(0, 0);
    cp_wait0();
    __syncthreads();

    uint32_t qh[4][4], ql[4][4];
    {
        int a_r = w * 16 + (lane & 15);
        int a_c = (lane >> 4) << 3;
#pragma unroll
        for (int ks = 0; ks < 4; ks++) {
            uint32_t off = (uint32_t)(a_r * APITCH + (ks * 16 + a_c) * 2);
            ldmatrix_x4(qh[ks], sb + off);
            ldmatrix_x4(ql[ks], sb + AQ_BYTES + off);
        }
    }

    float o[8][4];
#pragma unroll
    for (int i = 0; i < 8; i++)
#pragma unroll
        for (int j = 0; j < 4; j++) o[i][j] = 0.f;
    float m0 = -1e30f, m1 = -1e30f, l0 = 0.f, l1 = 0.f;

    int c2 = (lane & 3) * 2;
    int kb_r = lane & 7;
    int kb_c = ((lane >> 3) & 1) << 3;

    for (int kb = 0; kb < 16; kb++) {
        if (kb + 1 < 16) stage_kv((kb + 1) & 1, kb + 1);

        uint32_t kvb = sb + AKV_BASE + (kb & 1) * AKV_BUF;
        const float* crs = (const float*)(smem + AKV_BASE + (kb & 1) * AKV_BUF + 4 * AKV_T);

        float s[8][4];
#pragma unroll
        for (int nt = 0; nt < 8; nt++) {
            float b0 = crs[nt * 8 + c2];
            float b1 = crs[nt * 8 + c2 + 1];
            s[nt][0] = b0; s[nt][1] = b1; s[nt][2] = b0; s[nt][3] = b1;
        }

#pragma unroll
        for (int ks = 0; ks < 4; ks++) {
#pragma unroll
            for (int nt = 0; nt < 8; nt++) {
                uint32_t off = (uint32_t)((nt * 8 + kb_r) * APITCH + (ks * 16 + kb_c) * 2);
                uint32_t kh[2], kl[2];
                ldmatrix_x2(kh, kvb + off);
                ldmatrix_x2(kl, kvb + AKV_T + off);
                mma_bf16(s[nt], qh[ks], kh);
                mma_bf16(s[nt], qh[ks], kl);
                mma_bf16(s[nt], ql[ks], kh);
            }
        }

        float mx0 = -1e30f, mx1 = -1e30f;
#pragma unroll
        for (int nt = 0; nt < 8; nt++) {
            mx0 = fmaxf(mx0, fmaxf(s[nt][0], s[nt][1]));
            mx1 = fmaxf(mx1, fmaxf(s[nt][2], s[nt][3]));
        }
        mx0 = fmaxf(mx0, __shfl_xor_sync(0xffffffffu, mx0, 1));
        mx0 = fmaxf(mx0, __shfl_xor_sync(0xffffffffu, mx0, 2));
        mx1 = fmaxf(mx1, __shfl_xor_sync(0xffffffffu, mx1, 1));
        mx1 = fmaxf(mx1, __shfl_xor_sync(0xffffffffu, mx1, 2));
        float mn0 = fmaxf(m0, mx0), mn1 = fmaxf(m1, mx1);
        float sc0 = __expf(m0 - mn0), sc1 = __expf(m1 - mn1);
        m0 = mn0; m1 = mn1;

        float rs0 = 0.f, rs1 = 0.f;
        uint32_t ph0[8], ph1[8], pl0[8], pl1[8];
#pragma unroll
        for (int nt = 0; nt < 8; nt++) {
            float p0 = __expf(s[nt][0] - mn0);
            float p1 = __expf(s[nt][1] - mn0);
            float p2 = __expf(s[nt][2] - mn1);
            float p3 = __expf(s[nt][3] - mn1);
            rs0 += p0 + p1; rs1 += p2 + p3;
            __nv_bfloat162 hA = __floats2bfloat162_rn(p0, p1);
            __nv_bfloat162 hB = __floats2bfloat162_rn(p2, p3);
            ph0[nt] = *(uint32_t*)&hA;
            ph1[nt] = *(uint32_t*)&hB;
            __nv_bfloat162 lA = __floats2bfloat162_rn(
                p0 - __bfloat162float(hA.x), p1 - __bfloat162float(hA.y));
            __nv_bfloat162 lB = __floats2bfloat162_rn(
                p2 - __bfloat162float(hB.x), p3 - __bfloat162float(hB.y));
            pl0[nt] = *(uint32_t*)&lA;
            pl1[nt] = *(uint32_t*)&lB;
        }
        rs0 += __shfl_xor_sync(0xffffffffu, rs0, 1);
        rs0 += __shfl_xor_sync(0xffffffffu, rs0, 2);
        rs1 += __shfl_xor_sync(0xffffffffu, rs1, 1);
        rs1 += __shfl_xor_sync(0xffffffffu, rs1, 2);
        l0 = l0 * sc0 + rs0;
        l1 = l1 * sc1 + rs1;
#pragma unroll
        for (int nt = 0; nt < 8; nt++) {
            o[nt][0] *= sc0; o[nt][1] *= sc0;
            o[nt][2] *= sc1; o[nt][3] *= sc1;
        }

        int v_r = (lane & 7) + ((lane >> 3) & 1) * 8;
#pragma unroll
        for (int kt = 0; kt < 4; kt++) {
            uint32_t ah[4] = {ph0[2 * kt], ph1[2 * kt], ph0[2 * kt + 1], ph1[2 * kt + 1]};
            uint32_t al[4] = {pl0[2 * kt], pl1[2 * kt], pl0[2 * kt + 1], pl1[2 * kt + 1]};
#pragma unroll
            for (int nt = 0; nt < 8; nt++) {
                uint32_t voff = (uint32_t)((kt * 16 + v_r) * APITCH + nt * 16);
                uint32_t vh[2], vl[2];
                ldmatrix_x2_trans(vh, kvb + 2 * AKV_T + voff);
                ldmatrix_x2_trans(vl, kvb + 3 * AKV_T + voff);
                mma_bf16(o[nt], ah, vh);
                mma_bf16(o[nt], ah, vl);
                mma_bf16(o[nt], al, vh);
            }
        }

        if (kb + 1 < 16) {
            cp_wait0();
            __syncthreads();
        }
    }

    float inv0 = 1.f / l0, inv1 = 1.f / l1;
    int row0 = qt * 128 + w * 16 + (lane >> 2);
    __nv_bfloat162* Ch2 = (__nv_bfloat162*)Ch;
    __nv_bfloat162* Cl2 = (__nv_bfloat162*)Cl;
#pragma unroll
    for (int nt = 0; nt < 8; nt++) {
        int d = nt * 8 + c2;
        {
            float x0 = o[nt][0] * inv0, x1 = o[nt][1] * inv0;
            __nv_bfloat162 h2 = __floats2bfloat162_rn(x0, x1);
            __nv_bfloat162 l2 = __floats2bfloat162_rn(
                x0 - __bfloat162float(h2.x), x1 - __bfloat162float(h2.y));
            size_t idx = (((size_t)b * 1024 + row0) * 1024 + h * 64 + d) >> 1;
            Ch2[idx] = h2; Cl2[idx] = l2;
        }
        {
            float x0 = o[nt][2] * inv1, x1 = o[nt][3] * inv1;
            __nv_bfloat162 h2 = __floats2bfloat162_rn(x0, x1);
            __nv_bfloat162 l2 = __floats2bfloat162_rn(
                x0 - __bfloat162float(h2.x), x1 - __bfloat162float(h2.y));
            size_t idx = (((size_t)b * 1024 + row0 + 8) * 1024 + h * 64 + d) >> 1;
            Ch2[idx] = h2; Cl2[idx] = l2;
        }
    }
}

// ---------------------------------------------------------------------------
// Launch
// ---------------------------------------------------------------------------
extern "C" void kernel_launch(void* const* d_in, const int* in_sizes, int n_in,
                              void* d_out, int out_size)
{
    const float* w_feat = (const float*)d_in[0];
    const float* v_feat = (const float*)d_in[1];
    const float* Ww1  = (const float*)d_in[2];
    const float* bw1  = (const float*)d_in[3];
    const float* Wv1  = (const float*)d_in[4];
    const float* bv1  = (const float*)d_in[5];
    const float* Wv2  = (const float*)d_in[6];
    const float* bv2  = (const float*)d_in[7];
    const float* Wv3  = (const float*)d_in[8];
    const float* bv3  = (const float*)d_in[9];
    const float* Wv4  = (const float*)d_in[10];
    const float* bv4  = (const float*)d_in[11];
    const float* Wout = (const float*)d_in[12];
    const float* bout = (const float*)d_in[13];
    float* out = (float*)d_out;

    float *w1p, *v3p, *Sp, *crp;
    cudaGetSymbolAddress((void**)&w1p, g_w1);
    cudaGetSymbolAddress((void**)&v3p, g_v3);
    cudaGetSymbolAddress((void**)&Sp,  g_S);
    cudaGetSymbolAddress((void**)&crp, g_cr);

    __nv_bfloat16 *Qh, *Ql, *Kh, *Kl, *V4h, *V4l;
    cudaGetSymbolAddress((void**)&Qh,  g_Qh);
    cudaGetSymbolAddress((void**)&Ql,  g_Ql);
    cudaGetSymbolAddress((void**)&Kh,  g_Kh);
    cudaGetSymbolAddress((void**)&Kl,  g_Kl);
    cudaGetSymbolAddress((void**)&V4h, g_V4h);
    cudaGetSymbolAddress((void**)&V4l, g_V4l);

    __nv_bfloat16 *Ahv, *Alv, *Ahw, *Alw, *Whp, *Wlp, *Chp, *Clp;
    cudaGetSymbolAddress((void**)&Ahv, g_Ahv);
    cudaGetSymbolAddress((void**)&Alv, g_Alv);
    cudaGetSymbolAddress((void**)&Ahw, g_Ahw);
    cudaGetSymbolAddress((void**)&Alw, g_Alw);
    cudaGetSymbolAddress((void**)&Whp, g_Wh);
    cudaGetSymbolAddress((void**)&Wlp, g_Wl);
    cudaGetSymbolAddress((void**)&Chp, g_Ch);
    cudaGetSymbolAddress((void**)&Clp, g_Cl);

    cudaFuncSetAttribute(hmma_gemm_v4, cudaFuncAttributeMaxDynamicSharedMemorySize, GEMM_SMEM_BYTES);
    cudaFuncSetAttribute(hmma_gemm_w1, cudaFuncAttributeMaxDynamicSharedMemorySize, GEMM_SMEM_BYTES);
    cudaFuncSetAttribute(hmma_gemm_out, cudaFuncAttributeMaxDynamicSharedMemorySize, GEMM_SMEM_BYTES);
    cudaFuncSetAttribute(attn_hmma, cudaFuncAttributeMaxDynamicSharedMemorySize, ATTN_SMEM);

    split_kernel<<<4096, 256>>>(v_feat, Ahv, Alv, 1048576);
    split_kernel<<<512,  256>>>(w_feat, Ahw, Alw, 131072);
    split4_kernel<<<4096, 256>>>(Wv1, Wv2, Wv3, Wv4, Whp, Wlp);
    split2_kernel<<<2048, 256>>>(Ww1, Wout, Whp + 4ull * 1048576, Wlp + 4ull * 1048576);

    hmma_gemm_w1<<<dim3(8, 4), 256, GEMM_SMEM_BYTES>>>(
        Ahw, Alw, Whp + 4ull * 1048576, Wlp + 4ull * 1048576, bw1, w1p);

    hmma_gemm_v4<<<dim3(32, 32), 256, GEMM_SMEM_BYTES>>>(
        Ahv, Alv, Whp, Wlp, bv1, bv2, bv3, bv4,
        Qh, Ql, Kh, Kl, v3p, V4h, V4l);

    cross_scores<<<dim3(8, 64), 256>>>(w1p, v3p, Sp);
    softmax_rows<<<8192, 256>>>(Sp);
    cross_colsum<<<64, 1024>>>(Sp, crp);

    attn_hmma<<<dim3(8, 64), 256, ATTN_SMEM>>>(Qh, Ql, Kh, Kl, V4h, V4l, crp, Chp, Clp);

    hmma_gemm_out<<<dim3(8, 32), 256, GEMM_SMEM_BYTES>>>(
        Chp, Clp, Whp + 5ull * 1048576, Wlp + 5ull * 1048576, bout, out);
}

// round 7
// speedup vs baseline: 3.4552x; 1.0261x over previous
#include <cuda_runtime.h>
#include <cuda_bf16.h>
#include <cstdint>
#include <math.h>

// ---------------------------------------------------------------------------
// Shapes: bs=4, H=16, DK=64, D=1024, n_w=128, n_v=1024
// GEMMs + attention + cross-scores all on HMMA (mma.sync bf16x3 compensated).
// ---------------------------------------------------------------------------

__device__ __forceinline__ uint32_t smem_u32(const void* p) {
    uint32_t a;
    asm("{ .reg .u64 t; cvta.to.shared.u64 t, %1; cvt.u32.u64 %0, t; }"
        : "=r"(a) : "l"(p));
    return a;
}

__device__ __forceinline__ void cp_async16(uint32_t dst, const void* src) {
    asm volatile("cp.async.cg.shared.global [%0], [%1], 16;"
                 :: "r"(dst), "l"(src) : "memory");
}
__device__ __forceinline__ void cp_commit() {
    asm volatile("cp.async.commit_group;" ::: "memory");
}
__device__ __forceinline__ void cp_wait0() {
    asm volatile("cp.async.wait_group 0;" ::: "memory");
}
__device__ __forceinline__ void cp_wait1() {
    asm volatile("cp.async.wait_group 1;" ::: "memory");
}

__device__ __forceinline__ void ldmatrix_x4(uint32_t* r, uint32_t addr) {
    asm volatile("ldmatrix.sync.aligned.m8n8.x4.shared.b16 {%0,%1,%2,%3}, [%4];"
                 : "=r"(r[0]), "=r"(r[1]), "=r"(r[2]), "=r"(r[3]) : "r"(addr));
}
__device__ __forceinline__ void ldmatrix_x2(uint32_t* r, uint32_t addr) {
    asm volatile("ldmatrix.sync.aligned.m8n8.x2.shared.b16 {%0,%1}, [%2];"
                 : "=r"(r[0]), "=r"(r[1]) : "r"(addr));
}
__device__ __forceinline__ void ldmatrix_x2_trans(uint32_t* r, uint32_t addr) {
    asm volatile("ldmatrix.sync.aligned.m8n8.x2.trans.shared.b16 {%0,%1}, [%2];"
                 : "=r"(r[0]), "=r"(r[1]) : "r"(addr));
}

__device__ __forceinline__ void mma_bf16(float* c, const uint32_t* a, const uint32_t* b) {
    asm volatile(
        "mma.sync.aligned.m16n8k16.row.col.f32.bf16.bf16.f32 "
        "{%0,%1,%2,%3}, {%4,%5,%6,%7}, {%8,%9}, {%0,%1,%2,%3};"
        : "+f"(c[0]), "+f"(c[1]), "+f"(c[2]), "+f"(c[3])
        : "r"(a[0]), "r"(a[1]), "r"(a[2]), "r"(a[3]), "r"(b[0]), "r"(b[1]));
}

// ----------------------------- scratch ------------------------------------
__device__ __align__(256) float g_S [4 * 16 * 128 * 1024];
__device__ __align__(256) float g_cr[4 * 16 * 1024];

__device__ __align__(256) __nv_bfloat16 g_Qh[4194304], g_Ql[4194304];
__device__ __align__(256) __nv_bfloat16 g_Kh[4194304], g_Kl[4194304];
__device__ __align__(256) __nv_bfloat16 g_V4h[4194304], g_V4l[4194304];
__device__ __align__(256) __nv_bfloat16 g_V3h[4194304], g_V3l[4194304];
__device__ __align__(256) __nv_bfloat16 g_W1h[524288],  g_W1l[524288];

__device__ __align__(256) __nv_bfloat16 g_Ahv[4194304], g_Alv[4194304];
__device__ __align__(256) __nv_bfloat16 g_Ahw[524288],  g_Alw[524288];
__device__ __align__(256) __nv_bfloat16 g_Wh[6 * 1048576], g_Wl[6 * 1048576];
__device__ __align__(256) __nv_bfloat16 g_Ch[4194304],  g_Cl[4194304];

// ----------------------------- split fp32 -> bf16 hi/lo -------------------
__global__ void __launch_bounds__(256) split_kernel(
    const float* __restrict__ x, __nv_bfloat16* __restrict__ hi,
    __nv_bfloat16* __restrict__ lo, int n4)
{
    int i = blockIdx.x * 256 + threadIdx.x;
    if (i >= n4) return;
    float4 v = ((const float4*)x)[i];
    __nv_bfloat16 h0 = __float2bfloat16(v.x);
    __nv_bfloat16 h1 = __float2bfloat16(v.y);
    __nv_bfloat16 h2 = __float2bfloat16(v.z);
    __nv_bfloat16 h3 = __float2bfloat16(v.w);
    __nv_bfloat16 l0 = __float2bfloat16(v.x - __bfloat162float(h0));
    __nv_bfloat16 l1 = __float2bfloat16(v.y - __bfloat162float(h1));
    __nv_bfloat16 l2 = __float2bfloat16(v.z - __bfloat162float(h2));
    __nv_bfloat16 l3 = __float2bfloat16(v.w - __bfloat162float(h3));
    __nv_bfloat162* hp = (__nv_bfloat162*)hi;
    __nv_bfloat162* lp = (__nv_bfloat162*)lo;
    hp[2 * i]     = __nv_bfloat162{h0, h1};
    hp[2 * i + 1] = __nv_bfloat162{h2, h3};
    lp[2 * i]     = __nv_bfloat162{l0, l1};
    lp[2 * i + 1] = __nv_bfloat162{l2, l3};
}

__global__ void __launch_bounds__(256) split4_kernel(
    const float* __restrict__ p0, const float* __restrict__ p1,
    const float* __restrict__ p2, const float* __restrict__ p3,
    __nv_bfloat16* __restrict__ hi, __nv_bfloat16* __restrict__ lo)
{
    int i = blockIdx.x * 256 + threadIdx.x;
    int wsel = i >> 18;
    int j = i & 262143;
    const float* x = (wsel == 0) ? p0 : (wsel == 1) ? p1 : (wsel == 2) ? p2 : p3;
    float4 v = ((const float4*)x)[j];
    __nv_bfloat16 h0 = __float2bfloat16(v.x);
    __nv_bfloat16 h1 = __float2bfloat16(v.y);
    __nv_bfloat16 h2 = __float2bfloat16(v.z);
    __nv_bfloat16 h3 = __float2bfloat16(v.w);
    __nv_bfloat16 l0 = __float2bfloat16(v.x - __bfloat162float(h0));
    __nv_bfloat16 l1 = __float2bfloat16(v.y - __bfloat162float(h1));
    __nv_bfloat16 l2 = __float2bfloat16(v.z - __bfloat162float(h2));
    __nv_bfloat16 l3 = __float2bfloat16(v.w - __bfloat162float(h3));
    __nv_bfloat162* hp = (__nv_bfloat162*)hi;
    __nv_bfloat162* lp = (__nv_bfloat162*)lo;
    hp[2 * i]     = __nv_bfloat162{h0, h1};
    hp[2 * i + 1] = __nv_bfloat162{h2, h3};
    lp[2 * i]     = __nv_bfloat162{l0, l1};
    lp[2 * i + 1] = __nv_bfloat162{l2, l3};
}

__global__ void __launch_bounds__(256) split2_kernel(
    const float* __restrict__ p0, const float* __restrict__ p1,
    __nv_bfloat16* __restrict__ hi, __nv_bfloat16* __restrict__ lo)
{
    int i = blockIdx.x * 256 + threadIdx.x;
    int wsel = i >> 18;
    int j = i & 262143;
    const float* x = (wsel == 0) ? p0 : p1;
    float4 v = ((const float4*)x)[j];
    __nv_bfloat16 h0 = __float2bfloat16(v.x);
    __nv_bfloat16 h1 = __float2bfloat16(v.y);
    __nv_bfloat16 h2 = __float2bfloat16(v.z);
    __nv_bfloat16 h3 = __float2bfloat16(v.w);
    __nv_bfloat16 l0 = __float2bfloat16(v.x - __bfloat162float(h0));
    __nv_bfloat16 l1 = __float2bfloat16(v.y - __bfloat162float(h1));
    __nv_bfloat16 l2 = __float2bfloat16(v.z - __bfloat162float(h2));
    __nv_bfloat16 l3 = __float2bfloat16(v.w - __bfloat162float(h3));
    __nv_bfloat162* hp = (__nv_bfloat162*)hi;
    __nv_bfloat162* lp = (__nv_bfloat162*)lo;
    hp[2 * i]     = __nv_bfloat162{h0, h1};
    hp[2 * i + 1] = __nv_bfloat162{h2, h3};
    lp[2 * i]     = __nv_bfloat162{l0, l1};
    lp[2 * i + 1] = __nv_bfloat162{l2, l3};
}

// ----------------------------- HMMA GEMM core ------------------------------
static constexpr int GPITCH = 80;
static constexpr int TILE_BYTES = 128 * GPITCH;
static constexpr int STAGE_BYTES = 4 * TILE_BYTES;
static constexpr int GEMM_SMEM_BYTES = 2 * STAGE_BYTES;   // 81920

__device__ __forceinline__ void gemm_mainloop(
    const __nv_bfloat16* __restrict__ Ah, const __nv_bfloat16* __restrict__ Al,
    const __nv_bfloat16* __restrict__ Wh, const __nv_bfloat16* __restrict__ Wl,
    uint32_t sb, int bm, int bn, int t, float acc[4][4][4])
{
    int lane = t & 31, wid = t >> 5;
    int wm = (wid & 1) * 64;
    int wn = (wid >> 1) * 32;

    int r0 = t >> 2, c0 = t & 3;
    int r1 = (t + 256) >> 2;

    const __nv_bfloat16* srcs[4] = {Ah, Al, Wh, Wl};
    int rowoff[4] = {bm, bm, bn, bn};

    auto stage_load = [&](int s, int k0) {
        uint32_t base = sb + s * STAGE_BYTES;
#pragma unroll
        for (int tile = 0; tile < 4; tile++) {
            const __nv_bfloat16* g = srcs[tile] + (size_t)rowoff[tile] * 1024 + k0;
            uint32_t tb = base + tile * TILE_BYTES;
            cp_async16(tb + r0 * GPITCH + c0 * 16, g + (size_t)r0 * 1024 + c0 * 8);
            cp_async16(tb + r1 * GPITCH + c0 * 16, g + (size_t)r1 * 1024 + c0 * 8);
        }
        cp_commit();
    };

    stage_load(0, 0);

    int a_r = (lane & 15);
    int a_c = (lane >> 4) << 3;
    int b4_r = (lane & 7) + ((lane >> 4) & 1) * 8;
    int b4_c = ((lane >> 3) & 1) << 3;

    for (int c = 0; c < 32; c++) {
        if (c + 1 < 32) {
            stage_load((c + 1) & 1, (c + 1) * 32);
            cp_wait1();
        } else {
            cp_wait0();
        }
        __syncthreads();

        uint32_t base = sb + (c & 1) * STAGE_BYTES;
        uint32_t tAh = base, tAl = base + TILE_BYTES;
        uint32_t tWh = base + 2 * TILE_BYTES, tWl = base + 3 * TILE_BYTES;

#pragma unroll
        for (int kk = 0; kk < 32; kk += 16) {
            uint32_t ah[4][4], al[4][4];
#pragma unroll
            for (int mt = 0; mt < 4; mt++) {
                uint32_t off = (uint32_t)((wm + mt * 16 + a_r) * GPITCH + (kk + a_c) * 2);
                ldmatrix_x4(ah[mt], tAh + off);
                ldmatrix_x4(al[mt], tAl + off);
            }
#pragma unroll
            for (int np = 0; np < 2; np++) {
                uint32_t off = (uint32_t)((wn + np * 16 + b4_r) * GPITCH + (kk + b4_c) * 2);
                uint32_t bh4[4], bl4[4];
                ldmatrix_x4(bh4, tWh + off);
                ldmatrix_x4(bl4, tWl + off);
#pragma unroll
                for (int mt = 0; mt < 4; mt++) {
                    mma_bf16(acc[mt][2 * np + 0], ah[mt], bh4 + 0);
                    mma_bf16(acc[mt][2 * np + 0], ah[mt], bl4 + 0);
                    mma_bf16(acc[mt][2 * np + 0], al[mt], bh4 + 0);
                    mma_bf16(acc[mt][2 * np + 1], ah[mt], bh4 + 2);
                    mma_bf16(acc[mt][2 * np + 1], ah[mt], bl4 + 2);
                    mma_bf16(acc[mt][2 * np + 1], al[mt], bh4 + 2);
                }
            }
        }
        __syncthreads();
    }
}

// head-scatter bf16 hi/lo epilogue (parametrized n_per_b)
__device__ __forceinline__ void epi_head_bf16(
    float acc[4][4][4], const float* bias, __nv_bfloat16* outh, __nv_bfloat16* outl,
    int bm, int bn, int t, int n_per_b)
{
    int lane = t & 31, wid = t >> 5;
    int wm = (wid & 1) * 64, wn = (wid >> 1) * 32;
#pragma unroll
    for (int mt = 0; mt < 4; mt++) {
        int row_a = bm + wm + mt * 16 + (lane >> 2);
#pragma unroll
        for (int rr = 0; rr < 2; rr++) {
            int row = row_a + rr * 8;
            int b = row / n_per_b, ii = row % n_per_b;
#pragma unroll
            for (int nt = 0; nt < 4; nt++) {
                int o = bn + wn + nt * 8 + (lane & 3) * 2;
                float vx = acc[mt][nt][rr * 2 + 0] + bias[o];
                float vy = acc[mt][nt][rr * 2 + 1] + bias[o + 1];
                int h = o >> 6, d = o & 63;
                size_t idx = ((((size_t)(b * 16 + h) * n_per_b + ii) << 6) + (size_t)d) >> 1;
                __nv_bfloat162 h2 = __floats2bfloat162_rn(vx, vy);
                __nv_bfloat162 l2 = __floats2bfloat162_rn(
                    vx - __bfloat162float(h2.x), vy - __bfloat162float(h2.y));
                ((__nv_bfloat162*)outh)[idx] = h2;
                ((__nv_bfloat162*)outl)[idx] = l2;
            }
        }
    }
}

// batched v-projection: grid.x = bn*4 + wsel; all outputs bf16 hi/lo
__global__ void __launch_bounds__(256, 2) hmma_gemm_v4(
    const __nv_bfloat16* __restrict__ Ah, const __nv_bfloat16* __restrict__ Al,
    const __nv_bfloat16* __restrict__ WhB, const __nv_bfloat16* __restrict__ WlB,
    const float* __restrict__ bv1, const float* __restrict__ bv2,
    const float* __restrict__ bv3, const float* __restrict__ bv4,
    __nv_bfloat16* __restrict__ Qh, __nv_bfloat16* __restrict__ Ql,
    __nv_bfloat16* __restrict__ Kh, __nv_bfloat16* __restrict__ Kl,
    __nv_bfloat16* __restrict__ V3h, __nv_bfloat16* __restrict__ V3l,
    __nv_bfloat16* __restrict__ V4h, __nv_bfloat16* __restrict__ V4l)
{
    extern __shared__ char smem[];
    const uint32_t sb = smem_u32(smem);
    int t = threadIdx.x;
    int wsel = blockIdx.x & 3;
    int bn = (blockIdx.x >> 2) * 128;
    int bm = blockIdx.y * 128;

    float acc[4][4][4];
#pragma unroll
    for (int i = 0; i < 4; i++)
#pragma unroll
        for (int j = 0; j < 4; j++)
#pragma unroll
            for (int k = 0; k < 4; k++) acc[i][j][k] = 0.f;

    const __nv_bfloat16* Wh = WhB + (size_t)wsel * 1048576;
    const __nv_bfloat16* Wl = WlB + (size_t)wsel * 1048576;
    gemm_mainloop(Ah, Al, Wh, Wl, sb, bm, bn, t, acc);

    const float* bias = (wsel == 0) ? bv1 : (wsel == 1) ? bv2 : (wsel == 2) ? bv3 : bv4;
    if (wsel == 0)      epi_head_bf16(acc, bias, Qh,  Ql,  bm, bn, t, 1024);
    else if (wsel == 1) epi_head_bf16(acc, bias, Kh,  Kl,  bm, bn, t, 1024);
    else if (wsel == 2) epi_head_bf16(acc, bias, V3h, V3l, bm, bn, t, 1024);
    else                epi_head_bf16(acc, bias, V4h, V4l, bm, bn, t, 1024);
}

// w1 projection (small, head-scatter bf16 hi/lo, n_per_b = 128)
__global__ void __launch_bounds__(256, 2) hmma_gemm_w1(
    const __nv_bfloat16* __restrict__ Ah, const __nv_bfloat16* __restrict__ Al,
    const __nv_bfloat16* __restrict__ Wh, const __nv_bfloat16* __restrict__ Wl,
    const float* __restrict__ bias,
    __nv_bfloat16* __restrict__ W1h, __nv_bfloat16* __restrict__ W1l)
{
    extern __shared__ char smem[];
    const uint32_t sb = smem_u32(smem);
    int t = threadIdx.x;
    int bn = blockIdx.x * 128, bm = blockIdx.y * 128;
    float acc[4][4][4];
#pragma unroll
    for (int i = 0; i < 4; i++)
#pragma unroll
        for (int j = 0; j < 4; j++)
#pragma unroll
            for (int k = 0; k < 4; k++) acc[i][j][k] = 0.f;
    gemm_mainloop(Ah, Al, Wh, Wl, sb, bm, bn, t, acc);
    epi_head_bf16(acc, bias, W1h, W1l, bm, bn, t, 128);
}

// output projection (flat fp32)
__global__ void __launch_bounds__(256, 2) hmma_gemm_out(
    const __nv_bfloat16* __restrict__ Ah, const __nv_bfloat16* __restrict__ Al,
    const __nv_bfloat16* __restrict__ Wh, const __nv_bfloat16* __restrict__ Wl,
    const float* __restrict__ bias, float* __restrict__ outf)
{
    extern __shared__ char smem[];
    const uint32_t sb = smem_u32(smem);
    int t = threadIdx.x;
    int bn = blockIdx.x * 128, bm = blockIdx.y * 128;
    float acc[4][4][4];
#pragma unroll
    for (int i = 0; i < 4; i++)
#pragma unroll
        for (int j = 0; j < 4; j++)
#pragma unroll
            for (int k = 0; k < 4; k++) acc[i][j][k] = 0.f;
    gemm_mainloop(Ah, Al, Wh, Wl, sb, bm, bn, t, acc);

    int lane = t & 31, wid = t >> 5;
    int wm = (wid & 1) * 64, wn = (wid >> 1) * 32;
#pragma unroll
    for (int mt = 0; mt < 4; mt++) {
        int row_a = bm + wm + mt * 16 + (lane >> 2);
#pragma unroll
        for (int rr = 0; rr < 2; rr++) {
            int row = row_a + rr * 8;
#pragma unroll
            for (int nt = 0; nt < 4; nt++) {
                int o = bn + wn + nt * 8 + (lane & 3) * 2;
                float vx = acc[mt][nt][rr * 2 + 0] + bias[o];
                float vy = acc[mt][nt][rr * 2 + 1] + bias[o + 1];
                *(float2*)&outf[(size_t)row * 1024 + o] = float2{vx, vy};
            }
        }
    }
}

// ---------------------------------------------------------------------------
// HMMA cross scores: S[bh][w][v] = w1[bh,w,:] . v3[bh,v,:], K=64, bf16x3.
// grid (vt 0..7, bh 0..63), 256 threads, one-shot K (no mainloop).
// ---------------------------------------------------------------------------
static constexpr int XPITCH = 144;
static constexpr int X_T = 128 * XPITCH;          // 18432 per tensor
static constexpr int XS_SMEM = 4 * X_T;           // 73728

__global__ void __launch_bounds__(256) cross_scores_hmma(
    const __nv_bfloat16* __restrict__ W1h, const __nv_bfloat16* __restrict__ W1l,
    const __nv_bfloat16* __restrict__ V3h, const __nv_bfloat16* __restrict__ V3l,
    float* __restrict__ S)
{
    extern __shared__ char smem[];
    const uint32_t sb = smem_u32(smem);
    int t = threadIdx.x, lane = t & 31, wid = t >> 5;
    int vt = blockIdx.x, bh = blockIdx.y;

    const __nv_bfloat16* a_h = W1h + (size_t)bh * 8192;
    const __nv_bfloat16* a_l = W1l + (size_t)bh * 8192;
    const __nv_bfloat16* b_h = V3h + (size_t)bh * 65536 + (size_t)vt * 8192;
    const __nv_bfloat16* b_l = V3l + (size_t)bh * 65536 + (size_t)vt * 8192;

#pragma unroll
    for (int it = 0; it < 4; it++) {
        int ch = t + it * 256;           // 0..1023
        int row = ch >> 3, cc = ch & 7;
        size_t g = (size_t)row * 64 + cc * 8;
        uint32_t d = (uint32_t)(row * XPITCH + cc * 16);
        cp_async16(sb + 0 * X_T + d, a_h + g);
        cp_async16(sb + 1 * X_T + d, a_l + g);
        cp_async16(sb + 2 * X_T + d, b_h + g);
        cp_async16(sb + 3 * X_T + d, b_l + g);
    }
    cp_commit();
    cp_wait0();
    __syncthreads();

    int wm = (wid & 1) * 64, wn = (wid >> 1) * 32;
    int a_r = lane & 15, a_c = (lane >> 4) << 3;
    int b4_r = (lane & 7) + ((lane >> 4) & 1) * 8;
    int b4_c = ((lane >> 3) & 1) << 3;

    float acc[4][4][4];
#pragma unroll
    for (int i = 0; i < 4; i++)
#pragma unroll
        for (int j = 0; j < 4; j++)
#pragma unroll
            for (int k = 0; k < 4; k++) acc[i][j][k] = 0.f;

#pragma unroll
    for (int ks = 0; ks < 4; ks++) {
        uint32_t ah[4][4], al[4][4];
#pragma unroll
        for (int mt = 0; mt < 4; mt++) {
            uint32_t off = (uint32_t)((wm + mt * 16 + a_r) * XPITCH + (ks * 16 + a_c) * 2);
            ldmatrix_x4(ah[mt], sb + 0 * X_T + off);
            ldmatrix_x4(al[mt], sb + 1 * X_T + off);
        }
#pragma unroll
        for (int np = 0; np < 2; np++) {
            uint32_t off = (uint32_t)((wn + np * 16 + b4_r) * XPITCH + (ks * 16 + b4_c) * 2);
            uint32_t bh4[4], bl4[4];
            ldmatrix_x4(bh4, sb + 2 * X_T + off);
            ldmatrix_x4(bl4, sb + 3 * X_T + off);
#pragma unroll
            for (int mt = 0; mt < 4; mt++) {
                mma_bf16(acc[mt][2 * np + 0], ah[mt], bh4 + 0);
                mma_bf16(acc[mt][2 * np + 0], ah[mt], bl4 + 0);
                mma_bf16(acc[mt][2 * np + 0], al[mt], bh4 + 0);
                mma_bf16(acc[mt][2 * np + 1], ah[mt], bh4 + 2);
                mma_bf16(acc[mt][2 * np + 1], ah[mt], bl4 + 2);
                mma_bf16(acc[mt][2 * np + 1], al[mt], bh4 + 2);
            }
        }
    }

    float* Sb = S + (size_t)bh * 131072;
#pragma unroll
    for (int mt = 0; mt < 4; mt++) {
        int row_a = wm + mt * 16 + (lane >> 2);
#pragma unroll
        for (int rr = 0; rr < 2; rr++) {
            int w = row_a + rr * 8;
#pragma unroll
            for (int nt = 0; nt < 4; nt++) {
                int v = vt * 128 + wn + nt * 8 + (lane & 3) * 2;
                *(float2*)&Sb[(size_t)w * 1024 + v] =
                    float2{acc[mt][nt][rr * 2 + 0], acc[mt][nt][rr * 2 + 1]};
            }
        }
    }
}

__global__ void __launch_bounds__(256) softmax_rows(float* __restrict__ S)
{
    float* p = S + (size_t)blockIdx.x * 1024;
    int t = threadIdx.x;
    __shared__ float sred[8];

    float x[4];
    float mx = -1e30f;
#pragma unroll
    for (int j = 0; j < 4; j++) { x[j] = p[t + 256 * j]; mx = fmaxf(mx, x[j]); }
#pragma unroll
    for (int o = 16; o; o >>= 1) mx = fmaxf(mx, __shfl_xor_sync(0xffffffffu, mx, o));
    if ((t & 31) == 0) sred[t >> 5] = mx;
    __syncthreads();
    float bm = sred[0];
#pragma unroll
    for (int w = 1; w < 8; w++) bm = fmaxf(bm, sred[w]);
    __syncthreads();

    float sum = 0.f;
#pragma unroll
    for (int j = 0; j < 4; j++) { x[j] = __expf(x[j] - bm); sum += x[j]; }
#pragma unroll
    for (int o = 16; o; o >>= 1) sum += __shfl_xor_sync(0xffffffffu, sum, o);
    if ((t & 31) == 0) sred[t >> 5] = sum;
    __syncthreads();
    float tot = 0.f;
#pragma unroll
    for (int w = 0; w < 8; w++) tot += sred[w];
    float inv = 1.f / tot;
#pragma unroll
    for (int j = 0; j < 4; j++) p[t + 256 * j] = x[j] * inv;
}

__global__ void __launch_bounds__(1024) cross_colsum(
    const float* __restrict__ S, float* __restrict__ cross)
{
    int bh = blockIdx.x;
    int v  = threadIdx.x;
    const float* base = S + (size_t)bh * 131072 + v;
    float a = 0.f;
#pragma unroll
    for (int w = 0; w < 128; w++) a += base[(size_t)w * 1024];
    cross[(size_t)bh * 1024 + v] = a;
}

// ---------------------------------------------------------------------------
// HMMA flash self-attention with per-key bias (bf16x3 compensated).
// ---------------------------------------------------------------------------
static constexpr int APITCH = 144;
static constexpr int AQ_BYTES  = 128 * APITCH;
static constexpr int AKV_T     = 64 * APITCH;
static constexpr int AKV_BUF   = 4 * AKV_T + 256;
static constexpr int AKV_BASE  = 2 * AQ_BYTES;
static constexpr int ATTN_SMEM = AKV_BASE + 2 * AKV_BUF;

__global__ void __launch_bounds__(256, 1) attn_hmma(
    const __nv_bfloat16* __restrict__ Qh_g, const __nv_bfloat16* __restrict__ Ql_g,
    const __nv_bfloat16* __restrict__ Kh_g, const __nv_bfloat16* __restrict__ Kl_g,
    const __nv_bfloat16* __restrict__ Vh_g, const __nv_bfloat16* __restrict__ Vl_g,
    const float* __restrict__ cross,
    __nv_bfloat16* __restrict__ Ch, __nv_bfloat16* __restrict__ Cl)
{
    extern __shared__ char smem[];
    const uint32_t sb = smem_u32(smem);
    int t = threadIdx.x;
    int lane = t & 31, w = t >> 5;
    int bh = blockIdx.y, qt = blockIdx.x;
    int b = bh >> 4, h = bh & 15;

    const __nv_bfloat16* qh_g = Qh_g + (size_t)bh * 65536 + (size_t)qt * 8192;
    const __nv_bfloat16* ql_g = Ql_g + (size_t)bh * 65536 + (size_t)qt * 8192;
    const __nv_bfloat16* kh_g = Kh_g + (size_t)bh * 65536;
    const __nv_bfloat16* kl_g = Kl_g + (size_t)bh * 65536;
    const __nv_bfloat16* vh_g = Vh_g + (size_t)bh * 65536;
    const __nv_bfloat16* vl_g = Vl_g + (size_t)bh * 65536;
    const float* cr = cross + (size_t)bh * 1024;

    {
#pragma unroll
        for (int it = 0; it < 4; it++) {
            int ch = t + it * 256;
            int row = ch >> 3, cc = ch & 7;
            cp_async16(sb + row * APITCH + cc * 16, qh_g + (size_t)row * 64 + cc * 8);
            cp_async16(sb + AQ_BYTES + row * APITCH + cc * 16,
                       ql_g + (size_t)row * 64 + cc * 8);
        }
    }

    auto stage_kv = [&](int s, int kb) {
        uint32_t base = sb + AKV_BASE + s * AKV_BUF;
        int krow0 = kb * 64;
#pragma unroll
        for (int it = 0; it < 2; it++) {
            int ch = t + it * 256;
            int row = ch >> 3, cc = ch & 7;
            size_t g = (size_t)(krow0 + row) * 64 + cc * 8;
            uint32_t d = base + row * APITCH + cc * 16;
            cp_async16(d + 0 * AKV_T, kh_g + g);
            cp_async16(d + 1 * AKV_T, kl_g + g);
            cp_async16(d + 2 * AKV_T, vh_g + g);
            cp_async16(d + 3 * AKV_T, vl_g + g);
        }
        if (t < 16) cp_async16(base + 4 * AKV_T + t * 16, cr + kb * 64 + t * 4);
        cp_commit();
    };

    stage_kv(0, 0);
    cp_wait0();
    __syncthreads();

    uint32_t qh[4][4], ql[4][4];
    {
        int a_r = w * 16 + (lane & 15);
        int a_c = (lane >> 4) << 3;
#pragma unroll
        for (int ks = 0; ks < 4; ks++) {
            uint32_t off = (uint32_t)(a_r * APITCH + (ks * 16 + a_c) * 2);
            ldmatrix_x4(qh[ks], sb + off);
            ldmatrix_x4(ql[ks], sb + AQ_BYTES + off);
        }
    }

    float o[8][4];
#pragma unroll
    for (int i = 0; i < 8; i++)
#pragma unroll
        for (int j = 0; j < 4; j++) o[i][j] = 0.f;
    float m0 = -1e30f, m1 = -1e30f, l0 = 0.f, l1 = 0.f;

    int c2 = (lane & 3) * 2;
    int kb_r = lane & 7;
    int kb_c = ((lane >> 3) & 1) << 3;

    for (int kb = 0; kb < 16; kb++) {
        if (kb + 1 < 16) stage_kv((kb + 1) & 1, kb + 1);

        uint32_t kvb = sb + AKV_BASE + (kb & 1) * AKV_BUF;
        const float* crs = (const float*)(smem + AKV_BASE + (kb & 1) * AKV_BUF + 4 * AKV_T);

        float s[8][4];
#pragma unroll
        for (int nt = 0; nt < 8; nt++) {
            float b0 = crs[nt * 8 + c2];
            float b1 = crs[nt * 8 + c2 + 1];
            s[nt][0] = b0; s[nt][1] = b1; s[nt][2] = b0; s[nt][3] = b1;
        }

#pragma unroll
        for (int ks = 0; ks < 4; ks++) {
#pragma unroll
            for (int nt = 0; nt < 8; nt++) {
                uint32_t off = (uint32_t)((nt * 8 + kb_r) * APITCH + (ks * 16 + kb_c) * 2);
                uint32_t kh[2], kl[2];
                ldmatrix_x2(kh, kvb + off);
                ldmatrix_x2(kl, kvb + AKV_T + off);
                mma_bf16(s[nt], qh[ks], kh);
                mma_bf16(s[nt], qh[ks], kl);
                mma_bf16(s[nt], ql[ks], kh);
            }
        }

        float mx0 = -1e30f, mx1 = -1e30f;
#pragma unroll
        for (int nt = 0; nt < 8; nt++) {
            mx0 = fmaxf(mx0, fmaxf(s[nt][0], s[nt][1]));
            mx1 = fmaxf(mx1, fmaxf(s[nt][2], s[nt][3]));
        }
        mx0 = fmaxf(mx0, __shfl_xor_sync(0xffffffffu, mx0, 1));
        mx0 = fmaxf(mx0, __shfl_xor_sync(0xffffffffu, mx0, 2));
        mx1 = fmaxf(mx1, __shfl_xor_sync(0xffffffffu, mx1, 1));
        mx1 = fmaxf(mx1, __shfl_xor_sync(0xffffffffu, mx1, 2));
        float mn0 = fmaxf(m0, mx0), mn1 = fmaxf(m1, mx1);
        float sc0 = __expf(m0 - mn0), sc1 = __expf(m1 - mn1);
        m0 = mn0; m1 = mn1;

        float rs0 = 0.f, rs1 = 0.f;
        uint32_t ph0[8], ph1[8], pl0[8], pl1[8];
#pragma unroll
        for (int nt = 0; nt < 8; nt++) {
            float p0 = __expf(s[nt][0] - mn0);
            float p1 = __expf(s[nt][1] - mn0);
            float p2 = __expf(s[nt][2] - mn1);
            float p3 = __expf(s[nt][3] - mn1);
            rs0 += p0 + p1; rs1 += p2 + p3;
            __nv_bfloat162 hA = __floats2bfloat162_rn(p0, p1);
            __nv_bfloat162 hB = __floats2bfloat162_rn(p2, p3);
            ph0[nt] = *(uint32_t*)&hA;
            ph1[nt] = *(uint32_t*)&hB;
            __nv_bfloat162 lA = __floats2bfloat162_rn(
                p0 - __bfloat162float(hA.x), p1 - __bfloat162float(hA.y));
            __nv_bfloat162 lB = __floats2bfloat162_rn(
                p2 - __bfloat162float(hB.x), p3 - __bfloat162float(hB.y));
            pl0[nt] = *(uint32_t*)&lA;
            pl1[nt] = *(uint32_t*)&lB;
        }
        rs0 += __shfl_xor_sync(0xffffffffu, rs0, 1);
        rs0 += __shfl_xor_sync(0xffffffffu, rs0, 2);
        rs1 += __shfl_xor_sync(0xffffffffu, rs1, 1);
        rs1 += __shfl_xor_sync(0xffffffffu, rs1, 2);
        l0 = l0 * sc0 + rs0;
        l1 = l1 * sc1 + rs1;
#pragma unroll
        for (int nt = 0; nt < 8; nt++) {
            o[nt][0] *= sc0; o[nt][1] *= sc0;
            o[nt][2] *= sc1; o[nt][3] *= sc1;
        }

        int v_r = (lane & 7) + ((lane >> 3) & 1) * 8;
#pragma unroll
        for (int kt = 0; kt < 4; kt++) {
            uint32_t ah[4] = {ph0[2 * kt], ph1[2 * kt], ph0[2 * kt + 1], ph1[2 * kt + 1]};
            uint32_t al[4] = {pl0[2 * kt], pl1[2 * kt], pl0[2 * kt + 1], pl1[2 * kt + 1]};
#pragma unroll
            for (int nt = 0; nt < 8; nt++) {
                uint32_t voff = (uint32_t)((kt * 16 + v_r) * APITCH + nt * 16);
                uint32_t vh[2], vl[2];
                ldmatrix_x2_trans(vh, kvb + 2 * AKV_T + voff);
                ldmatrix_x2_trans(vl, kvb + 3 * AKV_T + voff);
                mma_bf16(o[nt], ah, vh);
                mma_bf16(o[nt], ah, vl);
                mma_bf16(o[nt], al, vh);
            }
        }

        if (kb + 1 < 16) {
            cp_wait0();
            __syncthreads();
        }
    }

    float inv0 = 1.f / l0, inv1 = 1.f / l1;
    int row0 = qt * 128 + w * 16 + (lane >> 2);
    __nv_bfloat162* Ch2 = (__nv_bfloat162*)Ch;
    __nv_bfloat162* Cl2 = (__nv_bfloat162*)Cl;
#pragma unroll
    for (int nt = 0; nt < 8; nt++) {
        int d = nt * 8 + c2;
        {
            float x0 = o[nt][0] * inv0, x1 = o[nt][1] * inv0;
            __nv_bfloat162 h2 = __floats2bfloat162_rn(x0, x1);
            __nv_bfloat162 l2 = __floats2bfloat162_rn(
                x0 - __bfloat162float(h2.x), x1 - __bfloat162float(h2.y));
            size_t idx = (((size_t)b * 1024 + row0) * 1024 + h * 64 + d) >> 1;
            Ch2[idx] = h2; Cl2[idx] = l2;
        }
        {
            float x0 = o[nt][2] * inv1, x1 = o[nt][3] * inv1;
            __nv_bfloat162 h2 = __floats2bfloat162_rn(x0, x1);
            __nv_bfloat162 l2 = __floats2bfloat162_rn(
                x0 - __bfloat162float(h2.x), x1 - __bfloat162float(h2.y));
            size_t idx = (((size_t)b * 1024 + row0 + 8) * 1024 + h * 64 + d) >> 1;
            Ch2[idx] = h2; Cl2[idx] = l2;
        }
    }
}

// ---------------------------------------------------------------------------
// Launch (launch index 3 = hmma_gemm_v4 -> ncu profiles it)
// ---------------------------------------------------------------------------
extern "C" void kernel_launch(void* const* d_in, const int* in_sizes, int n_in,
                              void* d_out, int out_size)
{
    const float* w_feat = (const float*)d_in[0];
    const float* v_feat = (const float*)d_in[1];
    const float* Ww1  = (const float*)d_in[2];
    const float* bw1  = (const float*)d_in[3];
    const float* Wv1  = (const float*)d_in[4];
    const float* bv1  = (const float*)d_in[5];
    const float* Wv2  = (const float*)d_in[6];
    const float* bv2  = (const float*)d_in[7];
    const float* Wv3  = (const float*)d_in[8];
    const float* bv3  = (const float*)d_in[9];
    const float* Wv4  = (const float*)d_in[10];
    const float* bv4  = (const float*)d_in[11];
    const float* Wout = (const float*)d_in[12];
    const float* bout = (const float*)d_in[13];
    float* out = (float*)d_out;

    float *Sp, *crp;
    cudaGetSymbolAddress((void**)&Sp,  g_S);
    cudaGetSymbolAddress((void**)&crp, g_cr);

    __nv_bfloat16 *Qh, *Ql, *Kh, *Kl, *V4h, *V4l, *V3h, *V3l, *W1h, *W1l;
    cudaGetSymbolAddress((void**)&Qh,  g_Qh);
    cudaGetSymbolAddress((void**)&Ql,  g_Ql);
    cudaGetSymbolAddress((void**)&Kh,  g_Kh);
    cudaGetSymbolAddress((void**)&Kl,  g_Kl);
    cudaGetSymbolAddress((void**)&V4h, g_V4h);
    cudaGetSymbolAddress((void**)&V4l, g_V4l);
    cudaGetSymbolAddress((void**)&V3h, g_V3h);
    cudaGetSymbolAddress((void**)&V3l, g_V3l);
    cudaGetSymbolAddress((void**)&W1h, g_W1h);
    cudaGetSymbolAddress((void**)&W1l, g_W1l);

    __nv_bfloat16 *Ahv, *Alv, *Ahw, *Alw, *Whp, *Wlp, *Chp, *Clp;
    cudaGetSymbolAddress((void**)&Ahv, g_Ahv);
    cudaGetSymbolAddress((void**)&Alv, g_Alv);
    cudaGetSymbolAddress((void**)&Ahw, g_Ahw);
    cudaGetSymbolAddress((void**)&Alw, g_Alw);
    cudaGetSymbolAddress((void**)&Whp, g_Wh);
    cudaGetSymbolAddress((void**)&Wlp, g_Wl);
    cudaGetSymbolAddress((void**)&Chp, g_Ch);
    cudaGetSymbolAddress((void**)&Clp, g_Cl);

    cudaFuncSetAttribute(hmma_gemm_v4, cudaFuncAttributeMaxDynamicSharedMemorySize, GEMM_SMEM_BYTES);
    cudaFuncSetAttribute(hmma_gemm_w1, cudaFuncAttributeMaxDynamicSharedMemorySize, GEMM_SMEM_BYTES);
    cudaFuncSetAttribute(hmma_gemm_out, cudaFuncAttributeMaxDynamicSharedMemorySize, GEMM_SMEM_BYTES);
    cudaFuncSetAttribute(cross_scores_hmma, cudaFuncAttributeMaxDynamicSharedMemorySize, XS_SMEM);
    cudaFuncSetAttribute(attn_hmma, cudaFuncAttributeMaxDynamicSharedMemorySize, ATTN_SMEM);

    // idx 0..2: splits needed by v4
    split_kernel<<<4096, 256>>>(v_feat, Ahv, Alv, 1048576);          // 0
    split4_kernel<<<4096, 256>>>(Wv1, Wv2, Wv3, Wv4, Whp, Wlp);      // 1
    split_kernel<<<512,  256>>>(w_feat, Ahw, Alw, 131072);           // 2

    // idx 3: batched v-projections  <-- ncu profile target
    hmma_gemm_v4<<<dim3(32, 32), 256, GEMM_SMEM_BYTES>>>(
        Ahv, Alv, Whp, Wlp, bv1, bv2, bv3, bv4,
        Qh, Ql, Kh, Kl, V3h, V3l, V4h, V4l);                         // 3

    // idx 4..5: remaining weight split + w1 projection
    split2_kernel<<<2048, 256>>>(Ww1, Wout, Whp + 4ull * 1048576, Wlp + 4ull * 1048576); // 4
    hmma_gemm_w1<<<dim3(8, 4), 256, GEMM_SMEM_BYTES>>>(
        Ahw, Alw, Whp + 4ull * 1048576, Wlp + 4ull * 1048576, bw1, W1h, W1l);            // 5

    // cross-attention bias path (HMMA scores)
    cross_scores_hmma<<<dim3(8, 64), 256, XS_SMEM>>>(W1h, W1l, V3h, V3l, Sp);            // 6
    softmax_rows<<<8192, 256>>>(Sp);                                                     // 7
    cross_colsum<<<64, 1024>>>(Sp, crp);                                                 // 8

    // HMMA flash self-attention
    attn_hmma<<<dim3(8, 64), 256, ATTN_SMEM>>>(Qh, Ql, Kh, Kl, V4h, V4l, crp, Chp, Clp); // 9

    // output projection
    hmma_gemm_out<<<dim3(8, 32), 256, GEMM_SMEM_BYTES>>>(
        Chp, Clp, Whp + 5ull * 1048576, Wlp + 5ull * 1048576, bout, out);                // 10
}

// round 8
// speedup vs baseline: 4.0610x; 1.1754x over previous
#include <cuda_runtime.h>
#include <cuda_fp16.h>
#include <cstdint>
#include <math.h>

// ---------------------------------------------------------------------------
// Shapes: bs=4, H=16, DK=64, D=1024, n_w=128, n_v=1024
// All matmuls on HMMA fp16 with error compensation:
//   3-term (A=Ah+Al, W=Wh+Wl; AhWh+AhWl+AlWh): Q/K projections, Q.K^T
//   2-term (A=Ah+Al, W=Wh;    AhWh+AlWh):      V3/V4/w1 proj, cross, P.V, out
// ---------------------------------------------------------------------------

__device__ __forceinline__ uint32_t smem_u32(const void* p) {
    uint32_t a;
    asm("{ .reg .u64 t; cvta.to.shared.u64 t, %1; cvt.u32.u64 %0, t; }"
        : "=r"(a) : "l"(p));
    return a;
}

__device__ __forceinline__ void cp_async16(uint32_t dst, const void* src) {
    asm volatile("cp.async.cg.shared.global [%0], [%1], 16;"
                 :: "r"(dst), "l"(src) : "memory");
}
__device__ __forceinline__ void cp_commit() {
    asm volatile("cp.async.commit_group;" ::: "memory");
}
__device__ __forceinline__ void cp_wait0() {
    asm volatile("cp.async.wait_group 0;" ::: "memory");
}
__device__ __forceinline__ void cp_wait1() {
    asm volatile("cp.async.wait_group 1;" ::: "memory");
}

__device__ __forceinline__ void ldmatrix_x4(uint32_t* r, uint32_t addr) {
    asm volatile("ldmatrix.sync.aligned.m8n8.x4.shared.b16 {%0,%1,%2,%3}, [%4];"
                 : "=r"(r[0]), "=r"(r[1]), "=r"(r[2]), "=r"(r[3]) : "r"(addr));
}
__device__ __forceinline__ void ldmatrix_x2(uint32_t* r, uint32_t addr) {
    asm volatile("ldmatrix.sync.aligned.m8n8.x2.shared.b16 {%0,%1}, [%2];"
                 : "=r"(r[0]), "=r"(r[1]) : "r"(addr));
}
__device__ __forceinline__ void ldmatrix_x2_trans(uint32_t* r, uint32_t addr) {
    asm volatile("ldmatrix.sync.aligned.m8n8.x2.trans.shared.b16 {%0,%1}, [%2];"
                 : "=r"(r[0]), "=r"(r[1]) : "r"(addr));
}

__device__ __forceinline__ void mma_f16(float* c, const uint32_t* a, const uint32_t* b) {
    asm volatile(
        "mma.sync.aligned.m16n8k16.row.col.f32.f16.f16.f32 "
        "{%0,%1,%2,%3}, {%4,%5,%6,%7}, {%8,%9}, {%0,%1,%2,%3};"
        : "+f"(c[0]), "+f"(c[1]), "+f"(c[2]), "+f"(c[3])
        : "r"(a[0]), "r"(a[1]), "r"(a[2]), "r"(a[3]), "r"(b[0]), "r"(b[1]));
}

// ----------------------------- scratch ------------------------------------
__device__ __align__(256) float g_S [4 * 16 * 128 * 1024];
__device__ __align__(256) float g_cr[4 * 16 * 1024];

__device__ __align__(256) __half g_Qh[4194304], g_Ql[4194304];
__device__ __align__(256) __half g_Kh[4194304], g_Kl[4194304];
__device__ __align__(256) __half g_V4h[4194304];
__device__ __align__(256) __half g_V3h[4194304];
__device__ __align__(256) __half g_W1h[524288],  g_W1l[524288];

__device__ __align__(256) __half g_Ahv[4194304], g_Alv[4194304];
__device__ __align__(256) __half g_Ahw[524288],  g_Alw[524288];
__device__ __align__(256) __half g_Wh[6 * 1048576], g_Wl[6 * 1048576];
__device__ __align__(256) __half g_Ch[4194304],  g_Cl[4194304];

// ----------------------------- split fp32 -> fp16 hi/lo -------------------
__device__ __forceinline__ void split4f(float4 v, __half2& h01, __half2& h23,
                                        __half2& l01, __half2& l23)
{
    __half h0 = __float2half_rn(v.x), h1 = __float2half_rn(v.y);
    __half h2 = __float2half_rn(v.z), h3 = __float2half_rn(v.w);
    __half l0 = __float2half_rn(v.x - __half2float(h0));
    __half l1 = __float2half_rn(v.y - __half2float(h1));
    __half l2 = __float2half_rn(v.z - __half2float(h2));
    __half l3 = __float2half_rn(v.w - __half2float(h3));
    h01 = __half2{h0, h1}; h23 = __half2{h2, h3};
    l01 = __half2{l0, l1}; l23 = __half2{l2, l3};
}

__global__ void __launch_bounds__(256) split_kernel(
    const float* __restrict__ x, __half* __restrict__ hi,
    __half* __restrict__ lo, int n4)
{
    int i = blockIdx.x * 256 + threadIdx.x;
    if (i >= n4) return;
    float4 v = ((const float4*)x)[i];
    __half2 h01, h23, l01, l23;
    split4f(v, h01, h23, l01, l23);
    ((__half2*)hi)[2 * i] = h01; ((__half2*)hi)[2 * i + 1] = h23;
    ((__half2*)lo)[2 * i] = l01; ((__half2*)lo)[2 * i + 1] = l23;
}

__global__ void __launch_bounds__(256) split4_kernel(
    const float* __restrict__ p0, const float* __restrict__ p1,
    const float* __restrict__ p2, const float* __restrict__ p3,
    __half* __restrict__ hi, __half* __restrict__ lo)
{
    int i = blockIdx.x * 256 + threadIdx.x;
    int wsel = i >> 18;
    int j = i & 262143;
    const float* x = (wsel == 0) ? p0 : (wsel == 1) ? p1 : (wsel == 2) ? p2 : p3;
    float4 v = ((const float4*)x)[j];
    __half2 h01, h23, l01, l23;
    split4f(v, h01, h23, l01, l23);
    ((__half2*)hi)[2 * i] = h01; ((__half2*)hi)[2 * i + 1] = h23;
    ((__half2*)lo)[2 * i] = l01; ((__half2*)lo)[2 * i + 1] = l23;
}

__global__ void __launch_bounds__(256) split2_kernel(
    const float* __restrict__ p0, const float* __restrict__ p1,
    __half* __restrict__ hi, __half* __restrict__ lo)
{
    int i = blockIdx.x * 256 + threadIdx.x;
    int wsel = i >> 18;
    int j = i & 262143;
    const float* x = (wsel == 0) ? p0 : p1;
    float4 v = ((const float4*)x)[j];
    __half2 h01, h23, l01, l23;
    split4f(v, h01, h23, l01, l23);
    ((__half2*)hi)[2 * i] = h01; ((__half2*)hi)[2 * i + 1] = h23;
    ((__half2*)lo)[2 * i] = l01; ((__half2*)lo)[2 * i + 1] = l23;
}

// ----------------------------- HMMA GEMM core ------------------------------
static constexpr int GPITCH = 80;
static constexpr int TILE_BYTES = 128 * GPITCH;
static constexpr int STAGE_BYTES = 4 * TILE_BYTES;
static constexpr int GEMM_SMEM_BYTES = 2 * STAGE_BYTES;   // 81920

// TERMS=3: AhWh + AhWl + AlWh ; TERMS=2: AhWh + AlWh (Wl never touched)
template <int TERMS>
__device__ __forceinline__ void gemm_mainloop(
    const __half* __restrict__ Ah, const __half* __restrict__ Al,
    const __half* __restrict__ Wh, const __half* __restrict__ Wl,
    uint32_t sb, int bm, int bn, int t, float acc[4][4][4])
{
    int lane = t & 31, wid = t >> 5;
    int wm = (wid & 1) * 64;
    int wn = (wid >> 1) * 32;

    int r0 = t >> 2, c0 = t & 3;
    int r1 = (t + 256) >> 2;

    const __half* srcs[4] = {Ah, Al, Wh, Wl};
    int rowoff[4] = {bm, bm, bn, bn};

    auto stage_load = [&](int s, int k0) {
#pragma unroll
        for (int tile = 0; tile < TERMS + 1; tile++) {
            const __half* g = srcs[tile] + (size_t)rowoff[tile] * 1024 + k0;
            uint32_t tb = sb + s * STAGE_BYTES + tile * TILE_BYTES;
            cp_async16(tb + r0 * GPITCH + c0 * 16, g + (size_t)r0 * 1024 + c0 * 8);
            cp_async16(tb + r1 * GPITCH + c0 * 16, g + (size_t)r1 * 1024 + c0 * 8);
        }
        cp_commit();
    };

    stage_load(0, 0);

    int a_r = (lane & 15);
    int a_c = (lane >> 4) << 3;
    int b4_r = (lane & 7) + ((lane >> 4) & 1) * 8;
    int b4_c = ((lane >> 3) & 1) << 3;

    for (int c = 0; c < 32; c++) {
        if (c + 1 < 32) {
            stage_load((c + 1) & 1, (c + 1) * 32);
            cp_wait1();
        } else {
            cp_wait0();
        }
        __syncthreads();

        uint32_t base = sb + (c & 1) * STAGE_BYTES;
        uint32_t tAh = base, tAl = base + TILE_BYTES;
        uint32_t tWh = base + 2 * TILE_BYTES, tWl = base + 3 * TILE_BYTES;

#pragma unroll
        for (int kk = 0; kk < 32; kk += 16) {
            uint32_t ah[4][4], al[4][4];
#pragma unroll
            for (int mt = 0; mt < 4; mt++) {
                uint32_t off = (uint32_t)((wm + mt * 16 + a_r) * GPITCH + (kk + a_c) * 2);
                ldmatrix_x4(ah[mt], tAh + off);
                ldmatrix_x4(al[mt], tAl + off);
            }
#pragma unroll
            for (int np = 0; np < 2; np++) {
                uint32_t off = (uint32_t)((wn + np * 16 + b4_r) * GPITCH + (kk + b4_c) * 2);
                uint32_t bh4[4];
                ldmatrix_x4(bh4, tWh + off);
                if (TERMS == 3) {
                    uint32_t bl4[4];
                    ldmatrix_x4(bl4, tWl + off);
#pragma unroll
                    for (int mt = 0; mt < 4; mt++) {
                        mma_f16(acc[mt][2 * np + 0], ah[mt], bh4 + 0);
                        mma_f16(acc[mt][2 * np + 0], ah[mt], bl4 + 0);
                        mma_f16(acc[mt][2 * np + 0], al[mt], bh4 + 0);
                        mma_f16(acc[mt][2 * np + 1], ah[mt], bh4 + 2);
                        mma_f16(acc[mt][2 * np + 1], ah[mt], bl4 + 2);
                        mma_f16(acc[mt][2 * np + 1], al[mt], bh4 + 2);
                    }
                } else {
#pragma unroll
                    for (int mt = 0; mt < 4; mt++) {
                        mma_f16(acc[mt][2 * np + 0], ah[mt], bh4 + 0);
                        mma_f16(acc[mt][2 * np + 0], al[mt], bh4 + 0);
                        mma_f16(acc[mt][2 * np + 1], ah[mt], bh4 + 2);
                        mma_f16(acc[mt][2 * np + 1], al[mt], bh4 + 2);
                    }
                }
            }
        }
        __syncthreads();
    }
}

// head-scatter epilogues
__device__ __forceinline__ void epi_head_pair(
    float acc[4][4][4], const float* bias, __half* outh, __half* outl,
    int bm, int bn, int t, int n_per_b)
{
    int lane = t & 31, wid = t >> 5;
    int wm = (wid & 1) * 64, wn = (wid >> 1) * 32;
#pragma unroll
    for (int mt = 0; mt < 4; mt++) {
        int row_a = bm + wm + mt * 16 + (lane >> 2);
#pragma unroll
        for (int rr = 0; rr < 2; rr++) {
            int row = row_a + rr * 8;
            int b = row / n_per_b, ii = row % n_per_b;
#pragma unroll
            for (int nt = 0; nt < 4; nt++) {
                int o = bn + wn + nt * 8 + (lane & 3) * 2;
                float vx = acc[mt][nt][rr * 2 + 0] + bias[o];
                float vy = acc[mt][nt][rr * 2 + 1] + bias[o + 1];
                int h = o >> 6, d = o & 63;
                size_t idx = ((((size_t)(b * 16 + h) * n_per_b + ii) << 6) + (size_t)d) >> 1;
                __half hx = __float2half_rn(vx), hy = __float2half_rn(vy);
                __half lx = __float2half_rn(vx - __half2float(hx));
                __half ly = __float2half_rn(vy - __half2float(hy));
                ((__half2*)outh)[idx] = __half2{hx, hy};
                ((__half2*)outl)[idx] = __half2{lx, ly};
            }
        }
    }
}

__device__ __forceinline__ void epi_head_hi(
    float acc[4][4][4], const float* bias, __half* outh,
    int bm, int bn, int t, int n_per_b)
{
    int lane = t & 31, wid = t >> 5;
    int wm = (wid & 1) * 64, wn = (wid >> 1) * 32;
#pragma unroll
    for (int mt = 0; mt < 4; mt++) {
        int row_a = bm + wm + mt * 16 + (lane >> 2);
#pragma unroll
        for (int rr = 0; rr < 2; rr++) {
            int row = row_a + rr * 8;
            int b = row / n_per_b, ii = row % n_per_b;
#pragma unroll
            for (int nt = 0; nt < 4; nt++) {
                int o = bn + wn + nt * 8 + (lane & 3) * 2;
                float vx = acc[mt][nt][rr * 2 + 0] + bias[o];
                float vy = acc[mt][nt][rr * 2 + 1] + bias[o + 1];
                int h = o >> 6, d = o & 63;
                size_t idx = ((((size_t)(b * 16 + h) * n_per_b + ii) << 6) + (size_t)d) >> 1;
                ((__half2*)outh)[idx] =
                    __half2{__float2half_rn(vx), __float2half_rn(vy)};
            }
        }
    }
}

// batched v-projection: grid.x = bn*4 + wsel
__global__ void __launch_bounds__(256, 2) hmma_gemm_v4(
    const __half* __restrict__ Ah, const __half* __restrict__ Al,
    const __half* __restrict__ WhB, const __half* __restrict__ WlB,
    const float* __restrict__ bv1, const float* __restrict__ bv2,
    const float* __restrict__ bv3, const float* __restrict__ bv4,
    __half* __restrict__ Qh, __half* __restrict__ Ql,
    __half* __restrict__ Kh, __half* __restrict__ Kl,
    __half* __restrict__ V3h, __half* __restrict__ V4h)
{
    extern __shared__ char smem[];
    const uint32_t sb = smem_u32(smem);
    int t = threadIdx.x;
    int wsel = blockIdx.x & 3;
    int bn = (blockIdx.x >> 2) * 128;
    int bm = blockIdx.y * 128;

    float acc[4][4][4];
#pragma unroll
    for (int i = 0; i < 4; i++)
#pragma unroll
        for (int j = 0; j < 4; j++)
#pragma unroll
            for (int k = 0; k < 4; k++) acc[i][j][k] = 0.f;

    const __half* Wh = WhB + (size_t)wsel * 1048576;
    const __half* Wl = WlB + (size_t)wsel * 1048576;

    if (wsel < 2) {
        gemm_mainloop<3>(Ah, Al, Wh, Wl, sb, bm, bn, t, acc);
        if (wsel == 0) epi_head_pair(acc, bv1, Qh, Ql, bm, bn, t, 1024);
        else           epi_head_pair(acc, bv2, Kh, Kl, bm, bn, t, 1024);
    } else {
        gemm_mainloop<2>(Ah, Al, Wh, Wl, sb, bm, bn, t, acc);
        if (wsel == 2) epi_head_hi(acc, bv3, V3h, bm, bn, t, 1024);
        else           epi_head_hi(acc, bv4, V4h, bm, bn, t, 1024);
    }
}

// w1 projection (2-term; w1 stored hi+lo for cross compensation)
__global__ void __launch_bounds__(256, 2) hmma_gemm_w1(
    const __half* __restrict__ Ah, const __half* __restrict__ Al,
    const __half* __restrict__ Wh, const __half* __restrict__ Wl,
    const float* __restrict__ bias,
    __half* __restrict__ W1h, __half* __restrict__ W1l)
{
    extern __shared__ char smem[];
    const uint32_t sb = smem_u32(smem);
    int t = threadIdx.x;
    int bn = blockIdx.x * 128, bm = blockIdx.y * 128;
    float acc[4][4][4];
#pragma unroll
    for (int i = 0; i < 4; i++)
#pragma unroll
        for (int j = 0; j < 4; j++)
#pragma unroll
            for (int k = 0; k < 4; k++) acc[i][j][k] = 0.f;
    gemm_mainloop<2>(Ah, Al, Wh, Wl, sb, bm, bn, t, acc);
    epi_head_pair(acc, bias, W1h, W1l, bm, bn, t, 128);
}

// output projection (2-term, flat fp32)
__global__ void __launch_bounds__(256, 2) hmma_gemm_out(
    const __half* __restrict__ Ah, const __half* __restrict__ Al,
    const __half* __restrict__ Wh, const __half* __restrict__ Wl,
    const float* __restrict__ bias, float* __restrict__ outf)
{
    extern __shared__ char smem[];
    const uint32_t sb = smem_u32(smem);
    int t = threadIdx.x;
    int bn = blockIdx.x * 128, bm = blockIdx.y * 128;
    float acc[4][4][4];
#pragma unroll
    for (int i = 0; i < 4; i++)
#pragma unroll
        for (int j = 0; j < 4; j++)
#pragma unroll
            for (int k = 0; k < 4; k++) acc[i][j][k] = 0.f;
    gemm_mainloop<2>(Ah, Al, Wh, Wl, sb, bm, bn, t, acc);

    int lane = t & 31, wid = t >> 5;
    int wm = (wid & 1) * 64, wn = (wid >> 1) * 32;
#pragma unroll
    for (int mt = 0; mt < 4; mt++) {
        int row_a = bm + wm + mt * 16 + (lane >> 2);
#pragma unroll
        for (int rr = 0; rr < 2; rr++) {
            int row = row_a + rr * 8;
#pragma unroll
            for (int nt = 0; nt < 4; nt++) {
                int o = bn + wn + nt * 8 + (lane & 3) * 2;
                float vx = acc[mt][nt][rr * 2 + 0] + bias[o];
                float vy = acc[mt][nt][rr * 2 + 1] + bias[o + 1];
                *(float2*)&outf[(size_t)row * 1024 + o] = float2{vx, vy};
            }
        }
    }
}

// ---------------------------------------------------------------------------
// HMMA cross scores (2-term: w1 compensated, v3 hi only)
// ---------------------------------------------------------------------------
static constexpr int XPITCH = 144;
static constexpr int X_T = 128 * XPITCH;
static constexpr int XS_SMEM = 3 * X_T;           // w1h, w1l, v3h

__global__ void __launch_bounds__(256) cross_scores_hmma(
    const __half* __restrict__ W1h, const __half* __restrict__ W1l,
    const __half* __restrict__ V3h, float* __restrict__ S)
{
    extern __shared__ char smem[];
    const uint32_t sb = smem_u32(smem);
    int t = threadIdx.x, lane = t & 31, wid = t >> 5;
    int vt = blockIdx.x, bh = blockIdx.y;

    const __half* a_h = W1h + (size_t)bh * 8192;
    const __half* a_l = W1l + (size_t)bh * 8192;
    const __half* b_h = V3h + (size_t)bh * 65536 + (size_t)vt * 8192;

#pragma unroll
    for (int it = 0; it < 4; it++) {
        int ch = t + it * 256;
        int row = ch >> 3, cc = ch & 7;
        size_t g = (size_t)row * 64 + cc * 8;
        uint32_t d = (uint32_t)(row * XPITCH + cc * 16);
        cp_async16(sb + 0 * X_T + d, a_h + g);
        cp_async16(sb + 1 * X_T + d, a_l + g);
        cp_async16(sb + 2 * X_T + d, b_h + g);
    }
    cp_commit();
    cp_wait0();
    __syncthreads();

    int wm = (wid & 1) * 64, wn = (wid >> 1) * 32;
    int a_r = lane & 15, a_c = (lane >> 4) << 3;
    int b4_r = (lane & 7) + ((lane >> 4) & 1) * 8;
    int b4_c = ((lane >> 3) & 1) << 3;

    float acc[4][4][4];
#pragma unroll
    for (int i = 0; i < 4; i++)
#pragma unroll
        for (int j = 0; j < 4; j++)
#pragma unroll
            for (int k = 0; k < 4; k++) acc[i][j][k] = 0.f;

#pragma unroll
    for (int ks = 0; ks < 4; ks++) {
        uint32_t ah[4][4], al[4][4];
#pragma unroll
        for (int mt = 0; mt < 4; mt++) {
            uint32_t off = (uint32_t)((wm + mt * 16 + a_r) * XPITCH + (ks * 16 + a_c) * 2);
            ldmatrix_x4(ah[mt], sb + 0 * X_T + off);
            ldmatrix_x4(al[mt], sb + 1 * X_T + off);
        }
#pragma unroll
        for (int np = 0; np < 2; np++) {
            uint32_t off = (uint32_t)((wn + np * 16 + b4_r) * XPITCH + (ks * 16 + b4_c) * 2);
            uint32_t bh4[4];
            ldmatrix_x4(bh4, sb + 2 * X_T + off);
#pragma unroll
            for (int mt = 0; mt < 4; mt++) {
                mma_f16(acc[mt][2 * np + 0], ah[mt], bh4 + 0);
                mma_f16(acc[mt][2 * np + 0], al[mt], bh4 + 0);
                mma_f16(acc[mt][2 * np + 1], ah[mt], bh4 + 2);
                mma_f16(acc[mt][2 * np + 1], al[mt], bh4 + 2);
            }
        }
    }

    float* Sb = S + (size_t)bh * 131072;
#pragma unroll
    for (int mt = 0; mt < 4; mt++) {
        int row_a = wm + mt * 16 + (lane >> 2);
#pragma unroll
        for (int rr = 0; rr < 2; rr++) {
            int w = row_a + rr * 8;
#pragma unroll
            for (int nt = 0; nt < 4; nt++) {
                int v = vt * 128 + wn + nt * 8 + (lane & 3) * 2;
                *(float2*)&Sb[(size_t)w * 1024 + v] =
                    float2{acc[mt][nt][rr * 2 + 0], acc[mt][nt][rr * 2 + 1]};
            }
        }
    }
}

__global__ void __launch_bounds__(256) softmax_rows(float* __restrict__ S)
{
    float* p = S + (size_t)blockIdx.x * 1024;
    int t = threadIdx.x;
    __shared__ float sred[8];

    float x[4];
    float mx = -1e30f;
#pragma unroll
    for (int j = 0; j < 4; j++) { x[j] = p[t + 256 * j]; mx = fmaxf(mx, x[j]); }
#pragma unroll
    for (int o = 16; o; o >>= 1) mx = fmaxf(mx, __shfl_xor_sync(0xffffffffu, mx, o));
    if ((t & 31) == 0) sred[t >> 5] = mx;
    __syncthreads();
    float bm = sred[0];
#pragma unroll
    for (int w = 1; w < 8; w++) bm = fmaxf(bm, sred[w]);
    __syncthreads();

    float sum = 0.f;
#pragma unroll
    for (int j = 0; j < 4; j++) { x[j] = __expf(x[j] - bm); sum += x[j]; }
#pragma unroll
    for (int o = 16; o; o >>= 1) sum += __shfl_xor_sync(0xffffffffu, sum, o);
    if ((t & 31) == 0) sred[t >> 5] = sum;
    __syncthreads();
    float tot = 0.f;
#pragma unroll
    for (int w = 0; w < 8; w++) tot += sred[w];
    float inv = 1.f / tot;
#pragma unroll
    for (int j = 0; j < 4; j++) p[t + 256 * j] = x[j] * inv;
}

__global__ void __launch_bounds__(1024) cross_colsum(
    const float* __restrict__ S, float* __restrict__ cross)
{
    int bh = blockIdx.x;
    int v  = threadIdx.x;
    const float* base = S + (size_t)bh * 131072 + v;
    float a = 0.f;
#pragma unroll
    for (int w = 0; w < 128; w++) a += base[(size_t)w * 1024];
    cross[(size_t)bh * 1024 + v] = a;
}

// ---------------------------------------------------------------------------
// HMMA flash self-attention: QK 3-term, PV 2-term (V hi only).
// ---------------------------------------------------------------------------
static constexpr int APITCH = 144;
static constexpr int AQ_BYTES  = 128 * APITCH;
static constexpr int AKV_T     = 64 * APITCH;
static constexpr int AKV_BUF   = 3 * AKV_T + 256;     // Kh, Kl, Vh + crs
static constexpr int AKV_BASE  = 2 * AQ_BYTES;
static constexpr int ATTN_SMEM = AKV_BASE + 2 * AKV_BUF;

__global__ void __launch_bounds__(256, 1) attn_hmma(
    const __half* __restrict__ Qh_g, const __half* __restrict__ Ql_g,
    const __half* __restrict__ Kh_g, const __half* __restrict__ Kl_g,
    const __half* __restrict__ Vh_g,
    const float* __restrict__ cross,
    __half* __restrict__ Ch, __half* __restrict__ Cl)
{
    extern __shared__ char smem[];
    const uint32_t sb = smem_u32(smem);
    int t = threadIdx.x;
    int lane = t & 31, w = t >> 5;
    int bh = blockIdx.y, qt = blockIdx.x;
    int b = bh >> 4, h = bh & 15;

    const __half* qh_g = Qh_g + (size_t)bh * 65536 + (size_t)qt * 8192;
    const __half* ql_g = Ql_g + (size_t)bh * 65536 + (size_t)qt * 8192;
    const __half* kh_g = Kh_g + (size_t)bh * 65536;
    const __half* kl_g = Kl_g + (size_t)bh * 65536;
    const __half* vh_g = Vh_g + (size_t)bh * 65536;
    const float* cr = cross + (size_t)bh * 1024;

    {
#pragma unroll
        for (int it = 0; it < 4; it++) {
            int ch = t + it * 256;
            int row = ch >> 3, cc = ch & 7;
            cp_async16(sb + row * APITCH + cc * 16, qh_g + (size_t)row * 64 + cc * 8);
            cp_async16(sb + AQ_BYTES + row * APITCH + cc * 16,
                       ql_g + (size_t)row * 64 + cc * 8);
        }
    }

    auto stage_kv = [&](int s, int kb) {
        uint32_t base = sb + AKV_BASE + s * AKV_BUF;
        int krow0 = kb * 64;
#pragma unroll
        for (int it = 0; it < 2; it++) {
            int ch = t + it * 256;
            int row = ch >> 3, cc = ch & 7;
            size_t g = (size_t)(krow0 + row) * 64 + cc * 8;
            uint32_t d = base + row * APITCH + cc * 16;
            cp_async16(d + 0 * AKV_T, kh_g + g);
            cp_async16(d + 1 * AKV_T, kl_g + g);
            cp_async16(d + 2 * AKV_T, vh_g + g);
        }
        if (t < 16) cp_async16(base + 3 * AKV_T + t * 16, cr + kb * 64 + t * 4);
        cp_commit();
    };

    stage_kv(0, 0);
    cp_wait0();
    __syncthreads();

    uint32_t qh[4][4], ql[4][4];
    {
        int a_r = w * 16 + (lane & 15);
        int a_c = (lane >> 4) << 3;
#pragma unroll
        for (int ks = 0; ks < 4; ks++) {
            uint32_t off = (uint32_t)(a_r * APITCH + (ks * 16 + a_c) * 2);
            ldmatrix_x4(qh[ks], sb + off);
            ldmatrix_x4(ql[ks], sb + AQ_BYTES + off);
        }
    }

    float o[8][4];
#pragma unroll
    for (int i = 0; i < 8; i++)
#pragma unroll
        for (int j = 0; j < 4; j++) o[i][j] = 0.f;
    float m0 = -1e30f, m1 = -1e30f, l0 = 0.f, l1 = 0.f;

    int c2 = (lane & 3) * 2;
    int kb_r = lane & 7;
    int kb_c = ((lane >> 3) & 1) << 3;

    for (int kb = 0; kb < 16; kb++) {
        if (kb + 1 < 16) stage_kv((kb + 1) & 1, kb + 1);

        uint32_t kvb = sb + AKV_BASE + (kb & 1) * AKV_BUF;
        const float* crs = (const float*)(smem + AKV_BASE + (kb & 1) * AKV_BUF + 3 * AKV_T);

        float s[8][4];
#pragma unroll
        for (int nt = 0; nt < 8; nt++) {
            float b0 = crs[nt * 8 + c2];
            float b1 = crs[nt * 8 + c2 + 1];
            s[nt][0] = b0; s[nt][1] = b1; s[nt][2] = b0; s[nt][3] = b1;
        }

#pragma unroll
        for (int ks = 0; ks < 4; ks++) {
#pragma unroll
            for (int nt = 0; nt < 8; nt++) {
                uint32_t off = (uint32_t)((nt * 8 + kb_r) * APITCH + (ks * 16 + kb_c) * 2);
                uint32_t kh[2], kl[2];
                ldmatrix_x2(kh, kvb + off);
                ldmatrix_x2(kl, kvb + AKV_T + off);
                mma_f16(s[nt], qh[ks], kh);
                mma_f16(s[nt], qh[ks], kl);
                mma_f16(s[nt], ql[ks], kh);
            }
        }

        float mx0 = -1e30f, mx1 = -1e30f;
#pragma unroll
        for (int nt = 0; nt < 8; nt++) {
            mx0 = fmaxf(mx0, fmaxf(s[nt][0], s[nt][1]));
            mx1 = fmaxf(mx1, fmaxf(s[nt][2], s[nt][3]));
        }
        mx0 = fmaxf(mx0, __shfl_xor_sync(0xffffffffu, mx0, 1));
        mx0 = fmaxf(mx0, __shfl_xor_sync(0xffffffffu, mx0, 2));
        mx1 = fmaxf(mx1, __shfl_xor_sync(0xffffffffu, mx1, 1));
        mx1 = fmaxf(mx1, __shfl_xor_sync(0xffffffffu, mx1, 2));
        float mn0 = fmaxf(m0, mx0), mn1 = fmaxf(m1, mx1);
        float sc0 = __expf(m0 - mn0), sc1 = __expf(m1 - mn1);
        m0 = mn0; m1 = mn1;

        float rs0 = 0.f, rs1 = 0.f;
        uint32_t ph0[8], ph1[8], pl0[8], pl1[8];
#pragma unroll
        for (int nt = 0; nt < 8; nt++) {
            float p0 = __expf(s[nt][0] - mn0);
            float p1 = __expf(s[nt][1] - mn0);
            float p2 = __expf(s[nt][2] - mn1);
            float p3 = __expf(s[nt][3] - mn1);
            rs0 += p0 + p1; rs1 += p2 + p3;
            __half2 hA = __floats2half2_rn(p0, p1);
            __half2 hB = __floats2half2_rn(p2, p3);
            ph0[nt] = *(uint32_t*)&hA;
            ph1[nt] = *(uint32_t*)&hB;
            __half2 lA = __floats2half2_rn(
                p0 - __half2float(hA.x), p1 - __half2float(hA.y));
            __half2 lB = __floats2half2_rn(
                p2 - __half2float(hB.x), p3 - __half2float(hB.y));
            pl0[nt] = *(uint32_t*)&lA;
            pl1[nt] = *(uint32_t*)&lB;
        }
        rs0 += __shfl_xor_sync(0xffffffffu, rs0, 1);
        rs0 += __shfl_xor_sync(0xffffffffu, rs0, 2);
        rs1 += __shfl_xor_sync(0xffffffffu, rs1, 1);
        rs1 += __shfl_xor_sync(0xffffffffu, rs1, 2);
        l0 = l0 * sc0 + rs0;
        l1 = l1 * sc1 + rs1;
#pragma unroll
        for (int nt = 0; nt < 8; nt++) {
            o[nt][0] *= sc0; o[nt][1] *= sc0;
            o[nt][2] *= sc1; o[nt][3] *= sc1;
        }

        int v_r = (lane & 7) + ((lane >> 3) & 1) * 8;
#pragma unroll
        for (int kt = 0; kt < 4; kt++) {
            uint32_t ah[4] = {ph0[2 * kt], ph1[2 * kt], ph0[2 * kt + 1], ph1[2 * kt + 1]};
            uint32_t al[4] = {pl0[2 * kt], pl1[2 * kt], pl0[2 * kt + 1], pl1[2 * kt + 1]};
#pragma unroll
            for (int nt = 0; nt < 8; nt++) {
                uint32_t voff = (uint32_t)((kt * 16 + v_r) * APITCH + nt * 16);
                uint32_t vh[2];
                ldmatrix_x2_trans(vh, kvb + 2 * AKV_T + voff);
                mma_f16(o[nt], ah, vh);
                mma_f16(o[nt], al, vh);
            }
        }

        if (kb + 1 < 16) {
            cp_wait0();
            __syncthreads();
        }
    }

    // epilogue: ctx hi+lo, concat layout
    float inv0 = 1.f / l0, inv1 = 1.f / l1;
    int row0 = qt * 128 + w * 16 + (lane >> 2);
    __half2* Ch2 = (__half2*)Ch;
    __half2* Cl2 = (__half2*)Cl;
#pragma unroll
    for (int nt = 0; nt < 8; nt++) {
        int d = nt * 8 + c2;
        {
            float x0 = o[nt][0] * inv0, x1 = o[nt][1] * inv0;
            __half hx = __float2half_rn(x0), hy = __float2half_rn(x1);
            __half lx = __float2half_rn(x0 - __half2float(hx));
            __half ly = __float2half_rn(x1 - __half2float(hy));
            size_t idx = (((size_t)b * 1024 + row0) * 1024 + h * 64 + d) >> 1;
            Ch2[idx] = __half2{hx, hy}; Cl2[idx] = __half2{lx, ly};
        }
        {
            float x0 = o[nt][2] * inv1, x1 = o[nt][3] * inv1;
            __half hx = __float2half_rn(x0), hy = __float2half_rn(x1);
            __half lx = __float2half_rn(x0 - __half2float(hx));
            __half ly = __float2half_rn(x1 - __half2float(hy));
            size_t idx = (((size_t)b * 1024 + row0 + 8) * 1024 + h * 64 + d) >> 1;
            Ch2[idx] = __half2{hx, hy}; Cl2[idx] = __half2{lx, ly};
        }
    }
}

// ---------------------------------------------------------------------------
// Launch (idx 3 = hmma_gemm_v4 -> ncu profiles it)
// ---------------------------------------------------------------------------
extern "C" void kernel_launch(void* const* d_in, const int* in_sizes, int n_in,
                              void* d_out, int out_size)
{
    const float* w_feat = (const float*)d_in[0];
    const float* v_feat = (const float*)d_in[1];
    const float* Ww1  = (const float*)d_in[2];
    const float* bw1  = (const float*)d_in[3];
    const float* Wv1  = (const float*)d_in[4];
    const float* bv1  = (const float*)d_in[5];
    const float* Wv2  = (const float*)d_in[6];
    const float* bv2  = (const float*)d_in[7];
    const float* Wv3  = (const float*)d_in[8];
    const float* bv3  = (const float*)d_in[9];
    const float* Wv4  = (const float*)d_in[10];
    const float* bv4  = (const float*)d_in[11];
    const float* Wout = (const float*)d_in[12];
    const float* bout = (const float*)d_in[13];
    float* out = (float*)d_out;

    float *Sp, *crp;
    cudaGetSymbolAddress((void**)&Sp,  g_S);
    cudaGetSymbolAddress((void**)&crp, g_cr);

    __half *Qh, *Ql, *Kh, *Kl, *V4h, *V3h, *W1h, *W1l;
    cudaGetSymbolAddress((void**)&Qh,  g_Qh);
    cudaGetSymbolAddress((void**)&Ql,  g_Ql);
    cudaGetSymbolAddress((void**)&Kh,  g_Kh);
    cudaGetSymbolAddress((void**)&Kl,  g_Kl);
    cudaGetSymbolAddress((void**)&V4h, g_V4h);
    cudaGetSymbolAddress((void**)&V3h, g_V3h);
    cudaGetSymbolAddress((void**)&W1h, g_W1h);
    cudaGetSymbolAddress((void**)&W1l, g_W1l);

    __half *Ahv, *Alv, *Ahw, *Alw, *Whp, *Wlp, *Chp, *Clp;
    cudaGetSymbolAddress((void**)&Ahv, g_Ahv);
    cudaGetSymbolAddress((void**)&Alv, g_Alv);
    cudaGetSymbolAddress((void**)&Ahw, g_Ahw);
    cudaGetSymbolAddress((void**)&Alw, g_Alw);
    cudaGetSymbolAddress((void**)&Whp, g_Wh);
    cudaGetSymbolAddress((void**)&Wlp, g_Wl);
    cudaGetSymbolAddress((void**)&Chp, g_Ch);
    cudaGetSymbolAddress((void**)&Clp, g_Cl);

    cudaFuncSetAttribute(hmma_gemm_v4, cudaFuncAttributeMaxDynamicSharedMemorySize, GEMM_SMEM_BYTES);
    cudaFuncSetAttribute(hmma_gemm_w1, cudaFuncAttributeMaxDynamicSharedMemorySize, GEMM_SMEM_BYTES);
    cudaFuncSetAttribute(hmma_gemm_out, cudaFuncAttributeMaxDynamicSharedMemorySize, GEMM_SMEM_BYTES);
    cudaFuncSetAttribute(cross_scores_hmma, cudaFuncAttributeMaxDynamicSharedMemorySize, XS_SMEM);
    cudaFuncSetAttribute(attn_hmma, cudaFuncAttributeMaxDynamicSharedMemorySize, ATTN_SMEM);

    // idx 0..2
    split_kernel<<<4096, 256>>>(v_feat, Ahv, Alv, 1048576);          // 0
    split4_kernel<<<4096, 256>>>(Wv1, Wv2, Wv3, Wv4, Whp, Wlp);      // 1
    split_kernel<<<512,  256>>>(w_feat, Ahw, Alw, 131072);           // 2

    // idx 3: batched v-projections  <-- ncu profile target
    hmma_gemm_v4<<<dim3(32, 32), 256, GEMM_SMEM_BYTES>>>(
        Ahv, Alv, Whp, Wlp, bv1, bv2, bv3, bv4,
        Qh, Ql, Kh, Kl, V3h, V4h);                                   // 3

    split2_kernel<<<2048, 256>>>(Ww1, Wout, Whp + 4ull * 1048576, Wlp + 4ull * 1048576); // 4
    hmma_gemm_w1<<<dim3(8, 4), 256, GEMM_SMEM_BYTES>>>(
        Ahw, Alw, Whp + 4ull * 1048576, Wlp + 4ull * 1048576, bw1, W1h, W1l);            // 5

    cross_scores_hmma<<<dim3(8, 64), 256, XS_SMEM>>>(W1h, W1l, V3h, Sp);                 // 6
    softmax_rows<<<8192, 256>>>(Sp);                                                     // 7
    cross_colsum<<<64, 1024>>>(Sp, crp);                                                 // 8

    attn_hmma<<<dim3(8, 64), 256, ATTN_SMEM>>>(Qh, Ql, Kh, Kl, V4h, crp, Chp, Clp);      // 9

    hmma_gemm_out<<<dim3(8, 32), 256, GEMM_SMEM_BYTES>>>(
        Chp, Clp, Whp + 5ull * 1048576, Wlp + 5ull * 1048576, bout, out);                // 10
}